// round 1
// baseline (speedup 1.0000x reference)
#include <cuda_runtime.h>
#include <cuda_bf16.h>

// Problem constants
#define BATCH 2
#define SEQ   2048
#define DIM   1024
#define NHEAD 16
#define HDIM  64
#define SCALE 0.125f   // 64^-0.5

#define M_TOK (BATCH * SEQ)          // 4096 rows of tokens

// Scratch (device globals: allocation-free rule)
__device__ float g_Q[BATCH * NHEAD * SEQ * HDIM];     // [b,h,n,d], pre-scaled by SCALE
__device__ float g_K[BATCH * NHEAD * SEQ * HDIM];
__device__ float g_V[BATCH * NHEAD * SEQ * HDIM];
__device__ float g_attn[M_TOK * DIM];                 // [b*n, h*64+d]

// ---------------------------------------------------------------------------
// GEMM core: C[m,n] = sum_k A[m,k] * B[n,k]  (both row-major, K-contiguous)
// BM=BN=128, BK=8, 256 threads, 8x8 micro-tile per thread.
// ---------------------------------------------------------------------------

__global__ __launch_bounds__(256) void gemm_qkv_kernel(
    const float* __restrict__ A,      // x [4096, 1024]
    const float* __restrict__ Bw,     // w_qkv [3072, 1024]
    const float* __restrict__ bias)   // b_qkv [3072]
{
    const int K = DIM;
    __shared__ float As[8][128];
    __shared__ float Bs[8][128];

    const int tid = threadIdx.x;
    const int m0 = blockIdx.y * 128;
    const int n0 = blockIdx.x * 128;

    const int lrow = tid >> 1;          // 0..127
    const int lk4  = (tid & 1) * 4;     // 0 or 4

    const float* Ag = A  + (size_t)(m0 + lrow) * K + lk4;
    const float* Bg = Bw + (size_t)(n0 + lrow) * K + lk4;

    const int ty = tid >> 4;            // 0..15
    const int tx = tid & 15;            // 0..15

    float acc[8][8];
#pragma unroll
    for (int i = 0; i < 8; i++)
#pragma unroll
        for (int j = 0; j < 8; j++) acc[i][j] = 0.f;

    for (int k0 = 0; k0 < K; k0 += 8) {
        float4 av = *(const float4*)(Ag + k0);
        float4 bv = *(const float4*)(Bg + k0);
        As[lk4 + 0][lrow] = av.x; As[lk4 + 1][lrow] = av.y;
        As[lk4 + 2][lrow] = av.z; As[lk4 + 3][lrow] = av.w;
        Bs[lk4 + 0][lrow] = bv.x; Bs[lk4 + 1][lrow] = bv.y;
        Bs[lk4 + 2][lrow] = bv.z; Bs[lk4 + 3][lrow] = bv.w;
        __syncthreads();

#pragma unroll
        for (int kk = 0; kk < 8; kk++) {
            float a[8], b[8];
            *(float4*)&a[0] = *(const float4*)&As[kk][ty * 8];
            *(float4*)&a[4] = *(const float4*)&As[kk][ty * 8 + 4];
            *(float4*)&b[0] = *(const float4*)&Bs[kk][tx * 8];
            *(float4*)&b[4] = *(const float4*)&Bs[kk][tx * 8 + 4];
#pragma unroll
            for (int i = 0; i < 8; i++)
#pragma unroll
                for (int j = 0; j < 8; j++)
                    acc[i][j] = fmaf(a[i], b[j], acc[i][j]);
        }
        __syncthreads();
    }

    // Epilogue: route 8 consecutive columns (one head chunk) to Q/K/V [b,h,n,d].
    const int n_base = n0 + tx * 8;
    const int which  = n_base >> 10;         // 0=Q 1=K 2=V
    const int rem    = n_base & 1023;
    const int h      = rem >> 6;
    const int d0     = rem & 63;
    float* buf = (which == 0) ? g_Q : ((which == 1) ? g_K : g_V);
    const float sc = (which == 0) ? SCALE : 1.f;

    float bb[8];
#pragma unroll
    for (int j = 0; j < 8; j++) bb[j] = bias[n_base + j];

#pragma unroll
    for (int i = 0; i < 8; i++) {
        const int m   = m0 + ty * 8 + i;
        const int b   = m >> 11;             // /2048
        const int tok = m & 2047;
        float* orow = buf + ((size_t)((b * NHEAD + h) * SEQ + tok)) * HDIM + d0;
        float4 v0, v1;
        v0.x = (acc[i][0] + bb[0]) * sc; v0.y = (acc[i][1] + bb[1]) * sc;
        v0.z = (acc[i][2] + bb[2]) * sc; v0.w = (acc[i][3] + bb[3]) * sc;
        v1.x = (acc[i][4] + bb[4]) * sc; v1.y = (acc[i][5] + bb[5]) * sc;
        v1.z = (acc[i][6] + bb[6]) * sc; v1.w = (acc[i][7] + bb[7]) * sc;
        *(float4*)(orow)     = v0;
        *(float4*)(orow + 4) = v1;
    }
}

__global__ __launch_bounds__(256) void gemm_proj_kernel(
    const float* __restrict__ Bw,     // w_proj [1024, 1024]
    const float* __restrict__ bias,   // b_proj [1024]
    float* __restrict__ out)          // [4096, 1024]
{
    const int K = DIM;
    __shared__ float As[8][128];
    __shared__ float Bs[8][128];

    const int tid = threadIdx.x;
    const int m0 = blockIdx.y * 128;
    const int n0 = blockIdx.x * 128;

    const int lrow = tid >> 1;
    const int lk4  = (tid & 1) * 4;

    const float* Ag = g_attn + (size_t)(m0 + lrow) * K + lk4;
    const float* Bg = Bw     + (size_t)(n0 + lrow) * K + lk4;

    const int ty = tid >> 4;
    const int tx = tid & 15;

    float acc[8][8];
#pragma unroll
    for (int i = 0; i < 8; i++)
#pragma unroll
        for (int j = 0; j < 8; j++) acc[i][j] = 0.f;

    for (int k0 = 0; k0 < K; k0 += 8) {
        float4 av = *(const float4*)(Ag + k0);
        float4 bv = *(const float4*)(Bg + k0);
        As[lk4 + 0][lrow] = av.x; As[lk4 + 1][lrow] = av.y;
        As[lk4 + 2][lrow] = av.z; As[lk4 + 3][lrow] = av.w;
        Bs[lk4 + 0][lrow] = bv.x; Bs[lk4 + 1][lrow] = bv.y;
        Bs[lk4 + 2][lrow] = bv.z; Bs[lk4 + 3][lrow] = bv.w;
        __syncthreads();

#pragma unroll
        for (int kk = 0; kk < 8; kk++) {
            float a[8], b[8];
            *(float4*)&a[0] = *(const float4*)&As[kk][ty * 8];
            *(float4*)&a[4] = *(const float4*)&As[kk][ty * 8 + 4];
            *(float4*)&b[0] = *(const float4*)&Bs[kk][tx * 8];
            *(float4*)&b[4] = *(const float4*)&Bs[kk][tx * 8 + 4];
#pragma unroll
            for (int i = 0; i < 8; i++)
#pragma unroll
                for (int j = 0; j < 8; j++)
                    acc[i][j] = fmaf(a[i], b[j], acc[i][j]);
        }
        __syncthreads();
    }

    const int n_base = n0 + tx * 8;
    float bb[8];
#pragma unroll
    for (int j = 0; j < 8; j++) bb[j] = bias[n_base + j];

#pragma unroll
    for (int i = 0; i < 8; i++) {
        const int m = m0 + ty * 8 + i;
        float* orow = out + (size_t)m * DIM + n_base;
        float4 v0, v1;
        v0.x = acc[i][0] + bb[0]; v0.y = acc[i][1] + bb[1];
        v0.z = acc[i][2] + bb[2]; v0.w = acc[i][3] + bb[3];
        v1.x = acc[i][4] + bb[4]; v1.y = acc[i][5] + bb[5];
        v1.z = acc[i][6] + bb[6]; v1.w = acc[i][7] + bb[7];
        *(float4*)(orow)     = v0;
        *(float4*)(orow + 4) = v1;
    }
}

// ---------------------------------------------------------------------------
// Flash attention, fp32. Grid: (SEQ/32 query tiles, B*H). 256 threads.
// Each warp owns 4 query rows; each lane owns output cols {lane, lane+32}.
// K tile stored transposed in smem (conflict-free), V natural.
// ---------------------------------------------------------------------------

#define QT 32
#define KT 64

__global__ __launch_bounds__(256) void attn_kernel()
{
    __shared__ float Qs[QT][HDIM];       // 8 KB
    __shared__ float Kst[HDIM][KT];      // 16 KB  [d][kk]
    __shared__ float Vs[KT][HDIM];       // 16 KB  [kk][d]
    __shared__ float Ps[8][KT];          // 2 KB

    const int bh = blockIdx.y;           // 0..31
    const int qt = blockIdx.x;           // 0..63
    const float* Qb = g_Q + (size_t)bh * SEQ * HDIM;
    const float* Kb = g_K + (size_t)bh * SEQ * HDIM;
    const float* Vb = g_V + (size_t)bh * SEQ * HDIM;

    const int tid  = threadIdx.x;
    const int lane = tid & 31;
    const int w    = tid >> 5;

    // Load Q tile: 32*64 floats = 512 float4, 2 per thread
    {
        const float4* Qg = (const float4*)(Qb + (size_t)qt * QT * HDIM);
        float4* Qs4 = (float4*)&Qs[0][0];
        Qs4[tid]       = Qg[tid];
        Qs4[tid + 256] = Qg[tid + 256];
    }

    float m[4], l[4], acc0[4], acc1[4];
#pragma unroll
    for (int i = 0; i < 4; i++) { m[i] = -1e30f; l[i] = 0.f; acc0[i] = 0.f; acc1[i] = 0.f; }

    for (int kt = 0; kt < SEQ / KT; kt++) {
        __syncthreads();
        const float4* Kg = (const float4*)(Kb + (size_t)kt * KT * HDIM);
        const float4* Vg = (const float4*)(Vb + (size_t)kt * KT * HDIM);
        float4* Vs4 = (float4*)&Vs[0][0];
#pragma unroll
        for (int i2 = 0; i2 < 4; i2++) {
            const int v = tid + i2 * 256;       // 0..1023
            const float4 kv = Kg[v];
            const int r = v >> 4, c = (v & 15) * 4;
            Kst[c + 0][r] = kv.x; Kst[c + 1][r] = kv.y;
            Kst[c + 2][r] = kv.z; Kst[c + 3][r] = kv.w;
            Vs4[v] = Vg[v];
        }
        __syncthreads();

#pragma unroll
        for (int i = 0; i < 4; i++) {
            const int ri = w * 4 + i;
            float s0 = 0.f, s1 = 0.f;
#pragma unroll
            for (int d = 0; d < HDIM; d++) {
                const float q = Qs[ri][d];
                s0 = fmaf(q, Kst[d][lane],      s0);
                s1 = fmaf(q, Kst[d][lane + 32], s1);
            }
            float smax = fmaxf(s0, s1);
#pragma unroll
            for (int off = 16; off; off >>= 1)
                smax = fmaxf(smax, __shfl_xor_sync(0xffffffffu, smax, off));

            const float mnew = fmaxf(m[i], smax);
            const float corr = __expf(m[i] - mnew);
            const float p0 = __expf(s0 - mnew);
            const float p1 = __expf(s1 - mnew);
            float ps = p0 + p1;
#pragma unroll
            for (int off = 16; off; off >>= 1)
                ps += __shfl_xor_sync(0xffffffffu, ps, off);

            l[i] = l[i] * corr + ps;
            m[i] = mnew;
            acc0[i] *= corr;
            acc1[i] *= corr;

            Ps[w][lane]      = p0;
            Ps[w][lane + 32] = p1;
            __syncwarp();
#pragma unroll
            for (int kk = 0; kk < KT; kk++) {
                const float p = Ps[w][kk];
                acc0[i] = fmaf(p, Vs[kk][lane],      acc0[i]);
                acc1[i] = fmaf(p, Vs[kk][lane + 32], acc1[i]);
            }
            __syncwarp();
        }
    }

    // Write O in [b, tok, h*64+d] layout (input layout for proj GEMM)
    const int b = bh >> 4, h = bh & 15;
#pragma unroll
    for (int i = 0; i < 4; i++) {
        const int ri  = w * 4 + i;
        const int tok = qt * QT + ri;
        const float inv = 1.f / l[i];
        float* o = g_attn + ((size_t)(b * SEQ + tok)) * DIM + h * HDIM;
        o[lane]      = acc0[i] * inv;
        o[lane + 32] = acc1[i] * inv;
    }
}

// ---------------------------------------------------------------------------

extern "C" void kernel_launch(void* const* d_in, const int* in_sizes, int n_in,
                              void* d_out, int out_size)
{
    const float* x      = (const float*)d_in[0];
    const float* w_qkv  = (const float*)d_in[1];
    const float* b_qkv  = (const float*)d_in[2];
    const float* w_proj = (const float*)d_in[3];
    const float* b_proj = (const float*)d_in[4];
    float* out = (float*)d_out;

    // QKV GEMM: M=4096, N=3072
    dim3 gq(3 * DIM / 128, M_TOK / 128);
    gemm_qkv_kernel<<<gq, 256>>>(x, w_qkv, b_qkv);

    // Attention
    dim3 ga(SEQ / QT, BATCH * NHEAD);
    attn_kernel<<<ga, 256>>>();

    // Projection: M=4096, N=1024
    dim3 gp(DIM / 128, M_TOK / 128);
    gemm_proj_kernel<<<gp, 256>>>(w_proj, b_proj, out);
}

// round 2
// speedup vs baseline: 1.9809x; 1.9809x over previous
#include <cuda_runtime.h>
#include <cuda_bf16.h>

// Problem constants
#define BATCH 2
#define SEQ   2048
#define DIM   1024
#define NHEAD 16
#define HDIM  64
#define SCALE 0.125f   // 64^-0.5

#define M_TOK (BATCH * SEQ)          // 4096 rows of tokens

// Scratch (device globals: allocation-free rule)
// Q, K stored d-major: [b, h, d, tok]   (Q pre-scaled by SCALE)
// V stored tok-major:  [b, h, tok, d]
__device__ float g_Q[BATCH * NHEAD * HDIM * SEQ];
__device__ float g_K[BATCH * NHEAD * HDIM * SEQ];
__device__ float g_V[BATCH * NHEAD * SEQ * HDIM];
__device__ float g_attn[M_TOK * DIM];                 // [b*n, h*64+d]

// ---------------------------------------------------------------------------
// GEMM core: C[m,n] = sum_k A[m,k] * B[n,k]  (both row-major, K-contiguous)
// BM=BN=128, BK=8, 256 threads, 8x8 micro-tile per thread.
// ---------------------------------------------------------------------------

__global__ __launch_bounds__(256) void gemm_qkv_kernel(
    const float* __restrict__ A,      // x [4096, 1024]
    const float* __restrict__ Bw,     // w_qkv [3072, 1024]
    const float* __restrict__ bias)   // b_qkv [3072]
{
    const int K = DIM;
    __shared__ float As[8][128];
    __shared__ float Bs[8][128];

    const int tid = threadIdx.x;
    const int m0 = blockIdx.y * 128;
    const int n0 = blockIdx.x * 128;

    const int lrow = tid >> 1;          // 0..127
    const int lk4  = (tid & 1) * 4;     // 0 or 4

    const float* Ag = A  + (size_t)(m0 + lrow) * K + lk4;
    const float* Bg = Bw + (size_t)(n0 + lrow) * K + lk4;

    const int ty = tid >> 4;            // 0..15
    const int tx = tid & 15;            // 0..15

    float acc[8][8];
#pragma unroll
    for (int i = 0; i < 8; i++)
#pragma unroll
        for (int j = 0; j < 8; j++) acc[i][j] = 0.f;

    for (int k0 = 0; k0 < K; k0 += 8) {
        float4 av = *(const float4*)(Ag + k0);
        float4 bv = *(const float4*)(Bg + k0);
        As[lk4 + 0][lrow] = av.x; As[lk4 + 1][lrow] = av.y;
        As[lk4 + 2][lrow] = av.z; As[lk4 + 3][lrow] = av.w;
        Bs[lk4 + 0][lrow] = bv.x; Bs[lk4 + 1][lrow] = bv.y;
        Bs[lk4 + 2][lrow] = bv.z; Bs[lk4 + 3][lrow] = bv.w;
        __syncthreads();

#pragma unroll
        for (int kk = 0; kk < 8; kk++) {
            float a[8], b[8];
            *(float4*)&a[0] = *(const float4*)&As[kk][ty * 8];
            *(float4*)&a[4] = *(const float4*)&As[kk][ty * 8 + 4];
            *(float4*)&b[0] = *(const float4*)&Bs[kk][tx * 8];
            *(float4*)&b[4] = *(const float4*)&Bs[kk][tx * 8 + 4];
#pragma unroll
            for (int i = 0; i < 8; i++)
#pragma unroll
                for (int j = 0; j < 8; j++)
                    acc[i][j] = fmaf(a[i], b[j], acc[i][j]);
        }
        __syncthreads();
    }

    // Epilogue: route 8 consecutive columns (one head chunk) to Q/K/V.
    const int n_base = n0 + tx * 8;
    const int which  = n_base >> 10;         // 0=Q 1=K 2=V
    const int rem    = n_base & 1023;
    const int h      = rem >> 6;
    const int d0     = rem & 63;

    float bb[8];
#pragma unroll
    for (int j = 0; j < 8; j++) bb[j] = bias[n_base + j];

    const int b    = m0 >> 11;               // batch (constant per block)
    const int tok0 = (m0 & 2047) + ty * 8;

    if (which != 2) {
        // Q or K: store d-major [b,h,d,tok] (transposed), fold SCALE into Q.
        float* buf = (which == 0) ? g_Q : g_K;
        const float sc = (which == 0) ? SCALE : 1.f;
#pragma unroll
        for (int j = 0; j < 8; j++) {
            float* col = buf + ((size_t)((b * NHEAD + h) * HDIM + d0 + j)) * SEQ + tok0;
            float4 v0, v1;
            v0.x = (acc[0][j] + bb[j]) * sc; v0.y = (acc[1][j] + bb[j]) * sc;
            v0.z = (acc[2][j] + bb[j]) * sc; v0.w = (acc[3][j] + bb[j]) * sc;
            v1.x = (acc[4][j] + bb[j]) * sc; v1.y = (acc[5][j] + bb[j]) * sc;
            v1.z = (acc[6][j] + bb[j]) * sc; v1.w = (acc[7][j] + bb[j]) * sc;
            *(float4*)(col)     = v0;
            *(float4*)(col + 4) = v1;
        }
    } else {
        // V: tok-major [b,h,tok,d]
#pragma unroll
        for (int i = 0; i < 8; i++) {
            const int tok = tok0 + i;
            float* orow = g_V + ((size_t)((b * NHEAD + h) * SEQ + tok)) * HDIM + d0;
            float4 v0, v1;
            v0.x = acc[i][0] + bb[0]; v0.y = acc[i][1] + bb[1];
            v0.z = acc[i][2] + bb[2]; v0.w = acc[i][3] + bb[3];
            v1.x = acc[i][4] + bb[4]; v1.y = acc[i][5] + bb[5];
            v1.z = acc[i][6] + bb[6]; v1.w = acc[i][7] + bb[7];
            *(float4*)(orow)     = v0;
            *(float4*)(orow + 4) = v1;
        }
    }
}

__global__ __launch_bounds__(256) void gemm_proj_kernel(
    const float* __restrict__ Bw,     // w_proj [1024, 1024]
    const float* __restrict__ bias,   // b_proj [1024]
    float* __restrict__ out)          // [4096, 1024]
{
    const int K = DIM;
    __shared__ float As[8][128];
    __shared__ float Bs[8][128];

    const int tid = threadIdx.x;
    const int m0 = blockIdx.y * 128;
    const int n0 = blockIdx.x * 128;

    const int lrow = tid >> 1;
    const int lk4  = (tid & 1) * 4;

    const float* Ag = g_attn + (size_t)(m0 + lrow) * K + lk4;
    const float* Bg = Bw     + (size_t)(n0 + lrow) * K + lk4;

    const int ty = tid >> 4;
    const int tx = tid & 15;

    float acc[8][8];
#pragma unroll
    for (int i = 0; i < 8; i++)
#pragma unroll
        for (int j = 0; j < 8; j++) acc[i][j] = 0.f;

    for (int k0 = 0; k0 < K; k0 += 8) {
        float4 av = *(const float4*)(Ag + k0);
        float4 bv = *(const float4*)(Bg + k0);
        As[lk4 + 0][lrow] = av.x; As[lk4 + 1][lrow] = av.y;
        As[lk4 + 2][lrow] = av.z; As[lk4 + 3][lrow] = av.w;
        Bs[lk4 + 0][lrow] = bv.x; Bs[lk4 + 1][lrow] = bv.y;
        Bs[lk4 + 2][lrow] = bv.z; Bs[lk4 + 3][lrow] = bv.w;
        __syncthreads();

#pragma unroll
        for (int kk = 0; kk < 8; kk++) {
            float a[8], b[8];
            *(float4*)&a[0] = *(const float4*)&As[kk][ty * 8];
            *(float4*)&a[4] = *(const float4*)&As[kk][ty * 8 + 4];
            *(float4*)&b[0] = *(const float4*)&Bs[kk][tx * 8];
            *(float4*)&b[4] = *(const float4*)&Bs[kk][tx * 8 + 4];
#pragma unroll
            for (int i = 0; i < 8; i++)
#pragma unroll
                for (int j = 0; j < 8; j++)
                    acc[i][j] = fmaf(a[i], b[j], acc[i][j]);
        }
        __syncthreads();
    }

    const int n_base = n0 + tx * 8;
    float bb[8];
#pragma unroll
    for (int j = 0; j < 8; j++) bb[j] = bias[n_base + j];

#pragma unroll
    for (int i = 0; i < 8; i++) {
        const int m = m0 + ty * 8 + i;
        float* orow = out + (size_t)m * DIM + n_base;
        float4 v0, v1;
        v0.x = acc[i][0] + bb[0]; v0.y = acc[i][1] + bb[1];
        v0.z = acc[i][2] + bb[2]; v0.w = acc[i][3] + bb[3];
        v1.x = acc[i][4] + bb[4]; v1.y = acc[i][5] + bb[5];
        v1.z = acc[i][6] + bb[6]; v1.w = acc[i][7] + bb[7];
        *(float4*)(orow)     = v0;
        *(float4*)(orow + 4) = v1;
    }
}

// ---------------------------------------------------------------------------
// Flash attention, GEMM-structured.
// Block: 128 q-rows x full head; per iteration 64 keys. 512 threads.
// Thread grid 32(ty) x 16(tx); per-thread 4x4 fragments for S and O.
// Both inner loops: 2x LDS.128 per 16 FMA.
// ---------------------------------------------------------------------------

#define QT 128
#define KT 64
#define PSTRIDE 132
// floats: Qst 64*128, Kst 64*64, Vs 64*64, Pst 64*132
#define ATTN_SMEM_FLOATS (64*128 + 64*64 + 64*64 + 64*PSTRIDE)
#define ATTN_SMEM_BYTES  (ATTN_SMEM_FLOATS * 4)

__global__ __launch_bounds__(512) void attn_kernel()
{
    extern __shared__ float sm[];
    float* Qst = sm;                       // [d=64][r=128]
    float* Kst = sm + 64 * 128;            // [d=64][c=64]
    float* Vs  = Kst + 64 * 64;            // [k=64][d=64]
    float* Pst = Vs + 64 * 64;             // [k=64][r=128 (+pad)]

    const int tid = threadIdx.x;
    const int ty  = tid >> 4;              // 0..31  (q rows ty*4..+3)
    const int tx  = tid & 15;              // 0..15  (cols tx*4..+3)
    const int bh  = blockIdx.y;            // 0..31
    const int qt  = blockIdx.x;            // 0..15

    const float* Qg = g_Q + (size_t)bh * HDIM * SEQ;   // [d][tok]
    const float* Kg = g_K + (size_t)bh * HDIM * SEQ;   // [d][tok]
    const float* Vg = g_V + (size_t)bh * SEQ * HDIM;   // [tok][d]

    // Load Q tile [64 d][128 r], coalesced, no transpose needed.
#pragma unroll
    for (int i = 0; i < 4; i++) {
        const int v = tid + i * 512;       // 0..2047
        const int d = v >> 5;              // 0..63
        const int r4 = (v & 31) * 4;       // 0..124
        *(float4*)&Qst[d * 128 + r4] =
            *(const float4*)&Qg[(size_t)d * SEQ + qt * QT + r4];
    }

    float m[4], l[4], acc[4][4];
#pragma unroll
    for (int i = 0; i < 4; i++) {
        m[i] = -1e30f; l[i] = 0.f;
#pragma unroll
        for (int j = 0; j < 4; j++) acc[i][j] = 0.f;
    }

    for (int kt = 0; kt < SEQ / KT; kt++) {
        __syncthreads();
        // Load K tile [64 d][64 c] and V tile [64 k][64 d]
#pragma unroll
        for (int i = 0; i < 2; i++) {
            const int v = tid + i * 512;   // 0..1023
            const int r = v >> 4;          // 0..63
            const int c4 = (v & 15) * 4;   // 0..60
            *(float4*)&Kst[r * 64 + c4] =
                *(const float4*)&Kg[(size_t)r * SEQ + kt * KT + c4];
            *(float4*)&Vs[r * 64 + c4] =
                *(const float4*)&Vg[(size_t)(kt * KT + r) * HDIM + c4];
        }
        __syncthreads();

        // S = Q K^T  (contraction over d)
        float s[4][4];
#pragma unroll
        for (int i = 0; i < 4; i++)
#pragma unroll
            for (int j = 0; j < 4; j++) s[i][j] = 0.f;

#pragma unroll 8
        for (int kk = 0; kk < 64; kk++) {
            const float4 a = *(const float4*)&Qst[kk * 128 + ty * 4];
            const float4 b = *(const float4*)&Kst[kk * 64 + tx * 4];
            s[0][0] = fmaf(a.x, b.x, s[0][0]); s[0][1] = fmaf(a.x, b.y, s[0][1]);
            s[0][2] = fmaf(a.x, b.z, s[0][2]); s[0][3] = fmaf(a.x, b.w, s[0][3]);
            s[1][0] = fmaf(a.y, b.x, s[1][0]); s[1][1] = fmaf(a.y, b.y, s[1][1]);
            s[1][2] = fmaf(a.y, b.z, s[1][2]); s[1][3] = fmaf(a.y, b.w, s[1][3]);
            s[2][0] = fmaf(a.z, b.x, s[2][0]); s[2][1] = fmaf(a.z, b.y, s[2][1]);
            s[2][2] = fmaf(a.z, b.z, s[2][2]); s[2][3] = fmaf(a.z, b.w, s[2][3]);
            s[3][0] = fmaf(a.w, b.x, s[3][0]); s[3][1] = fmaf(a.w, b.y, s[3][1]);
            s[3][2] = fmaf(a.w, b.z, s[3][2]); s[3][3] = fmaf(a.w, b.w, s[3][3]);
        }

        // Online softmax per row (rows complete within 16-lane tx group).
#pragma unroll
        for (int i = 0; i < 4; i++) {
            float rm = fmaxf(fmaxf(s[i][0], s[i][1]), fmaxf(s[i][2], s[i][3]));
#pragma unroll
            for (int off = 8; off; off >>= 1)
                rm = fmaxf(rm, __shfl_xor_sync(0xffffffffu, rm, off));
            const float mnew = fmaxf(m[i], rm);
            const float corr = __expf(m[i] - mnew);
            float rs = 0.f;
#pragma unroll
            for (int j = 0; j < 4; j++) {
                s[i][j] = __expf(s[i][j] - mnew);   // s becomes p
                rs += s[i][j];
            }
#pragma unroll
            for (int off = 8; off; off >>= 1)
                rs += __shfl_xor_sync(0xffffffffu, rs, off);
            l[i] = l[i] * corr + rs;
            m[i] = mnew;
#pragma unroll
            for (int j = 0; j < 4; j++) acc[i][j] *= corr;
        }

        // Store P transposed (key-major). Warp-local: each warp owns rows
        // ty*4 for its two ty values; readers are same-warp threads.
#pragma unroll
        for (int j = 0; j < 4; j++) {
            float4 pv;
            pv.x = s[0][j]; pv.y = s[1][j]; pv.z = s[2][j]; pv.w = s[3][j];
            *(float4*)&Pst[(tx * 4 + j) * PSTRIDE + ty * 4] = pv;
        }
        __syncwarp();

        // O += P V  (contraction over keys)
#pragma unroll 8
        for (int kk = 0; kk < 64; kk++) {
            const float4 a = *(const float4*)&Pst[kk * PSTRIDE + ty * 4];
            const float4 b = *(const float4*)&Vs[kk * 64 + tx * 4];
            acc[0][0] = fmaf(a.x, b.x, acc[0][0]); acc[0][1] = fmaf(a.x, b.y, acc[0][1]);
            acc[0][2] = fmaf(a.x, b.z, acc[0][2]); acc[0][3] = fmaf(a.x, b.w, acc[0][3]);
            acc[1][0] = fmaf(a.y, b.x, acc[1][0]); acc[1][1] = fmaf(a.y, b.y, acc[1][1]);
            acc[1][2] = fmaf(a.y, b.z, acc[1][2]); acc[1][3] = fmaf(a.y, b.w, acc[1][3]);
            acc[2][0] = fmaf(a.z, b.x, acc[2][0]); acc[2][1] = fmaf(a.z, b.y, acc[2][1]);
            acc[2][2] = fmaf(a.z, b.z, acc[2][2]); acc[2][3] = fmaf(a.z, b.w, acc[2][3]);
            acc[3][0] = fmaf(a.w, b.x, acc[3][0]); acc[3][1] = fmaf(a.w, b.y, acc[3][1]);
            acc[3][2] = fmaf(a.w, b.z, acc[3][2]); acc[3][3] = fmaf(a.w, b.w, acc[3][3]);
        }
    }

    // Write O in [b, tok, h*64+d] layout (proj GEMM input layout).
    const int b = bh >> 4, h = bh & 15;
#pragma unroll
    for (int i = 0; i < 4; i++) {
        const int tok = qt * QT + ty * 4 + i;
        const float inv = 1.f / l[i];
        float4 o;
        o.x = acc[i][0] * inv; o.y = acc[i][1] * inv;
        o.z = acc[i][2] * inv; o.w = acc[i][3] * inv;
        *(float4*)&g_attn[((size_t)(b * SEQ + tok)) * DIM + h * HDIM + tx * 4] = o;
    }
}

// ---------------------------------------------------------------------------

extern "C" void kernel_launch(void* const* d_in, const int* in_sizes, int n_in,
                              void* d_out, int out_size)
{
    const float* x      = (const float*)d_in[0];
    const float* w_qkv  = (const float*)d_in[1];
    const float* b_qkv  = (const float*)d_in[2];
    const float* w_proj = (const float*)d_in[3];
    const float* b_proj = (const float*)d_in[4];
    float* out = (float*)d_out;

    cudaFuncSetAttribute(attn_kernel,
                         cudaFuncAttributeMaxDynamicSharedMemorySize,
                         ATTN_SMEM_BYTES);

    // QKV GEMM: M=4096, N=3072
    dim3 gq(3 * DIM / 128, M_TOK / 128);
    gemm_qkv_kernel<<<gq, 256>>>(x, w_qkv, b_qkv);

    // Attention
    dim3 ga(SEQ / QT, BATCH * NHEAD);
    attn_kernel<<<ga, 512, ATTN_SMEM_BYTES>>>();

    // Projection: M=4096, N=1024
    dim3 gp(DIM / 128, M_TOK / 128);
    gemm_proj_kernel<<<gp, 256>>>(w_proj, b_proj, out);
}

// round 3
// speedup vs baseline: 2.0744x; 1.0472x over previous
#include <cuda_runtime.h>
#include <cuda_bf16.h>

// Problem constants
#define BATCH 2
#define SEQ   2048
#define DIM   1024
#define NHEAD 16
#define HDIM  64
#define SCALE 0.125f   // 64^-0.5

#define M_TOK (BATCH * SEQ)          // 4096 rows of tokens

// Scratch (device globals: allocation-free rule)
// Q, K stored d-major: [b, h, d, tok]   (Q pre-scaled by SCALE)
// V stored tok-major:  [b, h, tok, d]
__device__ float g_Q[BATCH * NHEAD * HDIM * SEQ];
__device__ float g_K[BATCH * NHEAD * HDIM * SEQ];
__device__ float g_V[BATCH * NHEAD * SEQ * HDIM];
__device__ float g_attn[M_TOK * DIM];                 // [b*n, h*64+d]

// ---------------------------------------------------------------------------
// GEMM core: C[m,n] = sum_k A[m,k] * B[n,k]  (row-major, K-contiguous)
// BM=256, BN=128, BK=8, 256 threads, 16x8 micro-tile, reg-prefetch pipeline.
// ---------------------------------------------------------------------------

__global__ __launch_bounds__(256) void gemm_qkv_kernel(
    const float* __restrict__ A,      // x [4096, 1024]
    const float* __restrict__ Bw,     // w_qkv [3072, 1024]
    const float* __restrict__ bias)   // b_qkv [3072]
{
    const int K = DIM;
    __shared__ float As[8][256];
    __shared__ float Bs[8][128];

    const int tid = threadIdx.x;
    const int m0 = blockIdx.y * 256;
    const int n0 = blockIdx.x * 128;

    const int lrow = tid >> 1;          // 0..127
    const int lk4  = (tid & 1) * 4;     // 0 or 4

    const float* Ag0 = A  + (size_t)(m0 + lrow) * K + lk4;
    const float* Ag1 = Ag0 + (size_t)128 * K;
    const float* Bg  = Bw + (size_t)(n0 + lrow) * K + lk4;

    const int ty = tid >> 4;            // 0..15 -> rows ty*16..+15
    const int tx = tid & 15;            // 0..15 -> cols tx*8..+7

    float acc[16][8];
#pragma unroll
    for (int i = 0; i < 16; i++)
#pragma unroll
        for (int j = 0; j < 8; j++) acc[i][j] = 0.f;

    float4 ra0 = *(const float4*)(Ag0);
    float4 ra1 = *(const float4*)(Ag1);
    float4 rb  = *(const float4*)(Bg);

    for (int k0 = 0; k0 < K; k0 += 8) {
        As[lk4 + 0][lrow] = ra0.x; As[lk4 + 1][lrow] = ra0.y;
        As[lk4 + 2][lrow] = ra0.z; As[lk4 + 3][lrow] = ra0.w;
        As[lk4 + 0][lrow + 128] = ra1.x; As[lk4 + 1][lrow + 128] = ra1.y;
        As[lk4 + 2][lrow + 128] = ra1.z; As[lk4 + 3][lrow + 128] = ra1.w;
        Bs[lk4 + 0][lrow] = rb.x; Bs[lk4 + 1][lrow] = rb.y;
        Bs[lk4 + 2][lrow] = rb.z; Bs[lk4 + 3][lrow] = rb.w;
        __syncthreads();

        if (k0 + 8 < K) {
            ra0 = *(const float4*)(Ag0 + k0 + 8);
            ra1 = *(const float4*)(Ag1 + k0 + 8);
            rb  = *(const float4*)(Bg  + k0 + 8);
        }

#pragma unroll
        for (int kk = 0; kk < 8; kk++) {
            float a[16], b[8];
            *(float4*)&a[0]  = *(const float4*)&As[kk][ty * 16];
            *(float4*)&a[4]  = *(const float4*)&As[kk][ty * 16 + 4];
            *(float4*)&a[8]  = *(const float4*)&As[kk][ty * 16 + 8];
            *(float4*)&a[12] = *(const float4*)&As[kk][ty * 16 + 12];
            *(float4*)&b[0]  = *(const float4*)&Bs[kk][tx * 8];
            *(float4*)&b[4]  = *(const float4*)&Bs[kk][tx * 8 + 4];
#pragma unroll
            for (int i = 0; i < 16; i++)
#pragma unroll
                for (int j = 0; j < 8; j++)
                    acc[i][j] = fmaf(a[i], b[j], acc[i][j]);
        }
        __syncthreads();
    }

    // Epilogue: route 8 consecutive columns (one head chunk) to Q/K/V.
    const int n_base = n0 + tx * 8;
    const int which  = n_base >> 10;         // 0=Q 1=K 2=V
    const int rem    = n_base & 1023;
    const int h      = rem >> 6;
    const int d0     = rem & 63;

    float bb[8];
#pragma unroll
    for (int j = 0; j < 8; j++) bb[j] = bias[n_base + j];

    const int b    = m0 >> 11;               // batch (block within one batch)
    const int tok0 = (m0 & 2047) + ty * 16;

    if (which != 2) {
        // Q or K: store d-major [b,h,d,tok] (transposed), fold SCALE into Q.
        float* buf = (which == 0) ? g_Q : g_K;
        const float sc = (which == 0) ? SCALE : 1.f;
#pragma unroll
        for (int j = 0; j < 8; j++) {
            float* col = buf + ((size_t)((b * NHEAD + h) * HDIM + d0 + j)) * SEQ + tok0;
#pragma unroll
            for (int q = 0; q < 4; q++) {
                float4 v;
                v.x = (acc[q * 4 + 0][j] + bb[j]) * sc;
                v.y = (acc[q * 4 + 1][j] + bb[j]) * sc;
                v.z = (acc[q * 4 + 2][j] + bb[j]) * sc;
                v.w = (acc[q * 4 + 3][j] + bb[j]) * sc;
                *(float4*)(col + q * 4) = v;
            }
        }
    } else {
        // V: tok-major [b,h,tok,d]
#pragma unroll
        for (int i = 0; i < 16; i++) {
            const int tok = tok0 + i;
            float* orow = g_V + ((size_t)((b * NHEAD + h) * SEQ + tok)) * HDIM + d0;
            float4 v0, v1;
            v0.x = acc[i][0] + bb[0]; v0.y = acc[i][1] + bb[1];
            v0.z = acc[i][2] + bb[2]; v0.w = acc[i][3] + bb[3];
            v1.x = acc[i][4] + bb[4]; v1.y = acc[i][5] + bb[5];
            v1.z = acc[i][6] + bb[6]; v1.w = acc[i][7] + bb[7];
            *(float4*)(orow)     = v0;
            *(float4*)(orow + 4) = v1;
        }
    }
}

__global__ __launch_bounds__(256) void gemm_proj_kernel(
    const float* __restrict__ Bw,     // w_proj [1024, 1024]
    const float* __restrict__ bias,   // b_proj [1024]
    float* __restrict__ out)          // [4096, 1024]
{
    const int K = DIM;
    __shared__ float As[8][256];
    __shared__ float Bs[8][128];

    const int tid = threadIdx.x;
    const int m0 = blockIdx.y * 256;
    const int n0 = blockIdx.x * 128;

    const int lrow = tid >> 1;
    const int lk4  = (tid & 1) * 4;

    const float* Ag0 = g_attn + (size_t)(m0 + lrow) * K + lk4;
    const float* Ag1 = Ag0 + (size_t)128 * K;
    const float* Bg  = Bw + (size_t)(n0 + lrow) * K + lk4;

    const int ty = tid >> 4;
    const int tx = tid & 15;

    float acc[16][8];
#pragma unroll
    for (int i = 0; i < 16; i++)
#pragma unroll
        for (int j = 0; j < 8; j++) acc[i][j] = 0.f;

    float4 ra0 = *(const float4*)(Ag0);
    float4 ra1 = *(const float4*)(Ag1);
    float4 rb  = *(const float4*)(Bg);

    for (int k0 = 0; k0 < K; k0 += 8) {
        As[lk4 + 0][lrow] = ra0.x; As[lk4 + 1][lrow] = ra0.y;
        As[lk4 + 2][lrow] = ra0.z; As[lk4 + 3][lrow] = ra0.w;
        As[lk4 + 0][lrow + 128] = ra1.x; As[lk4 + 1][lrow + 128] = ra1.y;
        As[lk4 + 2][lrow + 128] = ra1.z; As[lk4 + 3][lrow + 128] = ra1.w;
        Bs[lk4 + 0][lrow] = rb.x; Bs[lk4 + 1][lrow] = rb.y;
        Bs[lk4 + 2][lrow] = rb.z; Bs[lk4 + 3][lrow] = rb.w;
        __syncthreads();

        if (k0 + 8 < K) {
            ra0 = *(const float4*)(Ag0 + k0 + 8);
            ra1 = *(const float4*)(Ag1 + k0 + 8);
            rb  = *(const float4*)(Bg  + k0 + 8);
        }

#pragma unroll
        for (int kk = 0; kk < 8; kk++) {
            float a[16], b[8];
            *(float4*)&a[0]  = *(const float4*)&As[kk][ty * 16];
            *(float4*)&a[4]  = *(const float4*)&As[kk][ty * 16 + 4];
            *(float4*)&a[8]  = *(const float4*)&As[kk][ty * 16 + 8];
            *(float4*)&a[12] = *(const float4*)&As[kk][ty * 16 + 12];
            *(float4*)&b[0]  = *(const float4*)&Bs[kk][tx * 8];
            *(float4*)&b[4]  = *(const float4*)&Bs[kk][tx * 8 + 4];
#pragma unroll
            for (int i = 0; i < 16; i++)
#pragma unroll
                for (int j = 0; j < 8; j++)
                    acc[i][j] = fmaf(a[i], b[j], acc[i][j]);
        }
        __syncthreads();
    }

    const int n_base = n0 + tx * 8;
    float bb[8];
#pragma unroll
    for (int j = 0; j < 8; j++) bb[j] = bias[n_base + j];

#pragma unroll
    for (int i = 0; i < 16; i++) {
        const int m = m0 + ty * 16 + i;
        float* orow = out + (size_t)m * DIM + n_base;
        float4 v0, v1;
        v0.x = acc[i][0] + bb[0]; v0.y = acc[i][1] + bb[1];
        v0.z = acc[i][2] + bb[2]; v0.w = acc[i][3] + bb[3];
        v1.x = acc[i][4] + bb[4]; v1.y = acc[i][5] + bb[5];
        v1.z = acc[i][6] + bb[6]; v1.w = acc[i][7] + bb[7];
        *(float4*)(orow)     = v0;
        *(float4*)(orow + 4) = v1;
    }
}

// ---------------------------------------------------------------------------
// Flash attention, GEMM-structured.
// Block: 128 q-rows x 64 keys/iter, 128 threads (16 ty x 8 tx), 8x8 fragments
// in both QK^T and PV -> 1 B/FMA in both inner loops.
// ---------------------------------------------------------------------------

#define QT 128
#define KT 64
#define PSTRIDE 132
// floats: Qst 64*128, Kst 64*64, Vs 64*64, Pst 64*132
#define ATTN_SMEM_FLOATS (64*128 + 64*64 + 64*64 + 64*PSTRIDE)
#define ATTN_SMEM_BYTES  (ATTN_SMEM_FLOATS * 4)

__global__ __launch_bounds__(128) void attn_kernel()
{
    extern __shared__ float sm[];
    float* Qst = sm;                       // [d=64][r=128]
    float* Kst = sm + 64 * 128;            // [d=64][c=64]
    float* Vs  = Kst + 64 * 64;            // [k=64][d=64]
    float* Pst = Vs + 64 * 64;             // [k=64][r=128 (+pad)]

    const int tid = threadIdx.x;
    const int ty  = tid >> 3;              // 0..15  (q rows ty*8..+7)
    const int tx  = tid & 7;               // 0..7   (cols tx*8..+7)
    const int bh  = blockIdx.y;            // 0..31
    const int qt  = blockIdx.x;            // 0..15

    const float* Qg = g_Q + (size_t)bh * HDIM * SEQ;   // [d][tok]
    const float* Kg = g_K + (size_t)bh * HDIM * SEQ;   // [d][tok]
    const float* Vg = g_V + (size_t)bh * SEQ * HDIM;   // [tok][d]

    // Load Q tile [64 d][128 r], coalesced.
#pragma unroll
    for (int i = 0; i < 16; i++) {
        const int v = tid + i * 128;       // 0..2047
        const int d = v >> 5;              // 0..63
        const int r4 = (v & 31) * 4;       // 0..124
        *(float4*)&Qst[d * 128 + r4] =
            *(const float4*)&Qg[(size_t)d * SEQ + qt * QT + r4];
    }

    float m[8], l[8], acc[8][8];
#pragma unroll
    for (int i = 0; i < 8; i++) {
        m[i] = -1e30f; l[i] = 0.f;
#pragma unroll
        for (int j = 0; j < 8; j++) acc[i][j] = 0.f;
    }

    for (int kt = 0; kt < SEQ / KT; kt++) {
        __syncthreads();
        // Load K tile [64 d][64 c] and V tile [64 k][64 d]
#pragma unroll
        for (int i = 0; i < 8; i++) {
            const int v = tid + i * 128;   // 0..1023
            const int r = v >> 4;          // 0..63
            const int c4 = (v & 15) * 4;   // 0..60
            *(float4*)&Kst[r * 64 + c4] =
                *(const float4*)&Kg[(size_t)r * SEQ + kt * KT + c4];
            *(float4*)&Vs[r * 64 + c4] =
                *(const float4*)&Vg[(size_t)(kt * KT + r) * HDIM + c4];
        }
        __syncthreads();

        // S = Q K^T  (contraction over d)
        float s[8][8];
#pragma unroll
        for (int i = 0; i < 8; i++)
#pragma unroll
            for (int j = 0; j < 8; j++) s[i][j] = 0.f;

#pragma unroll 4
        for (int kk = 0; kk < 64; kk++) {
            float a[8], b[8];
            *(float4*)&a[0] = *(const float4*)&Qst[kk * 128 + ty * 8];
            *(float4*)&a[4] = *(const float4*)&Qst[kk * 128 + ty * 8 + 4];
            *(float4*)&b[0] = *(const float4*)&Kst[kk * 64 + tx * 8];
            *(float4*)&b[4] = *(const float4*)&Kst[kk * 64 + tx * 8 + 4];
#pragma unroll
            for (int i = 0; i < 8; i++)
#pragma unroll
                for (int j = 0; j < 8; j++)
                    s[i][j] = fmaf(a[i], b[j], s[i][j]);
        }

        // Online softmax per row (row spread over 8 tx lanes).
#pragma unroll
        for (int i = 0; i < 8; i++) {
            float rm = s[i][0];
#pragma unroll
            for (int j = 1; j < 8; j++) rm = fmaxf(rm, s[i][j]);
#pragma unroll
            for (int off = 4; off; off >>= 1)
                rm = fmaxf(rm, __shfl_xor_sync(0xffffffffu, rm, off));
            const float mnew = fmaxf(m[i], rm);
            const float corr = __expf(m[i] - mnew);
            float rs = 0.f;
#pragma unroll
            for (int j = 0; j < 8; j++) {
                s[i][j] = __expf(s[i][j] - mnew);   // s becomes p
                rs += s[i][j];
            }
#pragma unroll
            for (int off = 4; off; off >>= 1)
                rs += __shfl_xor_sync(0xffffffffu, rs, off);
            l[i] = l[i] * corr + rs;
            m[i] = mnew;
#pragma unroll
            for (int j = 0; j < 8; j++) acc[i][j] *= corr;
        }

        // Store P transposed (key-major). Warp-local (same-ty readers in warp).
#pragma unroll
        for (int j = 0; j < 8; j++) {
            float4 p0, p1;
            p0.x = s[0][j]; p0.y = s[1][j]; p0.z = s[2][j]; p0.w = s[3][j];
            p1.x = s[4][j]; p1.y = s[5][j]; p1.z = s[6][j]; p1.w = s[7][j];
            *(float4*)&Pst[(tx * 8 + j) * PSTRIDE + ty * 8]     = p0;
            *(float4*)&Pst[(tx * 8 + j) * PSTRIDE + ty * 8 + 4] = p1;
        }
        __syncwarp();

        // O += P V  (contraction over keys)
#pragma unroll 4
        for (int kk = 0; kk < 64; kk++) {
            float a[8], b[8];
            *(float4*)&a[0] = *(const float4*)&Pst[kk * PSTRIDE + ty * 8];
            *(float4*)&a[4] = *(const float4*)&Pst[kk * PSTRIDE + ty * 8 + 4];
            *(float4*)&b[0] = *(const float4*)&Vs[kk * 64 + tx * 8];
            *(float4*)&b[4] = *(const float4*)&Vs[kk * 64 + tx * 8 + 4];
#pragma unroll
            for (int i = 0; i < 8; i++)
#pragma unroll
                for (int j = 0; j < 8; j++)
                    acc[i][j] = fmaf(a[i], b[j], acc[i][j]);
        }
        __syncwarp();
    }

    // Write O in [b, tok, h*64+d] layout (proj GEMM input layout).
    const int b = bh >> 4, h = bh & 15;
#pragma unroll
    for (int i = 0; i < 8; i++) {
        const int tok = qt * QT + ty * 8 + i;
        const float inv = 1.f / l[i];
        float4 o0, o1;
        o0.x = acc[i][0] * inv; o0.y = acc[i][1] * inv;
        o0.z = acc[i][2] * inv; o0.w = acc[i][3] * inv;
        o1.x = acc[i][4] * inv; o1.y = acc[i][5] * inv;
        o1.z = acc[i][6] * inv; o1.w = acc[i][7] * inv;
        float* orow = &g_attn[((size_t)(b * SEQ + tok)) * DIM + h * HDIM + tx * 8];
        *(float4*)(orow)     = o0;
        *(float4*)(orow + 4) = o1;
    }
}

// ---------------------------------------------------------------------------

extern "C" void kernel_launch(void* const* d_in, const int* in_sizes, int n_in,
                              void* d_out, int out_size)
{
    const float* x      = (const float*)d_in[0];
    const float* w_qkv  = (const float*)d_in[1];
    const float* b_qkv  = (const float*)d_in[2];
    const float* w_proj = (const float*)d_in[3];
    const float* b_proj = (const float*)d_in[4];
    float* out = (float*)d_out;

    cudaFuncSetAttribute(attn_kernel,
                         cudaFuncAttributeMaxDynamicSharedMemorySize,
                         ATTN_SMEM_BYTES);

    // QKV GEMM: M=4096, N=3072
    dim3 gq(3 * DIM / 128, M_TOK / 256);
    gemm_qkv_kernel<<<gq, 256>>>(x, w_qkv, b_qkv);

    // Attention
    dim3 ga(SEQ / QT, BATCH * NHEAD);
    attn_kernel<<<ga, 128, ATTN_SMEM_BYTES>>>();

    // Projection: M=4096, N=1024
    dim3 gp(DIM / 128, M_TOK / 256);
    gemm_proj_kernel<<<gp, 256>>>(w_proj, b_proj, out);
}

// round 5
// speedup vs baseline: 2.7368x; 1.3193x over previous
#include <cuda_runtime.h>
#include <cuda_bf16.h>
#include <cstdint>

// Problem constants
#define BATCH 2
#define SEQ   2048
#define DIM   1024
#define NHEAD 16
#define HDIM  64
#define SCALE 0.125f   // 64^-0.5

#define M_TOK (BATCH * SEQ)          // 4096 rows of tokens

// ---------------------------------------------------------------------------
// Scratch (device globals: allocation-free rule)
// ---------------------------------------------------------------------------
// Q, K stored d-major: [b, h, d, tok]   (Q pre-scaled by SCALE)
// V stored tok-major:  [b, h, tok, d]
__device__ float g_Q[BATCH * NHEAD * HDIM * SEQ];
__device__ float g_K[BATCH * NHEAD * HDIM * SEQ];
__device__ float g_V[BATCH * NHEAD * SEQ * HDIM];
__device__ float g_attn[M_TOK * DIM];                 // [b*n, h*64+d]

// bf16 hi/lo split scratch
__device__ __nv_bfloat16 g_xhi[M_TOK * DIM];
__device__ __nv_bfloat16 g_xlo[M_TOK * DIM];
__device__ __nv_bfloat16 g_wqhi[3 * DIM * DIM];
__device__ __nv_bfloat16 g_wqlo[3 * DIM * DIM];
__device__ __nv_bfloat16 g_wphi[DIM * DIM];
__device__ __nv_bfloat16 g_wplo[DIM * DIM];
__device__ __nv_bfloat16 g_ohi[M_TOK * DIM];
__device__ __nv_bfloat16 g_olo[M_TOK * DIM];

// ---------------------------------------------------------------------------
// PTX helpers: mma.sync / ldmatrix / cp.async (all valid at plain sm_103)
// ---------------------------------------------------------------------------
__device__ __forceinline__ uint32_t smem_u32(const void* p) {
    uint32_t a;
    asm("{ .reg .u64 t; cvta.to.shared.u64 t, %1; cvt.u32.u64 %0, t; }"
        : "=r"(a) : "l"(p));
    return a;
}

#define CP_ASYNC16(dst, src) \
    asm volatile("cp.async.cg.shared.global [%0], [%1], 16;" \
        :: "r"(dst), "l"(src))
#define CP_COMMIT() asm volatile("cp.async.commit_group;" ::: "memory")
#define CP_WAIT(n)  asm volatile("cp.async.wait_group %0;" :: "n"(n) : "memory")

#define LDSM4(r, addr) \
    asm volatile("ldmatrix.sync.aligned.m8n8.x4.shared.b16 {%0,%1,%2,%3}, [%4];" \
        : "=r"((r)[0]), "=r"((r)[1]), "=r"((r)[2]), "=r"((r)[3]) : "r"(addr))
#define LDSM2(r, addr) \
    asm volatile("ldmatrix.sync.aligned.m8n8.x2.shared.b16 {%0,%1}, [%2];" \
        : "=r"((r)[0]), "=r"((r)[1]) : "r"(addr))

#define MMA_BF16(d, a, b) \
    asm volatile("mma.sync.aligned.m16n8k16.row.col.f32.bf16.bf16.f32 " \
        "{%0,%1,%2,%3}, {%4,%5,%6,%7}, {%8,%9}, {%0,%1,%2,%3};" \
        : "+f"((d)[0]), "+f"((d)[1]), "+f"((d)[2]), "+f"((d)[3]) \
        : "r"((a)[0]), "r"((a)[1]), "r"((a)[2]), "r"((a)[3]), \
          "r"((b)[0]), "r"((b)[1]))

// ---------------------------------------------------------------------------
// fp32 -> bf16 hi/lo split converter
// ---------------------------------------------------------------------------
__global__ __launch_bounds__(256) void cvt_hilo_kernel(
    const float* __restrict__ x, __nv_bfloat16* __restrict__ hi,
    __nv_bfloat16* __restrict__ lo, int n4)
{
    const int i = blockIdx.x * blockDim.x + threadIdx.x;
    if (i >= n4) return;
    const float4 v = ((const float4*)x)[i];
    __nv_bfloat16 h0 = __float2bfloat16(v.x);
    __nv_bfloat16 h1 = __float2bfloat16(v.y);
    __nv_bfloat16 h2 = __float2bfloat16(v.z);
    __nv_bfloat16 h3 = __float2bfloat16(v.w);
    __nv_bfloat16 l0 = __float2bfloat16(v.x - __bfloat162float(h0));
    __nv_bfloat16 l1 = __float2bfloat16(v.y - __bfloat162float(h1));
    __nv_bfloat16 l2 = __float2bfloat16(v.z - __bfloat162float(h2));
    __nv_bfloat16 l3 = __float2bfloat16(v.w - __bfloat162float(h3));
    ((__nv_bfloat162*)hi)[2 * i]     = __nv_bfloat162(h0, h1);
    ((__nv_bfloat162*)hi)[2 * i + 1] = __nv_bfloat162(h2, h3);
    ((__nv_bfloat162*)lo)[2 * i]     = __nv_bfloat162(l0, l1);
    ((__nv_bfloat162*)lo)[2 * i + 1] = __nv_bfloat162(l2, l3);
}

// ---------------------------------------------------------------------------
// mma.sync bf16x3 GEMM: D[m,n] = sum_k A[m,k]*B[n,k] + bias[n]  (fp32 result)
// CTA 128x128, BK=32, 8 warps (64x32 warp tiles), cp.async double buffer.
// mode 0: QKV epilogue (scatter to g_Q/g_K/g_V); mode 1: plain row-major out.
// ---------------------------------------------------------------------------
#define BK 32
#define SROW 80                     // bytes per smem row (32 bf16 + 8 pad)
#define TILE_B (128 * SROW)         // 10240
#define STAGE_B (4 * TILE_B)        // 40960: Ahi, Alo, Bhi, Blo
#define GEMM_DYN_BYTES (2 * STAGE_B)
#define NCHUNK (DIM / BK)           // 32

__device__ __forceinline__ void stage_load(
    char* stage,
    const __nv_bfloat16* __restrict__ Ah, const __nv_bfloat16* __restrict__ Al,
    const __nv_bfloat16* __restrict__ Bh, const __nv_bfloat16* __restrict__ Bl,
    int k0, int tid)
{
    const int row  = tid >> 1;           // 0..127
    const int half = tid & 1;            // 0,1 -> 32B each
    const uint32_t doff = (uint32_t)(row * SROW + half * 32);
    const size_t goff = (size_t)row * DIM + k0 + half * 16;

    const uint32_t d0 = smem_u32(stage) + doff;
    CP_ASYNC16(d0,                      Ah + goff);
    CP_ASYNC16(d0 + 16,                 Ah + goff + 8);
    CP_ASYNC16(d0 + TILE_B,             Al + goff);
    CP_ASYNC16(d0 + TILE_B + 16,        Al + goff + 8);
    CP_ASYNC16(d0 + 2 * TILE_B,         Bh + goff);
    CP_ASYNC16(d0 + 2 * TILE_B + 16,    Bh + goff + 8);
    CP_ASYNC16(d0 + 3 * TILE_B,         Bl + goff);
    CP_ASYNC16(d0 + 3 * TILE_B + 16,    Bl + goff + 8);
}

__global__ __launch_bounds__(256) void gemm_bf16x3_kernel(
    const __nv_bfloat16* __restrict__ Ahi, const __nv_bfloat16* __restrict__ Alo,
    const __nv_bfloat16* __restrict__ Bhi, const __nv_bfloat16* __restrict__ Blo,
    const float* __restrict__ bias, float* __restrict__ outp, int mode)
{
    extern __shared__ __align__(128) char smd[];
    const uint32_t smb = smem_u32(smd);

    const int tid  = threadIdx.x;
    const int wid  = tid >> 5;
    const int lane = tid & 31;
    const int m0 = blockIdx.y * 128;
    const int n0 = blockIdx.x * 128;

    const int wm = (wid >> 2) * 64;      // warp m-offset in CTA tile
    const int wn = (wid & 3) * 32;       // warp n-offset

    const __nv_bfloat16* Ah = Ahi + (size_t)m0 * DIM;
    const __nv_bfloat16* Al = Alo + (size_t)m0 * DIM;
    const __nv_bfloat16* Bh = Bhi + (size_t)n0 * DIM;
    const __nv_bfloat16* Bl = Blo + (size_t)n0 * DIM;

    float acc[4][4][4];
#pragma unroll
    for (int i = 0; i < 4; i++)
#pragma unroll
        for (int j = 0; j < 4; j++)
#pragma unroll
            for (int e = 0; e < 4; e++) acc[i][j][e] = 0.f;

    // Precompute ldmatrix smem address components (byte offsets)
    const uint32_t a_row  = (uint32_t)(wm + (lane & 15));      // + 16*i
    const uint32_t a_coff = (uint32_t)((lane >> 4) * 16);      // + 32*ks
    const uint32_t b_row  = (uint32_t)(wn + (lane & 7));       // + 8*j
    const uint32_t b_coff = (uint32_t)(((lane >> 3) & 1) * 16);

    stage_load(smd, Ah, Al, Bh, Bl, 0, tid);
    CP_COMMIT();

    for (int c = 0; c < NCHUNK; ++c) {
        if (c + 1 < NCHUNK) {
            stage_load(smd + ((c + 1) & 1) * STAGE_B, Ah, Al, Bh, Bl,
                       (c + 1) * BK, tid);
            CP_COMMIT();
            CP_WAIT(1);
        } else {
            CP_WAIT(0);
        }
        __syncthreads();

        const uint32_t sb = smb + (c & 1) * STAGE_B;
#pragma unroll
        for (int ks = 0; ks < 2; ++ks) {
            // B fragments (hi and lo) for all 4 n-frags
            uint32_t bh[4][2], bl[4][2];
#pragma unroll
            for (int j = 0; j < 4; ++j) {
                const uint32_t ba =
                    sb + 2 * TILE_B + (b_row + 8 * j) * SROW + ks * 32 + b_coff;
                LDSM2(bh[j], ba);
                LDSM2(bl[j], ba + TILE_B);
            }
#pragma unroll
            for (int i = 0; i < 4; ++i) {
                uint32_t ah[4], al[4];
                const uint32_t aa =
                    sb + (a_row + 16 * i) * SROW + ks * 32 + a_coff;
                LDSM4(ah, aa);
                LDSM4(al, aa + TILE_B);
#pragma unroll
                for (int j = 0; j < 4; ++j) {
                    MMA_BF16(acc[i][j], ah, bh[j]);
                    MMA_BF16(acc[i][j], ah, bl[j]);
                    MMA_BF16(acc[i][j], al, bh[j]);
                }
            }
        }
        __syncthreads();
    }

    // -------------------- Epilogue --------------------
    // acc element map: c0:(m,n) c1:(m,n+1) c2:(m+8,n) c3:(m+8,n+1)
    // with m = wm + 16i + lane/4, n = wn + 8j + 2*(lane%4)
    const int mloc0 = wm + (lane >> 2);
    const int nloc0 = wn + (lane & 3) * 2;

    if (mode == 0) {
        const int which = n0 >> 10;          // 0=Q 1=K 2=V (CTA-uniform)
        const int bI    = m0 >> 11;
        const int tokb  = m0 & 2047;
#pragma unroll
        for (int i = 0; i < 4; ++i) {
#pragma unroll
            for (int j = 0; j < 4; ++j) {
                const int n_g = n0 + nloc0 + 8 * j;
                const int tok = tokb + mloc0 + 16 * i;
                const float bv0 = bias[n_g], bv1 = bias[n_g + 1];
                const int h = (n_g & 1023) >> 6;
                const int d = n_g & 63;
                if (which != 2) {
                    float* buf = (which == 0) ? g_Q : g_K;
                    const float sc = (which == 0) ? SCALE : 1.f;
                    float* base = buf +
                        ((size_t)((bI * NHEAD + h) * HDIM + d)) * SEQ + tok;
                    base[0]       = (acc[i][j][0] + bv0) * sc;
                    base[SEQ]     = (acc[i][j][1] + bv1) * sc;
                    base[8]       = (acc[i][j][2] + bv0) * sc;
                    base[SEQ + 8] = (acc[i][j][3] + bv1) * sc;
                } else {
                    float* r0 = g_V +
                        ((size_t)((bI * NHEAD + h) * SEQ + tok)) * HDIM + d;
                    *(float2*)r0 =
                        make_float2(acc[i][j][0] + bv0, acc[i][j][1] + bv1);
                    *(float2*)(r0 + 8 * HDIM) =
                        make_float2(acc[i][j][2] + bv0, acc[i][j][3] + bv1);
                }
            }
        }
    } else {
#pragma unroll
        for (int i = 0; i < 4; ++i) {
#pragma unroll
            for (int j = 0; j < 4; ++j) {
                const int n_g = n0 + nloc0 + 8 * j;
                const int m_g = m0 + mloc0 + 16 * i;
                const float bv0 = bias[n_g], bv1 = bias[n_g + 1];
                float* r0 = outp + (size_t)m_g * DIM + n_g;
                *(float2*)r0 =
                    make_float2(acc[i][j][0] + bv0, acc[i][j][1] + bv1);
                *(float2*)(r0 + 8 * DIM) =
                    make_float2(acc[i][j][2] + bv0, acc[i][j][3] + bv1);
            }
        }
    }
}

// ---------------------------------------------------------------------------
// Flash attention, fp32 (unchanged from R3).
// ---------------------------------------------------------------------------
#define QT 128
#define KT 64
#define PSTRIDE 132
#define ATTN_SMEM_FLOATS (64*128 + 64*64 + 64*64 + 64*PSTRIDE)
#define ATTN_SMEM_BYTES  (ATTN_SMEM_FLOATS * 4)

__global__ __launch_bounds__(128) void attn_kernel()
{
    extern __shared__ float sm[];
    float* Qst = sm;                       // [d=64][r=128]
    float* Kst = sm + 64 * 128;            // [d=64][c=64]
    float* Vs  = Kst + 64 * 64;            // [k=64][d=64]
    float* Pst = Vs + 64 * 64;             // [k=64][r=128 (+pad)]

    const int tid = threadIdx.x;
    const int ty  = tid >> 3;
    const int tx  = tid & 7;
    const int bh  = blockIdx.y;
    const int qt  = blockIdx.x;

    const float* Qg = g_Q + (size_t)bh * HDIM * SEQ;
    const float* Kg = g_K + (size_t)bh * HDIM * SEQ;
    const float* Vg = g_V + (size_t)bh * SEQ * HDIM;

#pragma unroll
    for (int i = 0; i < 16; i++) {
        const int v = tid + i * 128;
        const int d = v >> 5;
        const int r4 = (v & 31) * 4;
        *(float4*)&Qst[d * 128 + r4] =
            *(const float4*)&Qg[(size_t)d * SEQ + qt * QT + r4];
    }

    float m[8], l[8], acc[8][8];
#pragma unroll
    for (int i = 0; i < 8; i++) {
        m[i] = -1e30f; l[i] = 0.f;
#pragma unroll
        for (int j = 0; j < 8; j++) acc[i][j] = 0.f;
    }

    for (int kt = 0; kt < SEQ / KT; kt++) {
        __syncthreads();
#pragma unroll
        for (int i = 0; i < 8; i++) {
            const int v = tid + i * 128;
            const int r = v >> 4;
            const int c4 = (v & 15) * 4;
            *(float4*)&Kst[r * 64 + c4] =
                *(const float4*)&Kg[(size_t)r * SEQ + kt * KT + c4];
            *(float4*)&Vs[r * 64 + c4] =
                *(const float4*)&Vg[(size_t)(kt * KT + r) * HDIM + c4];
        }
        __syncthreads();

        float s[8][8];
#pragma unroll
        for (int i = 0; i < 8; i++)
#pragma unroll
            for (int j = 0; j < 8; j++) s[i][j] = 0.f;

#pragma unroll 4
        for (int kk = 0; kk < 64; kk++) {
            float a[8], b[8];
            *(float4*)&a[0] = *(const float4*)&Qst[kk * 128 + ty * 8];
            *(float4*)&a[4] = *(const float4*)&Qst[kk * 128 + ty * 8 + 4];
            *(float4*)&b[0] = *(const float4*)&Kst[kk * 64 + tx * 8];
            *(float4*)&b[4] = *(const float4*)&Kst[kk * 64 + tx * 8 + 4];
#pragma unroll
            for (int i = 0; i < 8; i++)
#pragma unroll
                for (int j = 0; j < 8; j++)
                    s[i][j] = fmaf(a[i], b[j], s[i][j]);
        }

#pragma unroll
        for (int i = 0; i < 8; i++) {
            float rm = s[i][0];
#pragma unroll
            for (int j = 1; j < 8; j++) rm = fmaxf(rm, s[i][j]);
#pragma unroll
            for (int off = 4; off; off >>= 1)
                rm = fmaxf(rm, __shfl_xor_sync(0xffffffffu, rm, off));
            const float mnew = fmaxf(m[i], rm);
            const float corr = __expf(m[i] - mnew);
            float rs = 0.f;
#pragma unroll
            for (int j = 0; j < 8; j++) {
                s[i][j] = __expf(s[i][j] - mnew);
                rs += s[i][j];
            }
#pragma unroll
            for (int off = 4; off; off >>= 1)
                rs += __shfl_xor_sync(0xffffffffu, rs, off);
            l[i] = l[i] * corr + rs;
            m[i] = mnew;
#pragma unroll
            for (int j = 0; j < 8; j++) acc[i][j] *= corr;
        }

#pragma unroll
        for (int j = 0; j < 8; j++) {
            float4 p0, p1;
            p0.x = s[0][j]; p0.y = s[1][j]; p0.z = s[2][j]; p0.w = s[3][j];
            p1.x = s[4][j]; p1.y = s[5][j]; p1.z = s[6][j]; p1.w = s[7][j];
            *(float4*)&Pst[(tx * 8 + j) * PSTRIDE + ty * 8]     = p0;
            *(float4*)&Pst[(tx * 8 + j) * PSTRIDE + ty * 8 + 4] = p1;
        }
        __syncwarp();

#pragma unroll 4
        for (int kk = 0; kk < 64; kk++) {
            float a[8], b[8];
            *(float4*)&a[0] = *(const float4*)&Pst[kk * PSTRIDE + ty * 8];
            *(float4*)&a[4] = *(const float4*)&Pst[kk * PSTRIDE + ty * 8 + 4];
            *(float4*)&b[0] = *(const float4*)&Vs[kk * 64 + tx * 8];
            *(float4*)&b[4] = *(const float4*)&Vs[kk * 64 + tx * 8 + 4];
#pragma unroll
            for (int i = 0; i < 8; i++)
#pragma unroll
                for (int j = 0; j < 8; j++)
                    acc[i][j] = fmaf(a[i], b[j], acc[i][j]);
        }
        __syncwarp();
    }

    const int b = bh >> 4, h = bh & 15;
#pragma unroll
    for (int i = 0; i < 8; i++) {
        const int tok = qt * QT + ty * 8 + i;
        const float inv = 1.f / l[i];
        float4 o0, o1;
        o0.x = acc[i][0] * inv; o0.y = acc[i][1] * inv;
        o0.z = acc[i][2] * inv; o0.w = acc[i][3] * inv;
        o1.x = acc[i][4] * inv; o1.y = acc[i][5] * inv;
        o1.z = acc[i][6] * inv; o1.w = acc[i][7] * inv;
        float* orow = &g_attn[((size_t)(b * SEQ + tok)) * DIM + h * HDIM + tx * 8];
        *(float4*)(orow)     = o0;
        *(float4*)(orow + 4) = o1;
    }
}

// ---------------------------------------------------------------------------

extern "C" void kernel_launch(void* const* d_in, const int* in_sizes, int n_in,
                              void* d_out, int out_size)
{
    const float* x      = (const float*)d_in[0];
    const float* w_qkv  = (const float*)d_in[1];
    const float* b_qkv  = (const float*)d_in[2];
    const float* w_proj = (const float*)d_in[3];
    const float* b_proj = (const float*)d_in[4];
    float* out = (float*)d_out;

    __nv_bfloat16 *h_xhi, *h_xlo, *h_wqhi, *h_wqlo, *h_wphi, *h_wplo,
                  *h_ohi, *h_olo;
    float* h_attn;
    cudaGetSymbolAddress((void**)&h_xhi,  g_xhi);
    cudaGetSymbolAddress((void**)&h_xlo,  g_xlo);
    cudaGetSymbolAddress((void**)&h_wqhi, g_wqhi);
    cudaGetSymbolAddress((void**)&h_wqlo, g_wqlo);
    cudaGetSymbolAddress((void**)&h_wphi, g_wphi);
    cudaGetSymbolAddress((void**)&h_wplo, g_wplo);
    cudaGetSymbolAddress((void**)&h_ohi,  g_ohi);
    cudaGetSymbolAddress((void**)&h_olo,  g_olo);
    cudaGetSymbolAddress((void**)&h_attn, g_attn);

    cudaFuncSetAttribute(attn_kernel,
                         cudaFuncAttributeMaxDynamicSharedMemorySize,
                         ATTN_SMEM_BYTES);
    cudaFuncSetAttribute(gemm_bf16x3_kernel,
                         cudaFuncAttributeMaxDynamicSharedMemorySize,
                         GEMM_DYN_BYTES);

    // 1. Split inputs/weights into bf16 hi/lo
    cvt_hilo_kernel<<<(M_TOK * DIM / 4 + 255) / 256, 256>>>(
        x, h_xhi, h_xlo, M_TOK * DIM / 4);
    cvt_hilo_kernel<<<(3 * DIM * DIM / 4 + 255) / 256, 256>>>(
        w_qkv, h_wqhi, h_wqlo, 3 * DIM * DIM / 4);
    cvt_hilo_kernel<<<(DIM * DIM / 4 + 255) / 256, 256>>>(
        w_proj, h_wphi, h_wplo, DIM * DIM / 4);

    // 2. QKV GEMM (tensor cores): M=4096, N=3072
    dim3 gq(3 * DIM / 128, M_TOK / 128);
    gemm_bf16x3_kernel<<<gq, 256, GEMM_DYN_BYTES>>>(
        h_xhi, h_xlo, h_wqhi, h_wqlo, b_qkv, nullptr, 0);

    // 3. Attention
    dim3 ga(SEQ / QT, BATCH * NHEAD);
    attn_kernel<<<ga, 128, ATTN_SMEM_BYTES>>>();

    // 4. Split attention output
    cvt_hilo_kernel<<<(M_TOK * DIM / 4 + 255) / 256, 256>>>(
        h_attn, h_ohi, h_olo, M_TOK * DIM / 4);

    // 5. Projection GEMM (tensor cores): M=4096, N=1024
    dim3 gp(DIM / 128, M_TOK / 128);
    gemm_bf16x3_kernel<<<gp, 256, GEMM_DYN_BYTES>>>(
        h_ohi, h_olo, h_wphi, h_wplo, b_proj, out, 1);
}

// round 6
// speedup vs baseline: 4.8202x; 1.7613x over previous
#include <cuda_runtime.h>
#include <cuda_bf16.h>
#include <cstdint>

// Problem constants
#define BATCH 2
#define SEQ   2048
#define DIM   1024
#define NHEAD 16
#define HDIM  64
// SCALE * log2(e): fold into Q so QK^T scores are already in base-2 domain
#define QSCALE (0.125f * 1.4426950408889634f)

#define M_TOK (BATCH * SEQ)          // 4096 rows of tokens
#define NBH   (BATCH * NHEAD)        // 32

// ---------------------------------------------------------------------------
// Scratch (device globals: allocation-free rule)
// ---------------------------------------------------------------------------
// Q,K: [bh][tok][64] bf16 hi/lo (Q pre-scaled by QSCALE)
// V:   [bh][d][tok]  bf16 hi/lo (d-major for PV B-fragments)
__device__ __nv_bfloat16 g_qhi[NBH * SEQ * HDIM];
__device__ __nv_bfloat16 g_qlo[NBH * SEQ * HDIM];
__device__ __nv_bfloat16 g_khi[NBH * SEQ * HDIM];
__device__ __nv_bfloat16 g_klo[NBH * SEQ * HDIM];
__device__ __nv_bfloat16 g_vhi[NBH * HDIM * SEQ];
__device__ __nv_bfloat16 g_vlo[NBH * HDIM * SEQ];
// attention output, hi/lo, [b*n][h*64+d]  (proj GEMM A input)
__device__ __nv_bfloat16 g_ohi[M_TOK * DIM];
__device__ __nv_bfloat16 g_olo[M_TOK * DIM];
// GEMM operand splits
__device__ __nv_bfloat16 g_xhi[M_TOK * DIM];
__device__ __nv_bfloat16 g_xlo[M_TOK * DIM];
__device__ __nv_bfloat16 g_wqhi[3 * DIM * DIM];
__device__ __nv_bfloat16 g_wqlo[3 * DIM * DIM];
__device__ __nv_bfloat16 g_wphi[DIM * DIM];
__device__ __nv_bfloat16 g_wplo[DIM * DIM];

// ---------------------------------------------------------------------------
// PTX helpers: mma.sync / ldmatrix / cp.async (valid at plain sm_103)
// ---------------------------------------------------------------------------
__device__ __forceinline__ uint32_t smem_u32(const void* p) {
    uint32_t a;
    asm("{ .reg .u64 t; cvta.to.shared.u64 t, %1; cvt.u32.u64 %0, t; }"
        : "=r"(a) : "l"(p));
    return a;
}

#define CP_ASYNC16(dst, src) \
    asm volatile("cp.async.cg.shared.global [%0], [%1], 16;" \
        :: "r"(dst), "l"(src))
#define CP_COMMIT() asm volatile("cp.async.commit_group;" ::: "memory")
#define CP_WAIT(n)  asm volatile("cp.async.wait_group %0;" :: "n"(n) : "memory")

#define LDSM4(r, addr) \
    asm volatile("ldmatrix.sync.aligned.m8n8.x4.shared.b16 {%0,%1,%2,%3}, [%4];" \
        : "=r"((r)[0]), "=r"((r)[1]), "=r"((r)[2]), "=r"((r)[3]) : "r"(addr))
#define LDSM2(r, addr) \
    asm volatile("ldmatrix.sync.aligned.m8n8.x2.shared.b16 {%0,%1}, [%2];" \
        : "=r"((r)[0]), "=r"((r)[1]) : "r"(addr))

#define MMA_BF16(d, a, b) \
    asm volatile("mma.sync.aligned.m16n8k16.row.col.f32.bf16.bf16.f32 " \
        "{%0,%1,%2,%3}, {%4,%5,%6,%7}, {%8,%9}, {%0,%1,%2,%3};" \
        : "+f"((d)[0]), "+f"((d)[1]), "+f"((d)[2]), "+f"((d)[3]) \
        : "r"((a)[0]), "r"((a)[1]), "r"((a)[2]), "r"((a)[3]), \
          "r"((b)[0]), "r"((b)[1]))

// fast 2^y for y <= 0 (FMA/ALU pipes, no MUFU): round via magic constant,
// degree-5 Taylor on r in [-0.5, 0.5], scale by bit-built 2^n.
__device__ __forceinline__ float fast_ex2(float y) {
    y = fmaxf(y, -120.f);
    const float z = y + 12582912.f;              // 1.5 * 2^23
    const float r = y - (z - 12582912.f);
    const uint32_t fb = (__float_as_uint(z) + 0xB4C0007Fu) << 23;  // 2^n
    float p = 0.0013333558f;
    p = fmaf(p, r, 0.0096181291f);
    p = fmaf(p, r, 0.0555041087f);
    p = fmaf(p, r, 0.2402265069f);
    p = fmaf(p, r, 0.6931471806f);
    p = fmaf(p, r, 1.0f);
    return __uint_as_float(fb) * p;
}

__device__ __forceinline__ uint32_t split_hi2(float x, float y) {
    __nv_bfloat162 h = __floats2bfloat162_rn(x, y);
    return *(uint32_t*)&h;
}
__device__ __forceinline__ uint32_t split_lo2(float x, float y, uint32_t hi2) {
    __nv_bfloat162 h = *(__nv_bfloat162*)&hi2;
    __nv_bfloat162 l = __floats2bfloat162_rn(x - __bfloat162float(h.x),
                                             y - __bfloat162float(h.y));
    return *(uint32_t*)&l;
}

// ---------------------------------------------------------------------------
// fp32 -> bf16 hi/lo split converter
// ---------------------------------------------------------------------------
__global__ __launch_bounds__(256) void cvt_hilo_kernel(
    const float* __restrict__ x, __nv_bfloat16* __restrict__ hi,
    __nv_bfloat16* __restrict__ lo, int n4)
{
    const int i = blockIdx.x * blockDim.x + threadIdx.x;
    if (i >= n4) return;
    const float4 v = ((const float4*)x)[i];
    uint32_t h0 = split_hi2(v.x, v.y), h1 = split_hi2(v.z, v.w);
    uint32_t l0 = split_lo2(v.x, v.y, h0), l1 = split_lo2(v.z, v.w, h1);
    ((uint32_t*)hi)[2 * i]     = h0;
    ((uint32_t*)hi)[2 * i + 1] = h1;
    ((uint32_t*)lo)[2 * i]     = l0;
    ((uint32_t*)lo)[2 * i + 1] = l1;
}

// ---------------------------------------------------------------------------
// mma.sync bf16x3 GEMM: D[m,n] = sum_k A[m,k]*B[n,k] + bias[n]
// CTA 128x128, BK=32, 8 warps, cp.async double buffer.
// mode 0: QKV epilogue (emit bf16 hi/lo Q/K/V in attention layouts)
// mode 1: plain fp32 row-major out.
// ---------------------------------------------------------------------------
#define BK 32
#define SROW 80
#define TILE_B (128 * SROW)
#define STAGE_B (4 * TILE_B)
#define GEMM_DYN_BYTES (2 * STAGE_B)
#define NCHUNK (DIM / BK)

__device__ __forceinline__ void stage_load(
    char* stage,
    const __nv_bfloat16* __restrict__ Ah, const __nv_bfloat16* __restrict__ Al,
    const __nv_bfloat16* __restrict__ Bh, const __nv_bfloat16* __restrict__ Bl,
    int k0, int tid)
{
    const int row  = tid >> 1;
    const int half = tid & 1;
    const uint32_t doff = (uint32_t)(row * SROW + half * 32);
    const size_t goff = (size_t)row * DIM + k0 + half * 16;

    const uint32_t d0 = smem_u32(stage) + doff;
    CP_ASYNC16(d0,                   Ah + goff);
    CP_ASYNC16(d0 + 16,              Ah + goff + 8);
    CP_ASYNC16(d0 + TILE_B,          Al + goff);
    CP_ASYNC16(d0 + TILE_B + 16,     Al + goff + 8);
    CP_ASYNC16(d0 + 2 * TILE_B,      Bh + goff);
    CP_ASYNC16(d0 + 2 * TILE_B + 16, Bh + goff + 8);
    CP_ASYNC16(d0 + 3 * TILE_B,      Bl + goff);
    CP_ASYNC16(d0 + 3 * TILE_B + 16, Bl + goff + 8);
}

__global__ __launch_bounds__(256) void gemm_bf16x3_kernel(
    const __nv_bfloat16* __restrict__ Ahi, const __nv_bfloat16* __restrict__ Alo,
    const __nv_bfloat16* __restrict__ Bhi, const __nv_bfloat16* __restrict__ Blo,
    const float* __restrict__ bias, float* __restrict__ outp, int mode)
{
    extern __shared__ __align__(128) char smd[];
    const uint32_t smb = smem_u32(smd);

    const int tid  = threadIdx.x;
    const int wid  = tid >> 5;
    const int lane = tid & 31;
    const int m0 = blockIdx.y * 128;
    const int n0 = blockIdx.x * 128;

    const int wm = (wid >> 2) * 64;
    const int wn = (wid & 3) * 32;

    const __nv_bfloat16* Ah = Ahi + (size_t)m0 * DIM;
    const __nv_bfloat16* Al = Alo + (size_t)m0 * DIM;
    const __nv_bfloat16* Bh = Bhi + (size_t)n0 * DIM;
    const __nv_bfloat16* Bl = Blo + (size_t)n0 * DIM;

    float acc[4][4][4];
#pragma unroll
    for (int i = 0; i < 4; i++)
#pragma unroll
        for (int j = 0; j < 4; j++)
#pragma unroll
            for (int e = 0; e < 4; e++) acc[i][j][e] = 0.f;

    const uint32_t a_row  = (uint32_t)(wm + (lane & 15));
    const uint32_t a_coff = (uint32_t)((lane >> 4) * 16);
    const uint32_t b_row  = (uint32_t)(wn + (lane & 7));
    const uint32_t b_coff = (uint32_t)(((lane >> 3) & 1) * 16);

    stage_load(smd, Ah, Al, Bh, Bl, 0, tid);
    CP_COMMIT();

    for (int c = 0; c < NCHUNK; ++c) {
        if (c + 1 < NCHUNK) {
            stage_load(smd + ((c + 1) & 1) * STAGE_B, Ah, Al, Bh, Bl,
                       (c + 1) * BK, tid);
            CP_COMMIT();
            CP_WAIT(1);
        } else {
            CP_WAIT(0);
        }
        __syncthreads();

        const uint32_t sb = smb + (c & 1) * STAGE_B;
#pragma unroll
        for (int ks = 0; ks < 2; ++ks) {
            uint32_t bhf[4][2], blf[4][2];
#pragma unroll
            for (int j = 0; j < 4; ++j) {
                const uint32_t ba =
                    sb + 2 * TILE_B + (b_row + 8 * j) * SROW + ks * 32 + b_coff;
                LDSM2(bhf[j], ba);
                LDSM2(blf[j], ba + TILE_B);
            }
#pragma unroll
            for (int i = 0; i < 4; ++i) {
                uint32_t ahf[4], alf[4];
                const uint32_t aa =
                    sb + (a_row + 16 * i) * SROW + ks * 32 + a_coff;
                LDSM4(ahf, aa);
                LDSM4(alf, aa + TILE_B);
#pragma unroll
                for (int j = 0; j < 4; ++j) {
                    MMA_BF16(acc[i][j], ahf, bhf[j]);
                    MMA_BF16(acc[i][j], ahf, blf[j]);
                    MMA_BF16(acc[i][j], alf, bhf[j]);
                }
            }
        }
        __syncthreads();
    }

    // Epilogue. acc map: c0:(m,n) c1:(m,n+1) c2:(m+8,n) c3:(m+8,n+1)
    const int mloc0 = wm + (lane >> 2);
    const int nloc0 = wn + (lane & 3) * 2;

    if (mode == 0) {
        const int which = n0 >> 10;          // 0=Q 1=K 2=V (CTA-uniform)
        const int bI    = m0 >> 11;
        const int tokb  = m0 & 2047;
#pragma unroll
        for (int i = 0; i < 4; ++i) {
#pragma unroll
            for (int j = 0; j < 4; ++j) {
                const int n_g = n0 + nloc0 + 8 * j;
                const int tok = tokb + mloc0 + 16 * i;
                const int h = (n_g & 1023) >> 6;
                const int d = n_g & 63;
                const int bh = bI * NHEAD + h;
                float v0 = acc[i][j][0] + bias[n_g];
                float v1 = acc[i][j][1] + bias[n_g + 1];
                float v2 = acc[i][j][2] + bias[n_g];
                float v3 = acc[i][j][3] + bias[n_g + 1];
                if (which == 0) {
                    v0 *= QSCALE; v1 *= QSCALE; v2 *= QSCALE; v3 *= QSCALE;
                    const size_t a0 = ((size_t)bh * SEQ + tok) * HDIM + d;
                    uint32_t h2 = split_hi2(v0, v1);
                    *(uint32_t*)(g_qhi + a0) = h2;
                    *(uint32_t*)(g_qlo + a0) = split_lo2(v0, v1, h2);
                    h2 = split_hi2(v2, v3);
                    *(uint32_t*)(g_qhi + a0 + 8 * HDIM) = h2;
                    *(uint32_t*)(g_qlo + a0 + 8 * HDIM) = split_lo2(v2, v3, h2);
                } else if (which == 1) {
                    const size_t a0 = ((size_t)bh * SEQ + tok) * HDIM + d;
                    uint32_t h2 = split_hi2(v0, v1);
                    *(uint32_t*)(g_khi + a0) = h2;
                    *(uint32_t*)(g_klo + a0) = split_lo2(v0, v1, h2);
                    h2 = split_hi2(v2, v3);
                    *(uint32_t*)(g_khi + a0 + 8 * HDIM) = h2;
                    *(uint32_t*)(g_klo + a0 + 8 * HDIM) = split_lo2(v2, v3, h2);
                } else {
                    // V d-major: [bh][d][tok]
                    const size_t b0 = ((size_t)bh * HDIM + d) * SEQ + tok;
                    __nv_bfloat16 t;
                    t = __float2bfloat16(v0); g_vhi[b0] = t;
                    g_vlo[b0] = __float2bfloat16(v0 - __bfloat162float(t));
                    t = __float2bfloat16(v1); g_vhi[b0 + SEQ] = t;
                    g_vlo[b0 + SEQ] = __float2bfloat16(v1 - __bfloat162float(t));
                    t = __float2bfloat16(v2); g_vhi[b0 + 8] = t;
                    g_vlo[b0 + 8] = __float2bfloat16(v2 - __bfloat162float(t));
                    t = __float2bfloat16(v3); g_vhi[b0 + SEQ + 8] = t;
                    g_vlo[b0 + SEQ + 8] =
                        __float2bfloat16(v3 - __bfloat162float(t));
                }
            }
        }
    } else {
#pragma unroll
        for (int i = 0; i < 4; ++i) {
#pragma unroll
            for (int j = 0; j < 4; ++j) {
                const int n_g = n0 + nloc0 + 8 * j;
                const int m_g = m0 + mloc0 + 16 * i;
                const float bv0 = bias[n_g], bv1 = bias[n_g + 1];
                float* r0 = outp + (size_t)m_g * DIM + n_g;
                *(float2*)r0 =
                    make_float2(acc[i][j][0] + bv0, acc[i][j][1] + bv1);
                *(float2*)(r0 + 8 * DIM) =
                    make_float2(acc[i][j][2] + bv0, acc[i][j][3] + bv1);
            }
        }
    }
}

// ---------------------------------------------------------------------------
// Flash attention on mma.sync bf16x3.
// CTA: 128 q-rows x one bh; 8 warps, warp = 16 q-rows.
// K-tile 64 keys, cp.async double buffered. Q frags register-resident.
// P stays in registers (accumulator fragment == A fragment layout).
// ---------------------------------------------------------------------------
#define AT_SROW 144                       // 64 bf16 + 16B pad
#define AT_QT_B (128 * AT_SROW)           // 18432
#define AT_KT_B (64 * AT_SROW)            // 9216
#define AT_ST_B (4 * AT_KT_B)             // 36864
#define AT_SMEM (2 * AT_QT_B + 2 * AT_ST_B)   // 110592

__device__ __forceinline__ void load_kv_tile(uint32_t st, int bh, int kt, int tid)
{
    const __nv_bfloat16* kh = g_khi + ((size_t)bh * SEQ + kt * 64) * HDIM;
    const __nv_bfloat16* kl = g_klo + ((size_t)bh * SEQ + kt * 64) * HDIM;
    const __nv_bfloat16* vh = g_vhi + (size_t)bh * HDIM * SEQ + kt * 64;
    const __nv_bfloat16* vl = g_vlo + (size_t)bh * HDIM * SEQ + kt * 64;
#pragma unroll
    for (int i = 0; i < 2; i++) {
        const int idx = tid + i * 256;    // 0..511
        const int row = idx >> 3, ch = idx & 7;
        const uint32_t so = (uint32_t)(row * AT_SROW + ch * 16);
        CP_ASYNC16(st + so,               kh + (size_t)row * HDIM + ch * 8);
        CP_ASYNC16(st + AT_KT_B + so,     kl + (size_t)row * HDIM + ch * 8);
        CP_ASYNC16(st + 2 * AT_KT_B + so, vh + (size_t)row * SEQ + ch * 8);
        CP_ASYNC16(st + 3 * AT_KT_B + so, vl + (size_t)row * SEQ + ch * 8);
    }
}

__global__ __launch_bounds__(256) void attn_mma_kernel()
{
    extern __shared__ __align__(128) char sm[];
    const uint32_t smb  = smem_u32(sm);
    const uint32_t q_hi = smb;
    const uint32_t q_lo = smb + AT_QT_B;
    const uint32_t st0  = smb + 2 * AT_QT_B;

    const int tid = threadIdx.x;
    const int wid = tid >> 5, lane = tid & 31;
    const int qt = blockIdx.x, bh = blockIdx.y;

    // Load Q tile (hi/lo), 128 rows x 64 bf16
    {
        const __nv_bfloat16* qh = g_qhi + ((size_t)bh * SEQ + qt * 128) * HDIM;
        const __nv_bfloat16* ql = g_qlo + ((size_t)bh * SEQ + qt * 128) * HDIM;
#pragma unroll
        for (int i = 0; i < 4; i++) {
            const int idx = tid + i * 256;     // 0..1023
            const int row = idx >> 3, ch = idx & 7;
            const uint32_t so = (uint32_t)(row * AT_SROW + ch * 16);
            CP_ASYNC16(q_hi + so, qh + (size_t)row * HDIM + ch * 8);
            CP_ASYNC16(q_lo + so, ql + (size_t)row * HDIM + ch * 8);
        }
        CP_COMMIT();
    }
    load_kv_tile(st0, bh, 0, tid);
    CP_COMMIT();
    CP_WAIT(1);                // Q complete (KV tile 0 may be pending)
    __syncthreads();

    // Q A-fragments, register-resident: 4 ksteps x hi/lo
    uint32_t qhf[4][4], qlf[4][4];
    {
        const uint32_t qa =
            (uint32_t)((wid * 16 + (lane & 15)) * AT_SROW + (lane >> 4) * 16);
#pragma unroll
        for (int t = 0; t < 4; t++) {
            LDSM4(qhf[t], q_hi + qa + t * 32);
            LDSM4(qlf[t], q_lo + qa + t * 32);
        }
    }

    float m2[2] = {-1e30f, -1e30f}, l[2] = {0.f, 0.f};
    float po[8][4];
#pragma unroll
    for (int j = 0; j < 8; j++)
#pragma unroll
        for (int e = 0; e < 4; e++) po[j][e] = 0.f;

    const uint32_t brow =
        (uint32_t)((lane & 7) * AT_SROW + ((lane >> 3) & 1) * 16);

    for (int kt = 0; kt < SEQ / 64; kt++) {
        if (kt + 1 < SEQ / 64) {
            load_kv_tile(st0 + ((kt + 1) & 1) * AT_ST_B, bh, kt + 1, tid);
            CP_COMMIT();
            CP_WAIT(1);
        } else {
            CP_WAIT(0);
        }
        __syncthreads();

        const uint32_t sk  = st0 + (kt & 1) * AT_ST_B;
        const uint32_t skl = sk + AT_KT_B;
        const uint32_t sv  = sk + 2 * AT_KT_B;
        const uint32_t svl = sk + 3 * AT_KT_B;

        // S = Q K^T (base-2 scores; QSCALE folded into Q)
        float s[8][4];
#pragma unroll
        for (int j = 0; j < 8; j++)
#pragma unroll
            for (int e = 0; e < 4; e++) s[j][e] = 0.f;

#pragma unroll
        for (int j = 0; j < 8; j++) {
            const uint32_t kb = sk + (uint32_t)(j * 8 * AT_SROW) + brow;
#pragma unroll
            for (int t = 0; t < 4; t++) {
                uint32_t kbh[2], kbl[2];
                LDSM2(kbh, kb + t * 32);
                LDSM2(kbl, kb + AT_KT_B + t * 32);
                MMA_BF16(s[j], qhf[t], kbh);
                MMA_BF16(s[j], qhf[t], kbl);
                MMA_BF16(s[j], qlf[t], kbh);
            }
        }

        // Online softmax (rows r=lane>>2 and r+8; quad holds a row)
        float rmx0 = s[0][0], rmx1 = s[0][2];
#pragma unroll
        for (int j = 0; j < 8; j++) {
            rmx0 = fmaxf(rmx0, fmaxf(s[j][0], s[j][1]));
            rmx1 = fmaxf(rmx1, fmaxf(s[j][2], s[j][3]));
        }
        rmx0 = fmaxf(rmx0, __shfl_xor_sync(0xffffffffu, rmx0, 1));
        rmx0 = fmaxf(rmx0, __shfl_xor_sync(0xffffffffu, rmx0, 2));
        rmx1 = fmaxf(rmx1, __shfl_xor_sync(0xffffffffu, rmx1, 1));
        rmx1 = fmaxf(rmx1, __shfl_xor_sync(0xffffffffu, rmx1, 2));

        const float mn0 = fmaxf(m2[0], rmx0);
        const float mn1 = fmaxf(m2[1], rmx1);
        const float c0 = fast_ex2(m2[0] - mn0);
        const float c1 = fast_ex2(m2[1] - mn1);
        m2[0] = mn0; m2[1] = mn1;

        float rs0 = 0.f, rs1 = 0.f;
#pragma unroll
        for (int j = 0; j < 8; j++) {
            s[j][0] = fast_ex2(s[j][0] - mn0);
            s[j][1] = fast_ex2(s[j][1] - mn0);
            s[j][2] = fast_ex2(s[j][2] - mn1);
            s[j][3] = fast_ex2(s[j][3] - mn1);
            rs0 += s[j][0] + s[j][1];
            rs1 += s[j][2] + s[j][3];
        }
        rs0 += __shfl_xor_sync(0xffffffffu, rs0, 1);
        rs0 += __shfl_xor_sync(0xffffffffu, rs0, 2);
        rs1 += __shfl_xor_sync(0xffffffffu, rs1, 1);
        rs1 += __shfl_xor_sync(0xffffffffu, rs1, 2);
        l[0] = l[0] * c0 + rs0;
        l[1] = l[1] * c1 + rs1;
#pragma unroll
        for (int j = 0; j < 8; j++) {
            po[j][0] *= c0; po[j][1] *= c0;
            po[j][2] *= c1; po[j][3] *= c1;
        }

        // O += P V : P accumulator fragment doubles as A fragment.
#pragma unroll
        for (int t = 0; t < 4; t++) {
            uint32_t ph[4], pl[4];
            ph[0] = split_hi2(s[2 * t][0],     s[2 * t][1]);
            ph[1] = split_hi2(s[2 * t][2],     s[2 * t][3]);
            ph[2] = split_hi2(s[2 * t + 1][0], s[2 * t + 1][1]);
            ph[3] = split_hi2(s[2 * t + 1][2], s[2 * t + 1][3]);
            pl[0] = split_lo2(s[2 * t][0],     s[2 * t][1],     ph[0]);
            pl[1] = split_lo2(s[2 * t][2],     s[2 * t][3],     ph[1]);
            pl[2] = split_lo2(s[2 * t + 1][0], s[2 * t + 1][1], ph[2]);
            pl[3] = split_lo2(s[2 * t + 1][2], s[2 * t + 1][3], ph[3]);
#pragma unroll
            for (int j = 0; j < 8; j++) {
                const uint32_t vb = sv + (uint32_t)(j * 8 * AT_SROW) + brow;
                uint32_t vbh[2], vbl[2];
                LDSM2(vbh, vb + t * 32);
                LDSM2(vbl, vb + AT_KT_B + t * 32);
                MMA_BF16(po[j], ph, vbh);
                MMA_BF16(po[j], ph, vbl);
                MMA_BF16(po[j], pl, vbh);
            }
        }
        __syncthreads();
    }

    // Epilogue: O/l -> bf16 hi/lo [tok][h*64+d]
    const int h = bh & 15, bb = bh >> 4;
    const int tok0 = qt * 128 + wid * 16 + (lane >> 2);
    const float inv0 = 1.f / l[0], inv1 = 1.f / l[1];
#pragma unroll
    for (int j = 0; j < 8; j++) {
        const int d = h * HDIM + j * 8 + (lane & 3) * 2;
        const size_t a0 = ((size_t)(bb * SEQ + tok0)) * DIM + d;
        const size_t a1 = a0 + (size_t)8 * DIM;
        const float v0 = po[j][0] * inv0, v1 = po[j][1] * inv0;
        const float v2 = po[j][2] * inv1, v3 = po[j][3] * inv1;
        uint32_t h2 = split_hi2(v0, v1);
        *(uint32_t*)(g_ohi + a0) = h2;
        *(uint32_t*)(g_olo + a0) = split_lo2(v0, v1, h2);
        h2 = split_hi2(v2, v3);
        *(uint32_t*)(g_ohi + a1) = h2;
        *(uint32_t*)(g_olo + a1) = split_lo2(v2, v3, h2);
    }
}

// ---------------------------------------------------------------------------

extern "C" void kernel_launch(void* const* d_in, const int* in_sizes, int n_in,
                              void* d_out, int out_size)
{
    const float* x      = (const float*)d_in[0];
    const float* w_qkv  = (const float*)d_in[1];
    const float* b_qkv  = (const float*)d_in[2];
    const float* w_proj = (const float*)d_in[3];
    const float* b_proj = (const float*)d_in[4];
    float* out = (float*)d_out;

    __nv_bfloat16 *h_xhi, *h_xlo, *h_wqhi, *h_wqlo, *h_wphi, *h_wplo,
                  *h_ohi, *h_olo;
    cudaGetSymbolAddress((void**)&h_xhi,  g_xhi);
    cudaGetSymbolAddress((void**)&h_xlo,  g_xlo);
    cudaGetSymbolAddress((void**)&h_wqhi, g_wqhi);
    cudaGetSymbolAddress((void**)&h_wqlo, g_wqlo);
    cudaGetSymbolAddress((void**)&h_wphi, g_wphi);
    cudaGetSymbolAddress((void**)&h_wplo, g_wplo);
    cudaGetSymbolAddress((void**)&h_ohi,  g_ohi);
    cudaGetSymbolAddress((void**)&h_olo,  g_olo);

    cudaFuncSetAttribute(gemm_bf16x3_kernel,
                         cudaFuncAttributeMaxDynamicSharedMemorySize,
                         GEMM_DYN_BYTES);
    cudaFuncSetAttribute(attn_mma_kernel,
                         cudaFuncAttributeMaxDynamicSharedMemorySize,
                         AT_SMEM);

    // 1. Split inputs/weights into bf16 hi/lo
    cvt_hilo_kernel<<<(M_TOK * DIM / 4 + 255) / 256, 256>>>(
        x, h_xhi, h_xlo, M_TOK * DIM / 4);
    cvt_hilo_kernel<<<(3 * DIM * DIM / 4 + 255) / 256, 256>>>(
        w_qkv, h_wqhi, h_wqlo, 3 * DIM * DIM / 4);
    cvt_hilo_kernel<<<(DIM * DIM / 4 + 255) / 256, 256>>>(
        w_proj, h_wphi, h_wplo, DIM * DIM / 4);

    // 2. QKV GEMM -> bf16 hi/lo Q/K/V in attention layouts
    dim3 gq(3 * DIM / 128, M_TOK / 128);
    gemm_bf16x3_kernel<<<gq, 256, GEMM_DYN_BYTES>>>(
        h_xhi, h_xlo, h_wqhi, h_wqlo, b_qkv, nullptr, 0);

    // 3. Tensor-core flash attention -> g_ohi/g_olo
    dim3 ga(SEQ / 128, NBH);
    attn_mma_kernel<<<ga, 256, AT_SMEM>>>();

    // 4. Projection GEMM: M=4096, N=1024
    dim3 gp(DIM / 128, M_TOK / 128);
    gemm_bf16x3_kernel<<<gp, 256, GEMM_DYN_BYTES>>>(
        h_ohi, h_olo, h_wphi, h_wplo, b_proj, out, 1);
}

// round 8
// speedup vs baseline: 5.1592x; 1.0703x over previous
#include <cuda_runtime.h>
#include <cuda_bf16.h>
#include <cstdint>

// Problem constants
#define BATCH 2
#define SEQ   2048
#define DIM   1024
#define NHEAD 16
#define HDIM  64
// SCALE * log2(e): fold into Q so QK^T scores are already in base-2 domain
#define QSCALE (0.125f * 1.4426950408889634f)

#define M_TOK (BATCH * SEQ)          // 4096 rows of tokens
#define NBH   (BATCH * NHEAD)        // 32

// ---------------------------------------------------------------------------
// Scratch (device globals: allocation-free rule)
// ---------------------------------------------------------------------------
// Q,K: [bh][tok][64] bf16 hi/lo (Q pre-scaled by QSCALE)
// V:   [bh][d][tok]  bf16 hi/lo (d-major for PV B-fragments)
__device__ __nv_bfloat16 g_qhi[NBH * SEQ * HDIM];
__device__ __nv_bfloat16 g_qlo[NBH * SEQ * HDIM];
__device__ __nv_bfloat16 g_khi[NBH * SEQ * HDIM];
__device__ __nv_bfloat16 g_klo[NBH * SEQ * HDIM];
__device__ __nv_bfloat16 g_vhi[NBH * HDIM * SEQ];
__device__ __nv_bfloat16 g_vlo[NBH * HDIM * SEQ];
// attention output, hi/lo, [b*n][h*64+d]  (proj GEMM A input)
__device__ __nv_bfloat16 g_ohi[M_TOK * DIM];
__device__ __nv_bfloat16 g_olo[M_TOK * DIM];
// GEMM operand splits
__device__ __nv_bfloat16 g_xhi[M_TOK * DIM];
__device__ __nv_bfloat16 g_xlo[M_TOK * DIM];
__device__ __nv_bfloat16 g_wqhi[3 * DIM * DIM];
__device__ __nv_bfloat16 g_wqlo[3 * DIM * DIM];
__device__ __nv_bfloat16 g_wphi[DIM * DIM];
__device__ __nv_bfloat16 g_wplo[DIM * DIM];

// ---------------------------------------------------------------------------
// PTX helpers: mma.sync / ldmatrix / cp.async (valid at plain sm_103)
// ---------------------------------------------------------------------------
__device__ __forceinline__ uint32_t smem_u32(const void* p) {
    uint32_t a;
    asm("{ .reg .u64 t; cvta.to.shared.u64 t, %1; cvt.u32.u64 %0, t; }"
        : "=r"(a) : "l"(p));
    return a;
}

#define CP_ASYNC16(dst, src) \
    asm volatile("cp.async.cg.shared.global [%0], [%1], 16;" \
        :: "r"(dst), "l"(src))
#define CP_COMMIT() asm volatile("cp.async.commit_group;" ::: "memory")
#define CP_WAIT(n)  asm volatile("cp.async.wait_group %0;" :: "n"(n) : "memory")

#define LDSM4(r, addr) \
    asm volatile("ldmatrix.sync.aligned.m8n8.x4.shared.b16 {%0,%1,%2,%3}, [%4];" \
        : "=r"((r)[0]), "=r"((r)[1]), "=r"((r)[2]), "=r"((r)[3]) : "r"(addr))
#define LDSM2(r, addr) \
    asm volatile("ldmatrix.sync.aligned.m8n8.x2.shared.b16 {%0,%1}, [%2];" \
        : "=r"((r)[0]), "=r"((r)[1]) : "r"(addr))

#define MMA_BF16(d, a, b) \
    asm volatile("mma.sync.aligned.m16n8k16.row.col.f32.bf16.bf16.f32 " \
        "{%0,%1,%2,%3}, {%4,%5,%6,%7}, {%8,%9}, {%0,%1,%2,%3};" \
        : "+f"((d)[0]), "+f"((d)[1]), "+f"((d)[2]), "+f"((d)[3]) \
        : "r"((a)[0]), "r"((a)[1]), "r"((a)[2]), "r"((a)[3]), \
          "r"((b)[0]), "r"((b)[1]))

// fast 2^y for y <= 0 (FMA/ALU pipes, no MUFU)
__device__ __forceinline__ float fast_ex2(float y) {
    y = fmaxf(y, -120.f);
    const float z = y + 12582912.f;              // 1.5 * 2^23
    const float r = y - (z - 12582912.f);
    const uint32_t fb = (__float_as_uint(z) + 0xB4C0007Fu) << 23;  // 2^n
    float p = 0.0013333558f;
    p = fmaf(p, r, 0.0096181291f);
    p = fmaf(p, r, 0.0555041087f);
    p = fmaf(p, r, 0.2402265069f);
    p = fmaf(p, r, 0.6931471806f);
    p = fmaf(p, r, 1.0f);
    return __uint_as_float(fb) * p;
}

__device__ __forceinline__ uint32_t split_hi2(float x, float y) {
    __nv_bfloat162 h = __floats2bfloat162_rn(x, y);
    return *(uint32_t*)&h;
}
__device__ __forceinline__ uint32_t split_lo2(float x, float y, uint32_t hi2) {
    __nv_bfloat162 h = *(__nv_bfloat162*)&hi2;
    __nv_bfloat162 l = __floats2bfloat162_rn(x - __bfloat162float(h.x),
                                             y - __bfloat162float(h.y));
    return *(uint32_t*)&l;
}

// ---------------------------------------------------------------------------
// fp32 -> bf16 hi/lo split converter
// ---------------------------------------------------------------------------
__global__ __launch_bounds__(256) void cvt_hilo_kernel(
    const float* __restrict__ x, __nv_bfloat16* __restrict__ hi,
    __nv_bfloat16* __restrict__ lo, int n4)
{
    const int i = blockIdx.x * blockDim.x + threadIdx.x;
    if (i >= n4) return;
    const float4 v = ((const float4*)x)[i];
    uint32_t h0 = split_hi2(v.x, v.y), h1 = split_hi2(v.z, v.w);
    uint32_t l0 = split_lo2(v.x, v.y, h0), l1 = split_lo2(v.z, v.w, h1);
    ((uint32_t*)hi)[2 * i]     = h0;
    ((uint32_t*)hi)[2 * i + 1] = h1;
    ((uint32_t*)lo)[2 * i]     = l0;
    ((uint32_t*)lo)[2 * i + 1] = l1;
}

// ---------------------------------------------------------------------------
// mma.sync bf16x3 GEMM: D[m,n] = sum_k A[m,k]*B[n,k] + bias[n]
// CTA 128x128, BK=32, 8 warps, cp.async double buffer.
// MMAs emitted term-major across 4 accumulators (reuse distance 4).
// ---------------------------------------------------------------------------
#define BK 32
#define SROW 80
#define TILE_B (128 * SROW)
#define STAGE_B (4 * TILE_B)
#define GEMM_DYN_BYTES (2 * STAGE_B)
#define NCHUNK (DIM / BK)

__device__ __forceinline__ void stage_load(
    char* stage,
    const __nv_bfloat16* __restrict__ Ah, const __nv_bfloat16* __restrict__ Al,
    const __nv_bfloat16* __restrict__ Bh, const __nv_bfloat16* __restrict__ Bl,
    int k0, int tid)
{
    const int row  = tid >> 1;
    const int half = tid & 1;
    const uint32_t doff = (uint32_t)(row * SROW + half * 32);
    const size_t goff = (size_t)row * DIM + k0 + half * 16;

    const uint32_t d0 = smem_u32(stage) + doff;
    CP_ASYNC16(d0,                   Ah + goff);
    CP_ASYNC16(d0 + 16,              Ah + goff + 8);
    CP_ASYNC16(d0 + TILE_B,          Al + goff);
    CP_ASYNC16(d0 + TILE_B + 16,     Al + goff + 8);
    CP_ASYNC16(d0 + 2 * TILE_B,      Bh + goff);
    CP_ASYNC16(d0 + 2 * TILE_B + 16, Bh + goff + 8);
    CP_ASYNC16(d0 + 3 * TILE_B,      Bl + goff);
    CP_ASYNC16(d0 + 3 * TILE_B + 16, Bl + goff + 8);
}

__global__ __launch_bounds__(256, 2) void gemm_bf16x3_kernel(
    const __nv_bfloat16* __restrict__ Ahi, const __nv_bfloat16* __restrict__ Alo,
    const __nv_bfloat16* __restrict__ Bhi, const __nv_bfloat16* __restrict__ Blo,
    const float* __restrict__ bias, float* __restrict__ outp, int mode)
{
    extern __shared__ __align__(128) char smd[];
    const uint32_t smb = smem_u32(smd);

    const int tid  = threadIdx.x;
    const int wid  = tid >> 5;
    const int lane = tid & 31;
    const int m0 = blockIdx.y * 128;
    const int n0 = blockIdx.x * 128;

    const int wm = (wid >> 2) * 64;
    const int wn = (wid & 3) * 32;

    const __nv_bfloat16* Ah = Ahi + (size_t)m0 * DIM;
    const __nv_bfloat16* Al = Alo + (size_t)m0 * DIM;
    const __nv_bfloat16* Bh = Bhi + (size_t)n0 * DIM;
    const __nv_bfloat16* Bl = Blo + (size_t)n0 * DIM;

    float acc[4][4][4];
#pragma unroll
    for (int i = 0; i < 4; i++)
#pragma unroll
        for (int j = 0; j < 4; j++)
#pragma unroll
            for (int e = 0; e < 4; e++) acc[i][j][e] = 0.f;

    const uint32_t a_row  = (uint32_t)(wm + (lane & 15));
    const uint32_t a_coff = (uint32_t)((lane >> 4) * 16);
    const uint32_t b_row  = (uint32_t)(wn + (lane & 7));
    const uint32_t b_coff = (uint32_t)(((lane >> 3) & 1) * 16);

    stage_load(smd, Ah, Al, Bh, Bl, 0, tid);
    CP_COMMIT();

    for (int c = 0; c < NCHUNK; ++c) {
        if (c + 1 < NCHUNK) {
            stage_load(smd + ((c + 1) & 1) * STAGE_B, Ah, Al, Bh, Bl,
                       (c + 1) * BK, tid);
            CP_COMMIT();
            CP_WAIT(1);
        } else {
            CP_WAIT(0);
        }
        __syncthreads();

        const uint32_t sb = smb + (c & 1) * STAGE_B;
#pragma unroll
        for (int ks = 0; ks < 2; ++ks) {
            uint32_t bhf[4][2], blf[4][2];
#pragma unroll
            for (int j = 0; j < 4; ++j) {
                const uint32_t ba =
                    sb + 2 * TILE_B + (b_row + 8 * j) * SROW + ks * 32 + b_coff;
                LDSM2(bhf[j], ba);
                LDSM2(blf[j], ba + TILE_B);
            }
#pragma unroll
            for (int i = 0; i < 4; ++i) {
                uint32_t ahf[4], alf[4];
                const uint32_t aa =
                    sb + (a_row + 16 * i) * SROW + ks * 32 + a_coff;
                LDSM4(ahf, aa);
                LDSM4(alf, aa + TILE_B);
                // term-major: same-acc reuse distance = 4
#pragma unroll
                for (int j = 0; j < 4; ++j) MMA_BF16(acc[i][j], ahf, bhf[j]);
#pragma unroll
                for (int j = 0; j < 4; ++j) MMA_BF16(acc[i][j], ahf, blf[j]);
#pragma unroll
                for (int j = 0; j < 4; ++j) MMA_BF16(acc[i][j], alf, bhf[j]);
            }
        }
        __syncthreads();
    }

    // Epilogue. acc map: c0:(m,n) c1:(m,n+1) c2:(m+8,n) c3:(m+8,n+1)
    const int mloc0 = wm + (lane >> 2);
    const int nloc0 = wn + (lane & 3) * 2;

    if (mode == 0) {
        const int which = n0 >> 10;          // 0=Q 1=K 2=V (CTA-uniform)
        const int bI    = m0 >> 11;
        const int tokb  = m0 & 2047;
#pragma unroll
        for (int i = 0; i < 4; ++i) {
#pragma unroll
            for (int j = 0; j < 4; ++j) {
                const int n_g = n0 + nloc0 + 8 * j;
                const int tok = tokb + mloc0 + 16 * i;
                const int h = (n_g & 1023) >> 6;
                const int d = n_g & 63;
                const int bh = bI * NHEAD + h;
                float v0 = acc[i][j][0] + bias[n_g];
                float v1 = acc[i][j][1] + bias[n_g + 1];
                float v2 = acc[i][j][2] + bias[n_g];
                float v3 = acc[i][j][3] + bias[n_g + 1];
                if (which == 0) {
                    v0 *= QSCALE; v1 *= QSCALE; v2 *= QSCALE; v3 *= QSCALE;
                    const size_t a0 = ((size_t)bh * SEQ + tok) * HDIM + d;
                    uint32_t h2 = split_hi2(v0, v1);
                    *(uint32_t*)(g_qhi + a0) = h2;
                    *(uint32_t*)(g_qlo + a0) = split_lo2(v0, v1, h2);
                    h2 = split_hi2(v2, v3);
                    *(uint32_t*)(g_qhi + a0 + 8 * HDIM) = h2;
                    *(uint32_t*)(g_qlo + a0 + 8 * HDIM) = split_lo2(v2, v3, h2);
                } else if (which == 1) {
                    const size_t a0 = ((size_t)bh * SEQ + tok) * HDIM + d;
                    uint32_t h2 = split_hi2(v0, v1);
                    *(uint32_t*)(g_khi + a0) = h2;
                    *(uint32_t*)(g_klo + a0) = split_lo2(v0, v1, h2);
                    h2 = split_hi2(v2, v3);
                    *(uint32_t*)(g_khi + a0 + 8 * HDIM) = h2;
                    *(uint32_t*)(g_klo + a0 + 8 * HDIM) = split_lo2(v2, v3, h2);
                } else {
                    // V d-major: [bh][d][tok]
                    const size_t b0 = ((size_t)bh * HDIM + d) * SEQ + tok;
                    __nv_bfloat16 t;
                    t = __float2bfloat16(v0); g_vhi[b0] = t;
                    g_vlo[b0] = __float2bfloat16(v0 - __bfloat162float(t));
                    t = __float2bfloat16(v1); g_vhi[b0 + SEQ] = t;
                    g_vlo[b0 + SEQ] = __float2bfloat16(v1 - __bfloat162float(t));
                    t = __float2bfloat16(v2); g_vhi[b0 + 8] = t;
                    g_vlo[b0 + 8] = __float2bfloat16(v2 - __bfloat162float(t));
                    t = __float2bfloat16(v3); g_vhi[b0 + SEQ + 8] = t;
                    g_vlo[b0 + SEQ + 8] =
                        __float2bfloat16(v3 - __bfloat162float(t));
                }
            }
        }
    } else {
#pragma unroll
        for (int i = 0; i < 4; ++i) {
#pragma unroll
            for (int j = 0; j < 4; ++j) {
                const int n_g = n0 + nloc0 + 8 * j;
                const int m_g = m0 + mloc0 + 16 * i;
                const float bv0 = bias[n_g], bv1 = bias[n_g + 1];
                float* r0 = outp + (size_t)m_g * DIM + n_g;
                *(float2*)r0 =
                    make_float2(acc[i][j][0] + bv0, acc[i][j][1] + bv1);
                *(float2*)(r0 + 8 * DIM) =
                    make_float2(acc[i][j][2] + bv0, acc[i][j][3] + bv1);
            }
        }
    }
}

// ---------------------------------------------------------------------------
// Flash attention on mma.sync bf16x3.
// CTA: 128 q-rows x one bh; 8 warps, warp = 16 q-rows.
// MMAs striped across accumulator quads (reuse distance 4).
// ---------------------------------------------------------------------------
#define AT_SROW 144                       // 64 bf16 + 16B pad
#define AT_QT_B (128 * AT_SROW)           // 18432
#define AT_KT_B (64 * AT_SROW)            // 9216
#define AT_ST_B (4 * AT_KT_B)             // 36864
#define AT_SMEM (2 * AT_QT_B + 2 * AT_ST_B)   // 110592

__device__ __forceinline__ void load_kv_tile(uint32_t st, int bh, int kt, int tid)
{
    const __nv_bfloat16* kh = g_khi + ((size_t)bh * SEQ + kt * 64) * HDIM;
    const __nv_bfloat16* kl = g_klo + ((size_t)bh * SEQ + kt * 64) * HDIM;
    const __nv_bfloat16* vh = g_vhi + (size_t)bh * HDIM * SEQ + kt * 64;
    const __nv_bfloat16* vl = g_vlo + (size_t)bh * HDIM * SEQ + kt * 64;
#pragma unroll
    for (int i = 0; i < 2; i++) {
        const int idx = tid + i * 256;    // 0..511
        const int row = idx >> 3, ch = idx & 7;
        const uint32_t so = (uint32_t)(row * AT_SROW + ch * 16);
        CP_ASYNC16(st + so,               kh + (size_t)row * HDIM + ch * 8);
        CP_ASYNC16(st + AT_KT_B + so,     kl + (size_t)row * HDIM + ch * 8);
        CP_ASYNC16(st + 2 * AT_KT_B + so, vh + (size_t)row * SEQ + ch * 8);
        CP_ASYNC16(st + 3 * AT_KT_B + so, vl + (size_t)row * SEQ + ch * 8);
    }
}

__global__ __launch_bounds__(256, 2) void attn_mma_kernel()
{
    extern __shared__ __align__(128) char sm[];
    const uint32_t smb  = smem_u32(sm);
    const uint32_t q_hi = smb;
    const uint32_t q_lo = smb + AT_QT_B;
    const uint32_t st0  = smb + 2 * AT_QT_B;

    const int tid = threadIdx.x;
    const int wid = tid >> 5, lane = tid & 31;
    const int qt = blockIdx.x, bh = blockIdx.y;

    // Load Q tile (hi/lo), 128 rows x 64 bf16
    {
        const __nv_bfloat16* qh = g_qhi + ((size_t)bh * SEQ + qt * 128) * HDIM;
        const __nv_bfloat16* ql = g_qlo + ((size_t)bh * SEQ + qt * 128) * HDIM;
#pragma unroll
        for (int i = 0; i < 4; i++) {
            const int idx = tid + i * 256;     // 0..1023
            const int row = idx >> 3, ch = idx & 7;
            const uint32_t so = (uint32_t)(row * AT_SROW + ch * 16);
            CP_ASYNC16(q_hi + so, qh + (size_t)row * HDIM + ch * 8);
            CP_ASYNC16(q_lo + so, ql + (size_t)row * HDIM + ch * 8);
        }
        CP_COMMIT();
    }
    load_kv_tile(st0, bh, 0, tid);
    CP_COMMIT();
    CP_WAIT(1);                // Q complete (KV tile 0 may be pending)
    __syncthreads();

    // Q A-fragments, register-resident: 4 ksteps x hi/lo
    uint32_t qhf[4][4], qlf[4][4];
    {
        const uint32_t qa =
            (uint32_t)((wid * 16 + (lane & 15)) * AT_SROW + (lane >> 4) * 16);
#pragma unroll
        for (int t = 0; t < 4; t++) {
            LDSM4(qhf[t], q_hi + qa + t * 32);
            LDSM4(qlf[t], q_lo + qa + t * 32);
        }
    }

    float m2[2] = {-1e30f, -1e30f}, l[2] = {0.f, 0.f};
    float po[8][4];
#pragma unroll
    for (int j = 0; j < 8; j++)
#pragma unroll
        for (int e = 0; e < 4; e++) po[j][e] = 0.f;

    const uint32_t brow =
        (uint32_t)((lane & 7) * AT_SROW + ((lane >> 3) & 1) * 16);

    for (int kt = 0; kt < SEQ / 64; kt++) {
        if (kt + 1 < SEQ / 64) {
            load_kv_tile(st0 + ((kt + 1) & 1) * AT_ST_B, bh, kt + 1, tid);
            CP_COMMIT();
            CP_WAIT(1);
        } else {
            CP_WAIT(0);
        }
        __syncthreads();

        const uint32_t sk = st0 + (kt & 1) * AT_ST_B;
        const uint32_t sv = sk + 2 * AT_KT_B;

        // S = Q K^T (base-2 scores), kstep-outer, quad-striped accumulators
        float s[8][4];
#pragma unroll
        for (int j = 0; j < 8; j++)
#pragma unroll
            for (int e = 0; e < 4; e++) s[j][e] = 0.f;

#pragma unroll
        for (int t = 0; t < 4; t++) {
#pragma unroll
            for (int jq = 0; jq < 2; jq++) {
                uint32_t kbh[4][2], kbl[4][2];
#pragma unroll
                for (int jj = 0; jj < 4; jj++) {
                    const int j = jq * 4 + jj;
                    const uint32_t kb =
                        sk + (uint32_t)(j * 8 * AT_SROW) + brow + t * 32;
                    LDSM2(kbh[jj], kb);
                    LDSM2(kbl[jj], kb + AT_KT_B);
                }
#pragma unroll
                for (int jj = 0; jj < 4; jj++)
                    MMA_BF16(s[jq * 4 + jj], qhf[t], kbh[jj]);
#pragma unroll
                for (int jj = 0; jj < 4; jj++)
                    MMA_BF16(s[jq * 4 + jj], qhf[t], kbl[jj]);
#pragma unroll
                for (int jj = 0; jj < 4; jj++)
                    MMA_BF16(s[jq * 4 + jj], qlf[t], kbh[jj]);
            }
        }

        // Online softmax (rows r=lane>>2 and r+8; quad holds a row)
        float rmx0 = s[0][0], rmx1 = s[0][2];
#pragma unroll
        for (int j = 0; j < 8; j++) {
            rmx0 = fmaxf(rmx0, fmaxf(s[j][0], s[j][1]));
            rmx1 = fmaxf(rmx1, fmaxf(s[j][2], s[j][3]));
        }
        rmx0 = fmaxf(rmx0, __shfl_xor_sync(0xffffffffu, rmx0, 1));
        rmx0 = fmaxf(rmx0, __shfl_xor_sync(0xffffffffu, rmx0, 2));
        rmx1 = fmaxf(rmx1, __shfl_xor_sync(0xffffffffu, rmx1, 1));
        rmx1 = fmaxf(rmx1, __shfl_xor_sync(0xffffffffu, rmx1, 2));

        const float mn0 = fmaxf(m2[0], rmx0);
        const float mn1 = fmaxf(m2[1], rmx1);
        const float c0 = fast_ex2(m2[0] - mn0);
        const float c1 = fast_ex2(m2[1] - mn1);
        m2[0] = mn0; m2[1] = mn1;

        float rs0 = 0.f, rs1 = 0.f;
#pragma unroll
        for (int j = 0; j < 8; j++) {
            s[j][0] = fast_ex2(s[j][0] - mn0);
            s[j][1] = fast_ex2(s[j][1] - mn0);
            s[j][2] = fast_ex2(s[j][2] - mn1);
            s[j][3] = fast_ex2(s[j][3] - mn1);
            rs0 += s[j][0] + s[j][1];
            rs1 += s[j][2] + s[j][3];
        }
        rs0 += __shfl_xor_sync(0xffffffffu, rs0, 1);
        rs0 += __shfl_xor_sync(0xffffffffu, rs0, 2);
        rs1 += __shfl_xor_sync(0xffffffffu, rs1, 1);
        rs1 += __shfl_xor_sync(0xffffffffu, rs1, 2);
        l[0] = l[0] * c0 + rs0;
        l[1] = l[1] * c1 + rs1;
#pragma unroll
        for (int j = 0; j < 8; j++) {
            po[j][0] *= c0; po[j][1] *= c0;
            po[j][2] *= c1; po[j][3] *= c1;
        }

        // O += P V : P accumulator fragment doubles as A fragment.
        // kstep-outer, quad-striped po accumulators.
#pragma unroll
        for (int t = 0; t < 4; t++) {
            uint32_t ph[4], pl[4];
            ph[0] = split_hi2(s[2 * t][0],     s[2 * t][1]);
            ph[1] = split_hi2(s[2 * t][2],     s[2 * t][3]);
            ph[2] = split_hi2(s[2 * t + 1][0], s[2 * t + 1][1]);
            ph[3] = split_hi2(s[2 * t + 1][2], s[2 * t + 1][3]);
            pl[0] = split_lo2(s[2 * t][0],     s[2 * t][1],     ph[0]);
            pl[1] = split_lo2(s[2 * t][2],     s[2 * t][3],     ph[1]);
            pl[2] = split_lo2(s[2 * t + 1][0], s[2 * t + 1][1], ph[2]);
            pl[3] = split_lo2(s[2 * t + 1][2], s[2 * t + 1][3], ph[3]);
#pragma unroll
            for (int jq = 0; jq < 2; jq++) {
                uint32_t vbh[4][2], vbl[4][2];
#pragma unroll
                for (int jj = 0; jj < 4; jj++) {
                    const int j = jq * 4 + jj;
                    const uint32_t vb =
                        sv + (uint32_t)(j * 8 * AT_SROW) + brow + t * 32;
                    LDSM2(vbh[jj], vb);
                    LDSM2(vbl[jj], vb + AT_KT_B);
                }
#pragma unroll
                for (int jj = 0; jj < 4; jj++)
                    MMA_BF16(po[jq * 4 + jj], ph, vbh[jj]);
#pragma unroll
                for (int jj = 0; jj < 4; jj++)
                    MMA_BF16(po[jq * 4 + jj], ph, vbl[jj]);
#pragma unroll
                for (int jj = 0; jj < 4; jj++)
                    MMA_BF16(po[jq * 4 + jj], pl, vbh[jj]);
            }
        }
        __syncthreads();
    }

    // Epilogue: O/l -> bf16 hi/lo [tok][h*64+d]
    const int h = bh & 15, bb = bh >> 4;
    const int tok0 = qt * 128 + wid * 16 + (lane >> 2);
    const float inv0 = 1.f / l[0], inv1 = 1.f / l[1];
#pragma unroll
    for (int j = 0; j < 8; j++) {
        const int d = h * HDIM + j * 8 + (lane & 3) * 2;
        const size_t a0 = ((size_t)(bb * SEQ + tok0)) * DIM + d;
        const size_t a1 = a0 + (size_t)8 * DIM;
        const float v0 = po[j][0] * inv0, v1 = po[j][1] * inv0;
        const float v2 = po[j][2] * inv1, v3 = po[j][3] * inv1;
        uint32_t h2 = split_hi2(v0, v1);
        *(uint32_t*)(g_ohi + a0) = h2;
        *(uint32_t*)(g_olo + a0) = split_lo2(v0, v1, h2);
        h2 = split_hi2(v2, v3);
        *(uint32_t*)(g_ohi + a1) = h2;
        *(uint32_t*)(g_olo + a1) = split_lo2(v2, v3, h2);
    }
}

// ---------------------------------------------------------------------------

extern "C" void kernel_launch(void* const* d_in, const int* in_sizes, int n_in,
                              void* d_out, int out_size)
{
    const float* x      = (const float*)d_in[0];
    const float* w_qkv  = (const float*)d_in[1];
    const float* b_qkv  = (const float*)d_in[2];
    const float* w_proj = (const float*)d_in[3];
    const float* b_proj = (const float*)d_in[4];
    float* out = (float*)d_out;

    __nv_bfloat16 *h_xhi, *h_xlo, *h_wqhi, *h_wqlo, *h_wphi, *h_wplo,
                  *h_ohi, *h_olo;
    cudaGetSymbolAddress((void**)&h_xhi,  g_xhi);
    cudaGetSymbolAddress((void**)&h_xlo,  g_xlo);
    cudaGetSymbolAddress((void**)&h_wqhi, g_wqhi);
    cudaGetSymbolAddress((void**)&h_wqlo, g_wqlo);
    cudaGetSymbolAddress((void**)&h_wphi, g_wphi);
    cudaGetSymbolAddress((void**)&h_wplo, g_wplo);
    cudaGetSymbolAddress((void**)&h_ohi,  g_ohi);
    cudaGetSymbolAddress((void**)&h_olo,  g_olo);

    cudaFuncSetAttribute(gemm_bf16x3_kernel,
                         cudaFuncAttributeMaxDynamicSharedMemorySize,
                         GEMM_DYN_BYTES);
    cudaFuncSetAttribute(attn_mma_kernel,
                         cudaFuncAttributeMaxDynamicSharedMemorySize,
                         AT_SMEM);

    // 1. Split inputs/weights into bf16 hi/lo
    cvt_hilo_kernel<<<(M_TOK * DIM / 4 + 255) / 256, 256>>>(
        x, h_xhi, h_xlo, M_TOK * DIM / 4);
    cvt_hilo_kernel<<<(3 * DIM * DIM / 4 + 255) / 256, 256>>>(
        w_qkv, h_wqhi, h_wqlo, 3 * DIM * DIM / 4);
    cvt_hilo_kernel<<<(DIM * DIM / 4 + 255) / 256, 256>>>(
        w_proj, h_wphi, h_wplo, DIM * DIM / 4);

    // 2. QKV GEMM -> bf16 hi/lo Q/K/V in attention layouts
    dim3 gq(3 * DIM / 128, M_TOK / 128);
    gemm_bf16x3_kernel<<<gq, 256, GEMM_DYN_BYTES>>>(
        h_xhi, h_xlo, h_wqhi, h_wqlo, b_qkv, nullptr, 0);

    // 3. Tensor-core flash attention -> g_ohi/g_olo
    dim3 ga(SEQ / 128, NBH);
    attn_mma_kernel<<<ga, 256, AT_SMEM>>>();

    // 4. Projection GEMM: M=4096, N=1024
    dim3 gp(DIM / 128, M_TOK / 128);
    gemm_bf16x3_kernel<<<gp, 256, GEMM_DYN_BYTES>>>(
        h_ohi, h_olo, h_wphi, h_wplo, b_proj, out, 1);
}

// round 9
// speedup vs baseline: 7.0623x; 1.3689x over previous
#include <cuda_runtime.h>
#include <cuda_fp16.h>
#include <cstdint>

// Problem constants
#define BATCH 2
#define SEQ   2048
#define DIM   1024
#define NHEAD 16
#define HDIM  64
// SCALE * log2(e): fold into Q so QK^T scores are already in base-2 domain
#define QSCALE (0.125f * 1.4426950408889634f)

#define M_TOK (BATCH * SEQ)          // 4096 rows of tokens
#define NBH   (BATCH * NHEAD)        // 32

// ---------------------------------------------------------------------------
// Scratch (device globals: allocation-free rule)   — fp16 everywhere
// ---------------------------------------------------------------------------
// Q: [bh][tok][64] hi/lo (split side of S; pre-scaled by QSCALE)
// K: [bh][tok][64] single fp16 (unsplit side of S)
// V: [bh][d][tok]  hi/lo (split side of PV; d-major for B-fragments)
__device__ __half g_qhi[NBH * SEQ * HDIM];
__device__ __half g_qlo[NBH * SEQ * HDIM];
__device__ __half g_kh [NBH * SEQ * HDIM];
__device__ __half g_vhi[NBH * HDIM * SEQ];
__device__ __half g_vlo[NBH * HDIM * SEQ];
// attention output, hi/lo, [b*n][h*64+d]  (proj GEMM split A input)
__device__ __half g_ohi[M_TOK * DIM];
__device__ __half g_olo[M_TOK * DIM];
// GEMM operand splits: activations split, weights single
__device__ __half g_xhi[M_TOK * DIM];
__device__ __half g_xlo[M_TOK * DIM];
__device__ __half g_wqh[3 * DIM * DIM];
__device__ __half g_wph[DIM * DIM];

// ---------------------------------------------------------------------------
// PTX helpers: mma.sync / ldmatrix / cp.async (valid at plain sm_103)
// ---------------------------------------------------------------------------
__device__ __forceinline__ uint32_t smem_u32(const void* p) {
    uint32_t a;
    asm("{ .reg .u64 t; cvta.to.shared.u64 t, %1; cvt.u32.u64 %0, t; }"
        : "=r"(a) : "l"(p));
    return a;
}

#define CP_ASYNC16(dst, src) \
    asm volatile("cp.async.cg.shared.global [%0], [%1], 16;" \
        :: "r"(dst), "l"(src))
#define CP_COMMIT() asm volatile("cp.async.commit_group;" ::: "memory")
#define CP_WAIT(n)  asm volatile("cp.async.wait_group %0;" :: "n"(n) : "memory")

#define LDSM4(r, addr) \
    asm volatile("ldmatrix.sync.aligned.m8n8.x4.shared.b16 {%0,%1,%2,%3}, [%4];" \
        : "=r"((r)[0]), "=r"((r)[1]), "=r"((r)[2]), "=r"((r)[3]) : "r"(addr))
#define LDSM2(r, addr) \
    asm volatile("ldmatrix.sync.aligned.m8n8.x2.shared.b16 {%0,%1}, [%2];" \
        : "=r"((r)[0]), "=r"((r)[1]) : "r"(addr))

#define MMA_F16(d, a, b) \
    asm volatile("mma.sync.aligned.m16n8k16.row.col.f32.f16.f16.f32 " \
        "{%0,%1,%2,%3}, {%4,%5,%6,%7}, {%8,%9}, {%0,%1,%2,%3};" \
        : "+f"((d)[0]), "+f"((d)[1]), "+f"((d)[2]), "+f"((d)[3]) \
        : "r"((a)[0]), "r"((a)[1]), "r"((a)[2]), "r"((a)[3]), \
          "r"((b)[0]), "r"((b)[1]))

// fast 2^y for y <= 0 (FMA/ALU pipes, no MUFU)
__device__ __forceinline__ float fast_ex2(float y) {
    y = fmaxf(y, -120.f);
    const float z = y + 12582912.f;              // 1.5 * 2^23
    const float r = y - (z - 12582912.f);
    const uint32_t fb = (__float_as_uint(z) + 0xB4C0007Fu) << 23;  // 2^n
    float p = 0.0013333558f;
    p = fmaf(p, r, 0.0096181291f);
    p = fmaf(p, r, 0.0555041087f);
    p = fmaf(p, r, 0.2402265069f);
    p = fmaf(p, r, 0.6931471806f);
    p = fmaf(p, r, 1.0f);
    return __uint_as_float(fb) * p;
}

__device__ __forceinline__ uint32_t pack_h2(float x, float y) {
    __half2 h = __floats2half2_rn(x, y);
    return *(uint32_t*)&h;
}
__device__ __forceinline__ uint32_t pack_l2(float x, float y, uint32_t h2) {
    __half2 h = *(__half2*)&h2;
    __half2 l = __floats2half2_rn(x - __half2float(h.x),
                                  y - __half2float(h.y));
    return *(uint32_t*)&l;
}

// ---------------------------------------------------------------------------
// fp32 -> fp16 converters (hi/lo split, and single)
// ---------------------------------------------------------------------------
__global__ __launch_bounds__(256) void cvt_hilo_kernel(
    const float* __restrict__ x, __half* __restrict__ hi,
    __half* __restrict__ lo, int n4)
{
    const int i = blockIdx.x * blockDim.x + threadIdx.x;
    if (i >= n4) return;
    const float4 v = ((const float4*)x)[i];
    uint32_t h0 = pack_h2(v.x, v.y), h1 = pack_h2(v.z, v.w);
    ((uint32_t*)hi)[2 * i]     = h0;
    ((uint32_t*)hi)[2 * i + 1] = h1;
    ((uint32_t*)lo)[2 * i]     = pack_l2(v.x, v.y, h0);
    ((uint32_t*)lo)[2 * i + 1] = pack_l2(v.z, v.w, h1);
}

__global__ __launch_bounds__(256) void cvt_h_kernel(
    const float* __restrict__ x, __half* __restrict__ hi, int n4)
{
    const int i = blockIdx.x * blockDim.x + threadIdx.x;
    if (i >= n4) return;
    const float4 v = ((const float4*)x)[i];
    ((uint32_t*)hi)[2 * i]     = pack_h2(v.x, v.y);
    ((uint32_t*)hi)[2 * i + 1] = pack_h2(v.z, v.w);
}

// ---------------------------------------------------------------------------
// mma.sync fp16x2 GEMM: D[m,n] = sum_k (Ah+Al)[m,k]*Bh[n,k] + bias[n]
// CTA 128x128, BK=32, 8 warps, cp.async double buffer. 2 MMAs per product.
// mode 0: QKV epilogue (emit fp16 Q hi/lo, K, V hi/lo in attention layouts)
// mode 1: plain fp32 row-major out.
// ---------------------------------------------------------------------------
#define BK 32
#define SROW 80
#define TILE_B (128 * SROW)
#define STAGE_B (3 * TILE_B)        // Ah, Al, Bh
#define GEMM_DYN_BYTES (2 * STAGE_B)
#define NCHUNK (DIM / BK)

__device__ __forceinline__ void stage_load(
    char* stage,
    const __half* __restrict__ Ah, const __half* __restrict__ Al,
    const __half* __restrict__ Bh, int k0, int tid)
{
    const int row  = tid >> 1;
    const int half = tid & 1;
    const uint32_t doff = (uint32_t)(row * SROW + half * 32);
    const size_t goff = (size_t)row * DIM + k0 + half * 16;

    const uint32_t d0 = smem_u32(stage) + doff;
    CP_ASYNC16(d0,                   Ah + goff);
    CP_ASYNC16(d0 + 16,              Ah + goff + 8);
    CP_ASYNC16(d0 + TILE_B,          Al + goff);
    CP_ASYNC16(d0 + TILE_B + 16,     Al + goff + 8);
    CP_ASYNC16(d0 + 2 * TILE_B,      Bh + goff);
    CP_ASYNC16(d0 + 2 * TILE_B + 16, Bh + goff + 8);
}

__global__ __launch_bounds__(256, 2) void gemm_fp16x2_kernel(
    const __half* __restrict__ Ahi, const __half* __restrict__ Alo,
    const __half* __restrict__ Bhs,
    const float* __restrict__ bias, float* __restrict__ outp, int mode)
{
    extern __shared__ __align__(128) char smd[];
    const uint32_t smb = smem_u32(smd);

    const int tid  = threadIdx.x;
    const int wid  = tid >> 5;
    const int lane = tid & 31;
    const int m0 = blockIdx.y * 128;
    const int n0 = blockIdx.x * 128;

    const int wm = (wid >> 2) * 64;
    const int wn = (wid & 3) * 32;

    const __half* Ah = Ahi + (size_t)m0 * DIM;
    const __half* Al = Alo + (size_t)m0 * DIM;
    const __half* Bh = Bhs + (size_t)n0 * DIM;

    float acc[4][4][4];
#pragma unroll
    for (int i = 0; i < 4; i++)
#pragma unroll
        for (int j = 0; j < 4; j++)
#pragma unroll
            for (int e = 0; e < 4; e++) acc[i][j][e] = 0.f;

    const uint32_t a_row  = (uint32_t)(wm + (lane & 15));
    const uint32_t a_coff = (uint32_t)((lane >> 4) * 16);
    const uint32_t b_row  = (uint32_t)(wn + (lane & 7));
    const uint32_t b_coff = (uint32_t)(((lane >> 3) & 1) * 16);

    stage_load(smd, Ah, Al, Bh, 0, tid);
    CP_COMMIT();

    for (int c = 0; c < NCHUNK; ++c) {
        if (c + 1 < NCHUNK) {
            stage_load(smd + ((c + 1) & 1) * STAGE_B, Ah, Al, Bh,
                       (c + 1) * BK, tid);
            CP_COMMIT();
            CP_WAIT(1);
        } else {
            CP_WAIT(0);
        }
        __syncthreads();

        const uint32_t sb = smb + (c & 1) * STAGE_B;
#pragma unroll
        for (int ks = 0; ks < 2; ++ks) {
            uint32_t bhf[4][2];
#pragma unroll
            for (int j = 0; j < 4; ++j) {
                const uint32_t ba =
                    sb + 2 * TILE_B + (b_row + 8 * j) * SROW + ks * 32 + b_coff;
                LDSM2(bhf[j], ba);
            }
#pragma unroll
            for (int i = 0; i < 4; ++i) {
                uint32_t ahf[4], alf[4];
                const uint32_t aa =
                    sb + (a_row + 16 * i) * SROW + ks * 32 + a_coff;
                LDSM4(ahf, aa);
                LDSM4(alf, aa + TILE_B);
                // term-major: same-acc reuse distance = 4
#pragma unroll
                for (int j = 0; j < 4; ++j) MMA_F16(acc[i][j], ahf, bhf[j]);
#pragma unroll
                for (int j = 0; j < 4; ++j) MMA_F16(acc[i][j], alf, bhf[j]);
            }
        }
        __syncthreads();
    }

    // Epilogue. acc map: c0:(m,n) c1:(m,n+1) c2:(m+8,n) c3:(m+8,n+1)
    const int mloc0 = wm + (lane >> 2);
    const int nloc0 = wn + (lane & 3) * 2;

    if (mode == 0) {
        const int which = n0 >> 10;          // 0=Q 1=K 2=V (CTA-uniform)
        const int bI    = m0 >> 11;
        const int tokb  = m0 & 2047;
#pragma unroll
        for (int i = 0; i < 4; ++i) {
#pragma unroll
            for (int j = 0; j < 4; ++j) {
                const int n_g = n0 + nloc0 + 8 * j;
                const int tok = tokb + mloc0 + 16 * i;
                const int h = (n_g & 1023) >> 6;
                const int d = n_g & 63;
                const int bh = bI * NHEAD + h;
                float v0 = acc[i][j][0] + bias[n_g];
                float v1 = acc[i][j][1] + bias[n_g + 1];
                float v2 = acc[i][j][2] + bias[n_g];
                float v3 = acc[i][j][3] + bias[n_g + 1];
                if (which == 0) {
                    v0 *= QSCALE; v1 *= QSCALE; v2 *= QSCALE; v3 *= QSCALE;
                    const size_t a0 = ((size_t)bh * SEQ + tok) * HDIM + d;
                    uint32_t h2 = pack_h2(v0, v1);
                    *(uint32_t*)(g_qhi + a0) = h2;
                    *(uint32_t*)(g_qlo + a0) = pack_l2(v0, v1, h2);
                    h2 = pack_h2(v2, v3);
                    *(uint32_t*)(g_qhi + a0 + 8 * HDIM) = h2;
                    *(uint32_t*)(g_qlo + a0 + 8 * HDIM) = pack_l2(v2, v3, h2);
                } else if (which == 1) {
                    const size_t a0 = ((size_t)bh * SEQ + tok) * HDIM + d;
                    *(uint32_t*)(g_kh + a0)            = pack_h2(v0, v1);
                    *(uint32_t*)(g_kh + a0 + 8 * HDIM) = pack_h2(v2, v3);
                } else {
                    // V d-major hi/lo: [bh][d][tok]
                    const size_t b0 = ((size_t)bh * HDIM + d) * SEQ + tok;
                    __half t;
                    t = __float2half_rn(v0); g_vhi[b0] = t;
                    g_vlo[b0] = __float2half_rn(v0 - __half2float(t));
                    t = __float2half_rn(v1); g_vhi[b0 + SEQ] = t;
                    g_vlo[b0 + SEQ] = __float2half_rn(v1 - __half2float(t));
                    t = __float2half_rn(v2); g_vhi[b0 + 8] = t;
                    g_vlo[b0 + 8] = __float2half_rn(v2 - __half2float(t));
                    t = __float2half_rn(v3); g_vhi[b0 + SEQ + 8] = t;
                    g_vlo[b0 + SEQ + 8] =
                        __float2half_rn(v3 - __half2float(t));
                }
            }
        }
    } else {
#pragma unroll
        for (int i = 0; i < 4; ++i) {
#pragma unroll
            for (int j = 0; j < 4; ++j) {
                const int n_g = n0 + nloc0 + 8 * j;
                const int m_g = m0 + mloc0 + 16 * i;
                const float bv0 = bias[n_g], bv1 = bias[n_g + 1];
                float* r0 = outp + (size_t)m_g * DIM + n_g;
                *(float2*)r0 =
                    make_float2(acc[i][j][0] + bv0, acc[i][j][1] + bv1);
                *(float2*)(r0 + 8 * DIM) =
                    make_float2(acc[i][j][2] + bv0, acc[i][j][3] + bv1);
            }
        }
    }
}

// ---------------------------------------------------------------------------
// Flash attention, mma.sync fp16x2.
// CTA: 128 q-rows x one bh; 8 warps. S = (Qh+Ql)*Kh, O += Ph*(Vh+Vl).
// ---------------------------------------------------------------------------
#define AT_SROW 144                       // 64 fp16 + 16B pad
#define AT_QT_B (128 * AT_SROW)           // 18432
#define AT_KT_B (64 * AT_SROW)            // 9216
#define AT_ST_B (3 * AT_KT_B)             // 27648: Kh, Vh, Vl
#define AT_SMEM (2 * AT_QT_B + 2 * AT_ST_B)   // 92160

__device__ __forceinline__ void load_kv_tile(uint32_t st, int bh, int kt, int tid)
{
    const __half* kh = g_kh  + ((size_t)bh * SEQ + kt * 64) * HDIM;
    const __half* vh = g_vhi + (size_t)bh * HDIM * SEQ + kt * 64;
    const __half* vl = g_vlo + (size_t)bh * HDIM * SEQ + kt * 64;
#pragma unroll
    for (int i = 0; i < 2; i++) {
        const int idx = tid + i * 256;    // 0..511
        const int row = idx >> 3, ch = idx & 7;
        const uint32_t so = (uint32_t)(row * AT_SROW + ch * 16);
        CP_ASYNC16(st + so,               kh + (size_t)row * HDIM + ch * 8);
        CP_ASYNC16(st + AT_KT_B + so,     vh + (size_t)row * SEQ + ch * 8);
        CP_ASYNC16(st + 2 * AT_KT_B + so, vl + (size_t)row * SEQ + ch * 8);
    }
}

__global__ __launch_bounds__(256, 2) void attn_mma_kernel()
{
    extern __shared__ __align__(128) char sm[];
    const uint32_t smb  = smem_u32(sm);
    const uint32_t q_hi = smb;
    const uint32_t q_lo = smb + AT_QT_B;
    const uint32_t st0  = smb + 2 * AT_QT_B;

    const int tid = threadIdx.x;
    const int wid = tid >> 5, lane = tid & 31;
    const int qt = blockIdx.x, bh = blockIdx.y;

    // Load Q tile (hi/lo), 128 rows x 64 fp16
    {
        const __half* qh = g_qhi + ((size_t)bh * SEQ + qt * 128) * HDIM;
        const __half* ql = g_qlo + ((size_t)bh * SEQ + qt * 128) * HDIM;
#pragma unroll
        for (int i = 0; i < 4; i++) {
            const int idx = tid + i * 256;     // 0..1023
            const int row = idx >> 3, ch = idx & 7;
            const uint32_t so = (uint32_t)(row * AT_SROW + ch * 16);
            CP_ASYNC16(q_hi + so, qh + (size_t)row * HDIM + ch * 8);
            CP_ASYNC16(q_lo + so, ql + (size_t)row * HDIM + ch * 8);
        }
        CP_COMMIT();
    }
    load_kv_tile(st0, bh, 0, tid);
    CP_COMMIT();
    CP_WAIT(1);                // Q complete (KV tile 0 may be pending)
    __syncthreads();

    // Q A-fragments, register-resident: 4 ksteps x hi/lo
    uint32_t qhf[4][4], qlf[4][4];
    {
        const uint32_t qa =
            (uint32_t)((wid * 16 + (lane & 15)) * AT_SROW + (lane >> 4) * 16);
#pragma unroll
        for (int t = 0; t < 4; t++) {
            LDSM4(qhf[t], q_hi + qa + t * 32);
            LDSM4(qlf[t], q_lo + qa + t * 32);
        }
    }

    float m2[2] = {-1e30f, -1e30f}, l[2] = {0.f, 0.f};
    float po[8][4];
#pragma unroll
    for (int j = 0; j < 8; j++)
#pragma unroll
        for (int e = 0; e < 4; e++) po[j][e] = 0.f;

    const uint32_t brow =
        (uint32_t)((lane & 7) * AT_SROW + ((lane >> 3) & 1) * 16);

    for (int kt = 0; kt < SEQ / 64; kt++) {
        if (kt + 1 < SEQ / 64) {
            load_kv_tile(st0 + ((kt + 1) & 1) * AT_ST_B, bh, kt + 1, tid);
            CP_COMMIT();
            CP_WAIT(1);
        } else {
            CP_WAIT(0);
        }
        __syncthreads();

        const uint32_t sk = st0 + (kt & 1) * AT_ST_B;
        const uint32_t sv = sk + AT_KT_B;

        // S = (Qh+Ql) Kh, kstep-outer, quad-striped accumulators
        float s[8][4];
#pragma unroll
        for (int j = 0; j < 8; j++)
#pragma unroll
            for (int e = 0; e < 4; e++) s[j][e] = 0.f;

#pragma unroll
        for (int t = 0; t < 4; t++) {
#pragma unroll
            for (int jq = 0; jq < 2; jq++) {
                uint32_t kbh[4][2];
#pragma unroll
                for (int jj = 0; jj < 4; jj++) {
                    const int j = jq * 4 + jj;
                    LDSM2(kbh[jj],
                          sk + (uint32_t)(j * 8 * AT_SROW) + brow + t * 32);
                }
#pragma unroll
                for (int jj = 0; jj < 4; jj++)
                    MMA_F16(s[jq * 4 + jj], qhf[t], kbh[jj]);
#pragma unroll
                for (int jj = 0; jj < 4; jj++)
                    MMA_F16(s[jq * 4 + jj], qlf[t], kbh[jj]);
            }
        }

        // Online softmax (rows r=lane>>2 and r+8; quad holds a row)
        float rmx0 = s[0][0], rmx1 = s[0][2];
#pragma unroll
        for (int j = 0; j < 8; j++) {
            rmx0 = fmaxf(rmx0, fmaxf(s[j][0], s[j][1]));
            rmx1 = fmaxf(rmx1, fmaxf(s[j][2], s[j][3]));
        }
        rmx0 = fmaxf(rmx0, __shfl_xor_sync(0xffffffffu, rmx0, 1));
        rmx0 = fmaxf(rmx0, __shfl_xor_sync(0xffffffffu, rmx0, 2));
        rmx1 = fmaxf(rmx1, __shfl_xor_sync(0xffffffffu, rmx1, 1));
        rmx1 = fmaxf(rmx1, __shfl_xor_sync(0xffffffffu, rmx1, 2));

        const float mn0 = fmaxf(m2[0], rmx0);
        const float mn1 = fmaxf(m2[1], rmx1);
        const float c0 = fast_ex2(m2[0] - mn0);
        const float c1 = fast_ex2(m2[1] - mn1);
        m2[0] = mn0; m2[1] = mn1;

        float rs0 = 0.f, rs1 = 0.f;
#pragma unroll
        for (int j = 0; j < 8; j++) {
            s[j][0] = fast_ex2(s[j][0] - mn0);
            s[j][1] = fast_ex2(s[j][1] - mn0);
            s[j][2] = fast_ex2(s[j][2] - mn1);
            s[j][3] = fast_ex2(s[j][3] - mn1);
            rs0 += s[j][0] + s[j][1];
            rs1 += s[j][2] + s[j][3];
        }
        rs0 += __shfl_xor_sync(0xffffffffu, rs0, 1);
        rs0 += __shfl_xor_sync(0xffffffffu, rs0, 2);
        rs1 += __shfl_xor_sync(0xffffffffu, rs1, 1);
        rs1 += __shfl_xor_sync(0xffffffffu, rs1, 2);
        l[0] = l[0] * c0 + rs0;
        l[1] = l[1] * c1 + rs1;
#pragma unroll
        for (int j = 0; j < 8; j++) {
            po[j][0] *= c0; po[j][1] *= c0;
            po[j][2] *= c1; po[j][3] *= c1;
        }

        // O += Ph (Vh + Vl) : P fp16 unsplit (accumulator frag == A frag)
#pragma unroll
        for (int t = 0; t < 4; t++) {
            uint32_t ph[4];
            ph[0] = pack_h2(s[2 * t][0],     s[2 * t][1]);
            ph[1] = pack_h2(s[2 * t][2],     s[2 * t][3]);
            ph[2] = pack_h2(s[2 * t + 1][0], s[2 * t + 1][1]);
            ph[3] = pack_h2(s[2 * t + 1][2], s[2 * t + 1][3]);
#pragma unroll
            for (int jq = 0; jq < 2; jq++) {
                uint32_t vbh[4][2], vbl[4][2];
#pragma unroll
                for (int jj = 0; jj < 4; jj++) {
                    const int j = jq * 4 + jj;
                    const uint32_t vb =
                        sv + (uint32_t)(j * 8 * AT_SROW) + brow + t * 32;
                    LDSM2(vbh[jj], vb);
                    LDSM2(vbl[jj], vb + AT_KT_B);
                }
#pragma unroll
                for (int jj = 0; jj < 4; jj++)
                    MMA_F16(po[jq * 4 + jj], ph, vbh[jj]);
#pragma unroll
                for (int jj = 0; jj < 4; jj++)
                    MMA_F16(po[jq * 4 + jj], ph, vbl[jj]);
            }
        }
        __syncthreads();
    }

    // Epilogue: O/l -> fp16 hi/lo [tok][h*64+d]
    const int h = bh & 15, bb = bh >> 4;
    const int tok0 = qt * 128 + wid * 16 + (lane >> 2);
    const float inv0 = 1.f / l[0], inv1 = 1.f / l[1];
#pragma unroll
    for (int j = 0; j < 8; j++) {
        const int d = h * HDIM + j * 8 + (lane & 3) * 2;
        const size_t a0 = ((size_t)(bb * SEQ + tok0)) * DIM + d;
        const size_t a1 = a0 + (size_t)8 * DIM;
        const float v0 = po[j][0] * inv0, v1 = po[j][1] * inv0;
        const float v2 = po[j][2] * inv1, v3 = po[j][3] * inv1;
        uint32_t h2 = pack_h2(v0, v1);
        *(uint32_t*)(g_ohi + a0) = h2;
        *(uint32_t*)(g_olo + a0) = pack_l2(v0, v1, h2);
        h2 = pack_h2(v2, v3);
        *(uint32_t*)(g_ohi + a1) = h2;
        *(uint32_t*)(g_olo + a1) = pack_l2(v2, v3, h2);
    }
}

// ---------------------------------------------------------------------------

extern "C" void kernel_launch(void* const* d_in, const int* in_sizes, int n_in,
                              void* d_out, int out_size)
{
    const float* x      = (const float*)d_in[0];
    const float* w_qkv  = (const float*)d_in[1];
    const float* b_qkv  = (const float*)d_in[2];
    const float* w_proj = (const float*)d_in[3];
    const float* b_proj = (const float*)d_in[4];
    float* out = (float*)d_out;

    __half *h_xhi, *h_xlo, *h_wqh, *h_wph, *h_ohi, *h_olo;
    cudaGetSymbolAddress((void**)&h_xhi, g_xhi);
    cudaGetSymbolAddress((void**)&h_xlo, g_xlo);
    cudaGetSymbolAddress((void**)&h_wqh, g_wqh);
    cudaGetSymbolAddress((void**)&h_wph, g_wph);
    cudaGetSymbolAddress((void**)&h_ohi, g_ohi);
    cudaGetSymbolAddress((void**)&h_olo, g_olo);

    cudaFuncSetAttribute(gemm_fp16x2_kernel,
                         cudaFuncAttributeMaxDynamicSharedMemorySize,
                         GEMM_DYN_BYTES);
    cudaFuncSetAttribute(attn_mma_kernel,
                         cudaFuncAttributeMaxDynamicSharedMemorySize,
                         AT_SMEM);

    // 1. Convert: x -> hi/lo, weights -> single fp16
    cvt_hilo_kernel<<<(M_TOK * DIM / 4 + 255) / 256, 256>>>(
        x, h_xhi, h_xlo, M_TOK * DIM / 4);
    cvt_h_kernel<<<(3 * DIM * DIM / 4 + 255) / 256, 256>>>(
        w_qkv, h_wqh, 3 * DIM * DIM / 4);
    cvt_h_kernel<<<(DIM * DIM / 4 + 255) / 256, 256>>>(
        w_proj, h_wph, DIM * DIM / 4);

    // 2. QKV GEMM -> fp16 Q(hi/lo) / K / V(hi/lo) in attention layouts
    dim3 gq(3 * DIM / 128, M_TOK / 128);
    gemm_fp16x2_kernel<<<gq, 256, GEMM_DYN_BYTES>>>(
        h_xhi, h_xlo, h_wqh, b_qkv, nullptr, 0);

    // 3. Tensor-core flash attention -> g_ohi/g_olo
    dim3 ga(SEQ / 128, NBH);
    attn_mma_kernel<<<ga, 256, AT_SMEM>>>();

    // 4. Projection GEMM: M=4096, N=1024
    dim3 gp(DIM / 128, M_TOK / 128);
    gemm_fp16x2_kernel<<<gp, 256, GEMM_DYN_BYTES>>>(
        h_ohi, h_olo, h_wph, b_proj, out, 1);
}

// round 10
// speedup vs baseline: 8.5526x; 1.2110x over previous
#include <cuda_runtime.h>
#include <cuda_fp16.h>
#include <cstdint>

// Problem constants
#define BATCH 2
#define SEQ   2048
#define DIM   1024
#define NHEAD 16
#define HDIM  64
// SCALE * log2(e): fold into Q so QK^T scores are already in base-2 domain
#define QSCALE (0.125f * 1.4426950408889634f)

#define M_TOK (BATCH * SEQ)          // 4096 rows of tokens
#define NBH   (BATCH * NHEAD)        // 32

// ---------------------------------------------------------------------------
// Scratch (device globals: allocation-free rule)   — fp16 everywhere
// ---------------------------------------------------------------------------
// Q: [bh][tok][64] fp16 (pre-scaled by QSCALE); K: [bh][tok][64] fp16
// V: [bh][d][tok]  fp16 (d-major for PV B-fragments)
__device__ __half g_q[NBH * SEQ * HDIM];
__device__ __half g_k[NBH * SEQ * HDIM];
__device__ __half g_v[NBH * HDIM * SEQ];
// attention output, hi/lo, [b*n][h*64+d]  (proj GEMM split A input)
__device__ __half g_ohi[M_TOK * DIM];
__device__ __half g_olo[M_TOK * DIM];
// GEMM operand splits: activations split, weights single
__device__ __half g_xhi[M_TOK * DIM];
__device__ __half g_xlo[M_TOK * DIM];
__device__ __half g_wqh[3 * DIM * DIM];
__device__ __half g_wph[DIM * DIM];

// ---------------------------------------------------------------------------
// PTX helpers: mma.sync / ldmatrix / cp.async (valid at plain sm_103)
// ---------------------------------------------------------------------------
__device__ __forceinline__ uint32_t smem_u32(const void* p) {
    uint32_t a;
    asm("{ .reg .u64 t; cvta.to.shared.u64 t, %1; cvt.u32.u64 %0, t; }"
        : "=r"(a) : "l"(p));
    return a;
}

#define CP_ASYNC16(dst, src) \
    asm volatile("cp.async.cg.shared.global [%0], [%1], 16;" \
        :: "r"(dst), "l"(src))
#define CP_COMMIT() asm volatile("cp.async.commit_group;" ::: "memory")
#define CP_WAIT(n)  asm volatile("cp.async.wait_group %0;" :: "n"(n) : "memory")

#define LDSM4(r, addr) \
    asm volatile("ldmatrix.sync.aligned.m8n8.x4.shared.b16 {%0,%1,%2,%3}, [%4];" \
        : "=r"((r)[0]), "=r"((r)[1]), "=r"((r)[2]), "=r"((r)[3]) : "r"(addr))
#define LDSM2(r, addr) \
    asm volatile("ldmatrix.sync.aligned.m8n8.x2.shared.b16 {%0,%1}, [%2];" \
        : "=r"((r)[0]), "=r"((r)[1]) : "r"(addr))

#define MMA_F16(d, a, b) \
    asm volatile("mma.sync.aligned.m16n8k16.row.col.f32.f16.f16.f32 " \
        "{%0,%1,%2,%3}, {%4,%5,%6,%7}, {%8,%9}, {%0,%1,%2,%3};" \
        : "+f"((d)[0]), "+f"((d)[1]), "+f"((d)[2]), "+f"((d)[3]) \
        : "r"((a)[0]), "r"((a)[1]), "r"((a)[2]), "r"((a)[3]), \
          "r"((b)[0]), "r"((b)[1]))

// fast 2^y for y <= 0 (FMA/ALU pipes, no MUFU)
__device__ __forceinline__ float fast_ex2(float y) {
    y = fmaxf(y, -120.f);
    const float z = y + 12582912.f;              // 1.5 * 2^23
    const float r = y - (z - 12582912.f);
    const uint32_t fb = (__float_as_uint(z) + 0xB4C0007Fu) << 23;  // 2^n
    float p = 0.0013333558f;
    p = fmaf(p, r, 0.0096181291f);
    p = fmaf(p, r, 0.0555041087f);
    p = fmaf(p, r, 0.2402265069f);
    p = fmaf(p, r, 0.6931471806f);
    p = fmaf(p, r, 1.0f);
    return __uint_as_float(fb) * p;
}

__device__ __forceinline__ uint32_t pack_h2(float x, float y) {
    __half2 h = __floats2half2_rn(x, y);
    return *(uint32_t*)&h;
}
__device__ __forceinline__ uint32_t pack_l2(float x, float y, uint32_t h2) {
    __half2 h = *(__half2*)&h2;
    __half2 l = __floats2half2_rn(x - __half2float(h.x),
                                  y - __half2float(h.y));
    return *(uint32_t*)&l;
}

// ---------------------------------------------------------------------------
// fp32 -> fp16 converters (hi/lo split, and single)
// ---------------------------------------------------------------------------
__global__ __launch_bounds__(256) void cvt_hilo_kernel(
    const float* __restrict__ x, __half* __restrict__ hi,
    __half* __restrict__ lo, int n4)
{
    const int i = blockIdx.x * blockDim.x + threadIdx.x;
    if (i >= n4) return;
    const float4 v = ((const float4*)x)[i];
    uint32_t h0 = pack_h2(v.x, v.y), h1 = pack_h2(v.z, v.w);
    ((uint32_t*)hi)[2 * i]     = h0;
    ((uint32_t*)hi)[2 * i + 1] = h1;
    ((uint32_t*)lo)[2 * i]     = pack_l2(v.x, v.y, h0);
    ((uint32_t*)lo)[2 * i + 1] = pack_l2(v.z, v.w, h1);
}

__global__ __launch_bounds__(256) void cvt_h_kernel(
    const float* __restrict__ x, __half* __restrict__ hi, int n4)
{
    const int i = blockIdx.x * blockDim.x + threadIdx.x;
    if (i >= n4) return;
    const float4 v = ((const float4*)x)[i];
    ((uint32_t*)hi)[2 * i]     = pack_h2(v.x, v.y);
    ((uint32_t*)hi)[2 * i + 1] = pack_h2(v.z, v.w);
}

// ---------------------------------------------------------------------------
// mma.sync fp16x2 GEMM: D[m,n] = sum_k (Ah+Al)[m,k]*Bh[n,k] + bias[n]
// CTA 128x128, BK=32, 8 warps, cp.async double buffer. 2 MMAs per product.
// mode 0: QKV epilogue (emit fp16 Q/K/V in attention layouts)
// mode 1: plain fp32 row-major out.
// ---------------------------------------------------------------------------
#define BK 32
#define SROW 80
#define TILE_B (128 * SROW)
#define STAGE_B (3 * TILE_B)        // Ah, Al, Bh
#define GEMM_DYN_BYTES (2 * STAGE_B)
#define NCHUNK (DIM / BK)

__device__ __forceinline__ void stage_load(
    char* stage,
    const __half* __restrict__ Ah, const __half* __restrict__ Al,
    const __half* __restrict__ Bh, int k0, int tid)
{
    const int row  = tid >> 1;
    const int half = tid & 1;
    const uint32_t doff = (uint32_t)(row * SROW + half * 32);
    const size_t goff = (size_t)row * DIM + k0 + half * 16;

    const uint32_t d0 = smem_u32(stage) + doff;
    CP_ASYNC16(d0,                   Ah + goff);
    CP_ASYNC16(d0 + 16,              Ah + goff + 8);
    CP_ASYNC16(d0 + TILE_B,          Al + goff);
    CP_ASYNC16(d0 + TILE_B + 16,     Al + goff + 8);
    CP_ASYNC16(d0 + 2 * TILE_B,      Bh + goff);
    CP_ASYNC16(d0 + 2 * TILE_B + 16, Bh + goff + 8);
}

__global__ __launch_bounds__(256, 2) void gemm_fp16x2_kernel(
    const __half* __restrict__ Ahi, const __half* __restrict__ Alo,
    const __half* __restrict__ Bhs,
    const float* __restrict__ bias, float* __restrict__ outp, int mode)
{
    extern __shared__ __align__(128) char smd[];
    const uint32_t smb = smem_u32(smd);

    const int tid  = threadIdx.x;
    const int wid  = tid >> 5;
    const int lane = tid & 31;
    const int m0 = blockIdx.y * 128;
    const int n0 = blockIdx.x * 128;

    const int wm = (wid >> 2) * 64;
    const int wn = (wid & 3) * 32;

    const __half* Ah = Ahi + (size_t)m0 * DIM;
    const __half* Al = Alo + (size_t)m0 * DIM;
    const __half* Bh = Bhs + (size_t)n0 * DIM;

    float acc[4][4][4];
#pragma unroll
    for (int i = 0; i < 4; i++)
#pragma unroll
        for (int j = 0; j < 4; j++)
#pragma unroll
            for (int e = 0; e < 4; e++) acc[i][j][e] = 0.f;

    const uint32_t a_row  = (uint32_t)(wm + (lane & 15));
    const uint32_t a_coff = (uint32_t)((lane >> 4) * 16);
    const uint32_t b_row  = (uint32_t)(wn + (lane & 7));
    const uint32_t b_coff = (uint32_t)(((lane >> 3) & 1) * 16);

    stage_load(smd, Ah, Al, Bh, 0, tid);
    CP_COMMIT();

    for (int c = 0; c < NCHUNK; ++c) {
        if (c + 1 < NCHUNK) {
            stage_load(smd + ((c + 1) & 1) * STAGE_B, Ah, Al, Bh,
                       (c + 1) * BK, tid);
            CP_COMMIT();
            CP_WAIT(1);
        } else {
            CP_WAIT(0);
        }
        __syncthreads();

        const uint32_t sb = smb + (c & 1) * STAGE_B;
#pragma unroll
        for (int ks = 0; ks < 2; ++ks) {
            uint32_t bhf[4][2];
#pragma unroll
            for (int j = 0; j < 4; ++j) {
                const uint32_t ba =
                    sb + 2 * TILE_B + (b_row + 8 * j) * SROW + ks * 32 + b_coff;
                LDSM2(bhf[j], ba);
            }
#pragma unroll
            for (int i = 0; i < 4; ++i) {
                uint32_t ahf[4], alf[4];
                const uint32_t aa =
                    sb + (a_row + 16 * i) * SROW + ks * 32 + a_coff;
                LDSM4(ahf, aa);
                LDSM4(alf, aa + TILE_B);
                // term-major: same-acc reuse distance = 4
#pragma unroll
                for (int j = 0; j < 4; ++j) MMA_F16(acc[i][j], ahf, bhf[j]);
#pragma unroll
                for (int j = 0; j < 4; ++j) MMA_F16(acc[i][j], alf, bhf[j]);
            }
        }
        __syncthreads();
    }

    // Epilogue. acc map: c0:(m,n) c1:(m,n+1) c2:(m+8,n) c3:(m+8,n+1)
    const int mloc0 = wm + (lane >> 2);
    const int nloc0 = wn + (lane & 3) * 2;

    if (mode == 0) {
        const int which = n0 >> 10;          // 0=Q 1=K 2=V (CTA-uniform)
        const int bI    = m0 >> 11;
        const int tokb  = m0 & 2047;
#pragma unroll
        for (int i = 0; i < 4; ++i) {
#pragma unroll
            for (int j = 0; j < 4; ++j) {
                const int n_g = n0 + nloc0 + 8 * j;
                const int tok = tokb + mloc0 + 16 * i;
                const int h = (n_g & 1023) >> 6;
                const int d = n_g & 63;
                const int bh = bI * NHEAD + h;
                float v0 = acc[i][j][0] + bias[n_g];
                float v1 = acc[i][j][1] + bias[n_g + 1];
                float v2 = acc[i][j][2] + bias[n_g];
                float v3 = acc[i][j][3] + bias[n_g + 1];
                if (which == 0) {
                    v0 *= QSCALE; v1 *= QSCALE; v2 *= QSCALE; v3 *= QSCALE;
                    const size_t a0 = ((size_t)bh * SEQ + tok) * HDIM + d;
                    *(uint32_t*)(g_q + a0)            = pack_h2(v0, v1);
                    *(uint32_t*)(g_q + a0 + 8 * HDIM) = pack_h2(v2, v3);
                } else if (which == 1) {
                    const size_t a0 = ((size_t)bh * SEQ + tok) * HDIM + d;
                    *(uint32_t*)(g_k + a0)            = pack_h2(v0, v1);
                    *(uint32_t*)(g_k + a0 + 8 * HDIM) = pack_h2(v2, v3);
                } else {
                    // V d-major: [bh][d][tok]
                    const size_t b0 = ((size_t)bh * HDIM + d) * SEQ + tok;
                    g_v[b0]           = __float2half_rn(v0);
                    g_v[b0 + SEQ]     = __float2half_rn(v1);
                    g_v[b0 + 8]       = __float2half_rn(v2);
                    g_v[b0 + SEQ + 8] = __float2half_rn(v3);
                }
            }
        }
    } else {
#pragma unroll
        for (int i = 0; i < 4; ++i) {
#pragma unroll
            for (int j = 0; j < 4; ++j) {
                const int n_g = n0 + nloc0 + 8 * j;
                const int m_g = m0 + mloc0 + 16 * i;
                const float bv0 = bias[n_g], bv1 = bias[n_g + 1];
                float* r0 = outp + (size_t)m_g * DIM + n_g;
                *(float2*)r0 =
                    make_float2(acc[i][j][0] + bv0, acc[i][j][1] + bv1);
                *(float2*)(r0 + 8 * DIM) =
                    make_float2(acc[i][j][2] + bv0, acc[i][j][3] + bv1);
            }
        }
    }
}

// ---------------------------------------------------------------------------
// Flash attention, pure fp16 mma.sync (1 MMA per product).
// CTA: 128 q-rows x one bh; 8 warps. S = Q*K, O += P*V.
// ---------------------------------------------------------------------------
#define AT_SROW 144                       // 64 fp16 + 16B pad
#define AT_QT_B (128 * AT_SROW)           // 18432
#define AT_KT_B (64 * AT_SROW)            // 9216
#define AT_ST_B (2 * AT_KT_B)             // 18432: K, V
#define AT_SMEM (AT_QT_B + 2 * AT_ST_B)   // 55296

__device__ __forceinline__ void load_kv_tile(uint32_t st, int bh, int kt, int tid)
{
    const __half* kh = g_k + ((size_t)bh * SEQ + kt * 64) * HDIM;
    const __half* vh = g_v + (size_t)bh * HDIM * SEQ + kt * 64;
#pragma unroll
    for (int i = 0; i < 2; i++) {
        const int idx = tid + i * 256;    // 0..511
        const int row = idx >> 3, ch = idx & 7;
        const uint32_t so = (uint32_t)(row * AT_SROW + ch * 16);
        CP_ASYNC16(st + so,           kh + (size_t)row * HDIM + ch * 8);
        CP_ASYNC16(st + AT_KT_B + so, vh + (size_t)row * SEQ + ch * 8);
    }
}

__global__ __launch_bounds__(256, 2) void attn_mma_kernel()
{
    extern __shared__ __align__(128) char sm[];
    const uint32_t smb = smem_u32(sm);
    const uint32_t q_s = smb;
    const uint32_t st0 = smb + AT_QT_B;

    const int tid = threadIdx.x;
    const int wid = tid >> 5, lane = tid & 31;
    const int qt = blockIdx.x, bh = blockIdx.y;

    // Load Q tile, 128 rows x 64 fp16
    {
        const __half* qh = g_q + ((size_t)bh * SEQ + qt * 128) * HDIM;
#pragma unroll
        for (int i = 0; i < 4; i++) {
            const int idx = tid + i * 256;     // 0..1023
            const int row = idx >> 3, ch = idx & 7;
            CP_ASYNC16(q_s + (uint32_t)(row * AT_SROW + ch * 16),
                       qh + (size_t)row * HDIM + ch * 8);
        }
        CP_COMMIT();
    }
    load_kv_tile(st0, bh, 0, tid);
    CP_COMMIT();
    CP_WAIT(1);                // Q complete (KV tile 0 may be pending)
    __syncthreads();

    // Q A-fragments, register-resident: 4 ksteps
    uint32_t qf[4][4];
    {
        const uint32_t qa =
            (uint32_t)((wid * 16 + (lane & 15)) * AT_SROW + (lane >> 4) * 16);
#pragma unroll
        for (int t = 0; t < 4; t++) LDSM4(qf[t], q_s + qa + t * 32);
    }

    float m2[2] = {-1e30f, -1e30f}, l[2] = {0.f, 0.f};
    float po[8][4];
#pragma unroll
    for (int j = 0; j < 8; j++)
#pragma unroll
        for (int e = 0; e < 4; e++) po[j][e] = 0.f;

    const uint32_t brow =
        (uint32_t)((lane & 7) * AT_SROW + ((lane >> 3) & 1) * 16);

    for (int kt = 0; kt < SEQ / 64; kt++) {
        if (kt + 1 < SEQ / 64) {
            load_kv_tile(st0 + ((kt + 1) & 1) * AT_ST_B, bh, kt + 1, tid);
            CP_COMMIT();
            CP_WAIT(1);
        } else {
            CP_WAIT(0);
        }
        __syncthreads();

        const uint32_t sk = st0 + (kt & 1) * AT_ST_B;
        const uint32_t sv = sk + AT_KT_B;

        // S = Q K^T, kstep-outer, quad-striped accumulators
        float s[8][4];
#pragma unroll
        for (int j = 0; j < 8; j++)
#pragma unroll
            for (int e = 0; e < 4; e++) s[j][e] = 0.f;

#pragma unroll
        for (int t = 0; t < 4; t++) {
#pragma unroll
            for (int jq = 0; jq < 2; jq++) {
                uint32_t kbh[4][2];
#pragma unroll
                for (int jj = 0; jj < 4; jj++) {
                    const int j = jq * 4 + jj;
                    LDSM2(kbh[jj],
                          sk + (uint32_t)(j * 8 * AT_SROW) + brow + t * 32);
                }
#pragma unroll
                for (int jj = 0; jj < 4; jj++)
                    MMA_F16(s[jq * 4 + jj], qf[t], kbh[jj]);
            }
        }

        // Online softmax (rows r=lane>>2 and r+8; quad holds a row)
        float rmx0 = s[0][0], rmx1 = s[0][2];
#pragma unroll
        for (int j = 0; j < 8; j++) {
            rmx0 = fmaxf(rmx0, fmaxf(s[j][0], s[j][1]));
            rmx1 = fmaxf(rmx1, fmaxf(s[j][2], s[j][3]));
        }
        rmx0 = fmaxf(rmx0, __shfl_xor_sync(0xffffffffu, rmx0, 1));
        rmx0 = fmaxf(rmx0, __shfl_xor_sync(0xffffffffu, rmx0, 2));
        rmx1 = fmaxf(rmx1, __shfl_xor_sync(0xffffffffu, rmx1, 1));
        rmx1 = fmaxf(rmx1, __shfl_xor_sync(0xffffffffu, rmx1, 2));

        const float mn0 = fmaxf(m2[0], rmx0);
        const float mn1 = fmaxf(m2[1], rmx1);
        const float c0 = fast_ex2(m2[0] - mn0);
        const float c1 = fast_ex2(m2[1] - mn1);
        m2[0] = mn0; m2[1] = mn1;

        float rs0 = 0.f, rs1 = 0.f;
#pragma unroll
        for (int j = 0; j < 8; j++) {
            s[j][0] = fast_ex2(s[j][0] - mn0);
            s[j][1] = fast_ex2(s[j][1] - mn0);
            s[j][2] = fast_ex2(s[j][2] - mn1);
            s[j][3] = fast_ex2(s[j][3] - mn1);
            rs0 += s[j][0] + s[j][1];
            rs1 += s[j][2] + s[j][3];
        }
        rs0 += __shfl_xor_sync(0xffffffffu, rs0, 1);
        rs0 += __shfl_xor_sync(0xffffffffu, rs0, 2);
        rs1 += __shfl_xor_sync(0xffffffffu, rs1, 1);
        rs1 += __shfl_xor_sync(0xffffffffu, rs1, 2);
        l[0] = l[0] * c0 + rs0;
        l[1] = l[1] * c1 + rs1;
#pragma unroll
        for (int j = 0; j < 8; j++) {
            po[j][0] *= c0; po[j][1] *= c0;
            po[j][2] *= c1; po[j][3] *= c1;
        }

        // O += P V : P fp16 (accumulator frag == A frag)
#pragma unroll
        for (int t = 0; t < 4; t++) {
            uint32_t ph[4];
            ph[0] = pack_h2(s[2 * t][0],     s[2 * t][1]);
            ph[1] = pack_h2(s[2 * t][2],     s[2 * t][3]);
            ph[2] = pack_h2(s[2 * t + 1][0], s[2 * t + 1][1]);
            ph[3] = pack_h2(s[2 * t + 1][2], s[2 * t + 1][3]);
#pragma unroll
            for (int jq = 0; jq < 2; jq++) {
                uint32_t vbh[4][2];
#pragma unroll
                for (int jj = 0; jj < 4; jj++) {
                    const int j = jq * 4 + jj;
                    LDSM2(vbh[jj],
                          sv + (uint32_t)(j * 8 * AT_SROW) + brow + t * 32);
                }
#pragma unroll
                for (int jj = 0; jj < 4; jj++)
                    MMA_F16(po[jq * 4 + jj], ph, vbh[jj]);
            }
        }
        __syncthreads();
    }

    // Epilogue: O/l -> fp16 hi/lo [tok][h*64+d]
    const int h = bh & 15, bb = bh >> 4;
    const int tok0 = qt * 128 + wid * 16 + (lane >> 2);
    const float inv0 = 1.f / l[0], inv1 = 1.f / l[1];
#pragma unroll
    for (int j = 0; j < 8; j++) {
        const int d = h * HDIM + j * 8 + (lane & 3) * 2;
        const size_t a0 = ((size_t)(bb * SEQ + tok0)) * DIM + d;
        const size_t a1 = a0 + (size_t)8 * DIM;
        const float v0 = po[j][0] * inv0, v1 = po[j][1] * inv0;
        const float v2 = po[j][2] * inv1, v3 = po[j][3] * inv1;
        uint32_t h2 = pack_h2(v0, v1);
        *(uint32_t*)(g_ohi + a0) = h2;
        *(uint32_t*)(g_olo + a0) = pack_l2(v0, v1, h2);
        h2 = pack_h2(v2, v3);
        *(uint32_t*)(g_ohi + a1) = h2;
        *(uint32_t*)(g_olo + a1) = pack_l2(v2, v3, h2);
    }
}

// ---------------------------------------------------------------------------

extern "C" void kernel_launch(void* const* d_in, const int* in_sizes, int n_in,
                              void* d_out, int out_size)
{
    const float* x      = (const float*)d_in[0];
    const float* w_qkv  = (const float*)d_in[1];
    const float* b_qkv  = (const float*)d_in[2];
    const float* w_proj = (const float*)d_in[3];
    const float* b_proj = (const float*)d_in[4];
    float* out = (float*)d_out;

    __half *h_xhi, *h_xlo, *h_wqh, *h_wph, *h_ohi, *h_olo;
    cudaGetSymbolAddress((void**)&h_xhi, g_xhi);
    cudaGetSymbolAddress((void**)&h_xlo, g_xlo);
    cudaGetSymbolAddress((void**)&h_wqh, g_wqh);
    cudaGetSymbolAddress((void**)&h_wph, g_wph);
    cudaGetSymbolAddress((void**)&h_ohi, g_ohi);
    cudaGetSymbolAddress((void**)&h_olo, g_olo);

    cudaFuncSetAttribute(gemm_fp16x2_kernel,
                         cudaFuncAttributeMaxDynamicSharedMemorySize,
                         GEMM_DYN_BYTES);
    cudaFuncSetAttribute(attn_mma_kernel,
                         cudaFuncAttributeMaxDynamicSharedMemorySize,
                         AT_SMEM);

    // 1. Convert: x -> hi/lo, weights -> single fp16
    cvt_hilo_kernel<<<(M_TOK * DIM / 4 + 255) / 256, 256>>>(
        x, h_xhi, h_xlo, M_TOK * DIM / 4);
    cvt_h_kernel<<<(3 * DIM * DIM / 4 + 255) / 256, 256>>>(
        w_qkv, h_wqh, 3 * DIM * DIM / 4);
    cvt_h_kernel<<<(DIM * DIM / 4 + 255) / 256, 256>>>(
        w_proj, h_wph, DIM * DIM / 4);

    // 2. QKV GEMM -> fp16 Q / K / V in attention layouts
    dim3 gq(3 * DIM / 128, M_TOK / 128);
    gemm_fp16x2_kernel<<<gq, 256, GEMM_DYN_BYTES>>>(
        h_xhi, h_xlo, h_wqh, b_qkv, nullptr, 0);

    // 3. Tensor-core flash attention -> g_ohi/g_olo
    dim3 ga(SEQ / 128, NBH);
    attn_mma_kernel<<<ga, 256, AT_SMEM>>>();

    // 4. Projection GEMM: M=4096, N=1024
    dim3 gp(DIM / 128, M_TOK / 128);
    gemm_fp16x2_kernel<<<gp, 256, GEMM_DYN_BYTES>>>(
        h_ohi, h_olo, h_wph, b_proj, out, 1);
}

// round 11
// speedup vs baseline: 10.1778x; 1.1900x over previous
#include <cuda_runtime.h>
#include <cuda_fp16.h>
#include <cstdint>

// Problem constants
#define BATCH 2
#define SEQ   2048
#define DIM   1024
#define NHEAD 16
#define HDIM  64
// SCALE * log2(e): fold into Q so QK^T scores are already in base-2 domain
#define QSCALE (0.125f * 1.4426950408889634f)

#define M_TOK (BATCH * SEQ)          // 4096 rows of tokens
#define NBH   (BATCH * NHEAD)        // 32

// ---------------------------------------------------------------------------
// Scratch (device globals: allocation-free rule)   — fp16 everywhere
// ---------------------------------------------------------------------------
// Q: [bh][tok][64] fp16 (pre-scaled by QSCALE); K: [bh][tok][64] fp16
// V: [bh][d][tok]  fp16 (d-major for PV B-fragments)
__device__ __half g_q[NBH * SEQ * HDIM];
__device__ __half g_k[NBH * SEQ * HDIM];
__device__ __half g_v[NBH * HDIM * SEQ];
// attention output, hi/lo, [b*n][h*64+d]  (proj GEMM split A input)
__device__ __half g_ohi[M_TOK * DIM];
__device__ __half g_olo[M_TOK * DIM];
// GEMM operands: x single fp16 (precision beyond fp16 is rounded away by the
// qkv epilogue anyway), weights single fp16
__device__ __half g_xh[M_TOK * DIM];
__device__ __half g_wqh[3 * DIM * DIM];
__device__ __half g_wph[DIM * DIM];

// ---------------------------------------------------------------------------
// PTX helpers: mma.sync / ldmatrix / cp.async (valid at plain sm_103)
// ---------------------------------------------------------------------------
__device__ __forceinline__ uint32_t smem_u32(const void* p) {
    uint32_t a;
    asm("{ .reg .u64 t; cvta.to.shared.u64 t, %1; cvt.u32.u64 %0, t; }"
        : "=r"(a) : "l"(p));
    return a;
}

#define CP_ASYNC16(dst, src) \
    asm volatile("cp.async.cg.shared.global [%0], [%1], 16;" \
        :: "r"(dst), "l"(src))
#define CP_COMMIT() asm volatile("cp.async.commit_group;" ::: "memory")
#define CP_WAIT(n)  asm volatile("cp.async.wait_group %0;" :: "n"(n) : "memory")

#define LDSM4(r, addr) \
    asm volatile("ldmatrix.sync.aligned.m8n8.x4.shared.b16 {%0,%1,%2,%3}, [%4];" \
        : "=r"((r)[0]), "=r"((r)[1]), "=r"((r)[2]), "=r"((r)[3]) : "r"(addr))
#define LDSM2(r, addr) \
    asm volatile("ldmatrix.sync.aligned.m8n8.x2.shared.b16 {%0,%1}, [%2];" \
        : "=r"((r)[0]), "=r"((r)[1]) : "r"(addr))

#define MMA_F16(d, a, b) \
    asm volatile("mma.sync.aligned.m16n8k16.row.col.f32.f16.f16.f32 " \
        "{%0,%1,%2,%3}, {%4,%5,%6,%7}, {%8,%9}, {%0,%1,%2,%3};" \
        : "+f"((d)[0]), "+f"((d)[1]), "+f"((d)[2]), "+f"((d)[3]) \
        : "r"((a)[0]), "r"((a)[1]), "r"((a)[2]), "r"((a)[3]), \
          "r"((b)[0]), "r"((b)[1]))

// fast 2^y for y <= 0 (FMA/ALU pipes, no MUFU)
__device__ __forceinline__ float fast_ex2(float y) {
    y = fmaxf(y, -120.f);
    const float z = y + 12582912.f;              // 1.5 * 2^23
    const float r = y - (z - 12582912.f);
    const uint32_t fb = (__float_as_uint(z) + 0xB4C0007Fu) << 23;  // 2^n
    float p = 0.0013333558f;
    p = fmaf(p, r, 0.0096181291f);
    p = fmaf(p, r, 0.0555041087f);
    p = fmaf(p, r, 0.2402265069f);
    p = fmaf(p, r, 0.6931471806f);
    p = fmaf(p, r, 1.0f);
    return __uint_as_float(fb) * p;
}

__device__ __forceinline__ uint32_t pack_h2(float x, float y) {
    __half2 h = __floats2half2_rn(x, y);
    return *(uint32_t*)&h;
}
__device__ __forceinline__ uint32_t pack_l2(float x, float y, uint32_t h2) {
    __half2 h = *(__half2*)&h2;
    __half2 l = __floats2half2_rn(x - __half2float(h.x),
                                  y - __half2float(h.y));
    return *(uint32_t*)&l;
}

// ---------------------------------------------------------------------------
// fp32 -> fp16 converter (single)
// ---------------------------------------------------------------------------
__global__ __launch_bounds__(256) void cvt_h_kernel(
    const float* __restrict__ x, __half* __restrict__ hi, int n4)
{
    const int i = blockIdx.x * blockDim.x + threadIdx.x;
    if (i >= n4) return;
    const float4 v = ((const float4*)x)[i];
    ((uint32_t*)hi)[2 * i]     = pack_h2(v.x, v.y);
    ((uint32_t*)hi)[2 * i + 1] = pack_h2(v.z, v.w);
}

// ---------------------------------------------------------------------------
// mma.sync fp16 GEMM: D[m,n] = sum_k A[m,k]*B[n,k] + bias[n]
// SPLIT=1: A = Ah + Al (2 MMAs per product); SPLIT=0: A = Ah (1 MMA).
// CTA 128x128, BK=32, 8 warps, cp.async double buffer.
// mode 0: QKV epilogue (emit fp16 Q/K/V in attention layouts)
// mode 1: plain fp32 row-major out.
// ---------------------------------------------------------------------------
#define BK 32
#define SROW 80
#define TILE_B (128 * SROW)
#define NCHUNK (DIM / BK)

template <int SPLIT>
__device__ __forceinline__ void stage_load(
    char* stage,
    const __half* __restrict__ Ah, const __half* __restrict__ Al,
    const __half* __restrict__ Bh, int k0, int tid)
{
    const int row  = tid >> 1;
    const int half = tid & 1;
    const uint32_t doff = (uint32_t)(row * SROW + half * 32);
    const size_t goff = (size_t)row * DIM + k0 + half * 16;
    constexpr uint32_t BOFF = (SPLIT ? 2u : 1u) * TILE_B;

    const uint32_t d0 = smem_u32(stage) + doff;
    CP_ASYNC16(d0,             Ah + goff);
    CP_ASYNC16(d0 + 16,        Ah + goff + 8);
    if (SPLIT) {
        CP_ASYNC16(d0 + TILE_B,      Al + goff);
        CP_ASYNC16(d0 + TILE_B + 16, Al + goff + 8);
    }
    CP_ASYNC16(d0 + BOFF,      Bh + goff);
    CP_ASYNC16(d0 + BOFF + 16, Bh + goff + 8);
}

template <int SPLIT>
__global__ __launch_bounds__(256, 2) void gemm_fp16_kernel(
    const __half* __restrict__ Ahi, const __half* __restrict__ Alo,
    const __half* __restrict__ Bhs,
    const float* __restrict__ bias, float* __restrict__ outp, int mode)
{
    constexpr uint32_t STAGE_B = (SPLIT ? 3u : 2u) * TILE_B;
    constexpr uint32_t BOFF    = (SPLIT ? 2u : 1u) * TILE_B;

    extern __shared__ __align__(128) char smd[];
    const uint32_t smb = smem_u32(smd);

    const int tid  = threadIdx.x;
    const int wid  = tid >> 5;
    const int lane = tid & 31;
    const int m0 = blockIdx.y * 128;
    const int n0 = blockIdx.x * 128;

    const int wm = (wid >> 2) * 64;
    const int wn = (wid & 3) * 32;

    const __half* Ah = Ahi + (size_t)m0 * DIM;
    const __half* Al = SPLIT ? (Alo + (size_t)m0 * DIM) : Ahi;
    const __half* Bh = Bhs + (size_t)n0 * DIM;

    float acc[4][4][4];
#pragma unroll
    for (int i = 0; i < 4; i++)
#pragma unroll
        for (int j = 0; j < 4; j++)
#pragma unroll
            for (int e = 0; e < 4; e++) acc[i][j][e] = 0.f;

    const uint32_t a_row  = (uint32_t)(wm + (lane & 15));
    const uint32_t a_coff = (uint32_t)((lane >> 4) * 16);
    const uint32_t b_row  = (uint32_t)(wn + (lane & 7));
    const uint32_t b_coff = (uint32_t)(((lane >> 3) & 1) * 16);

    stage_load<SPLIT>(smd, Ah, Al, Bh, 0, tid);
    CP_COMMIT();

    for (int c = 0; c < NCHUNK; ++c) {
        if (c + 1 < NCHUNK) {
            stage_load<SPLIT>(smd + ((c + 1) & 1) * STAGE_B, Ah, Al, Bh,
                              (c + 1) * BK, tid);
            CP_COMMIT();
            CP_WAIT(1);
        } else {
            CP_WAIT(0);
        }
        __syncthreads();

        const uint32_t sb = smb + (c & 1) * STAGE_B;
#pragma unroll
        for (int ks = 0; ks < 2; ++ks) {
            uint32_t bhf[4][2];
#pragma unroll
            for (int j = 0; j < 4; ++j) {
                const uint32_t ba =
                    sb + BOFF + (b_row + 8 * j) * SROW + ks * 32 + b_coff;
                LDSM2(bhf[j], ba);
            }
#pragma unroll
            for (int i = 0; i < 4; ++i) {
                uint32_t ahf[4];
                const uint32_t aa =
                    sb + (a_row + 16 * i) * SROW + ks * 32 + a_coff;
                LDSM4(ahf, aa);
                // term-major: same-acc reuse distance = 4
#pragma unroll
                for (int j = 0; j < 4; ++j) MMA_F16(acc[i][j], ahf, bhf[j]);
                if (SPLIT) {
                    uint32_t alf[4];
                    LDSM4(alf, aa + TILE_B);
#pragma unroll
                    for (int j = 0; j < 4; ++j)
                        MMA_F16(acc[i][j], alf, bhf[j]);
                }
            }
        }
        __syncthreads();
    }

    // Epilogue. acc map: c0:(m,n) c1:(m,n+1) c2:(m+8,n) c3:(m+8,n+1)
    const int mloc0 = wm + (lane >> 2);
    const int nloc0 = wn + (lane & 3) * 2;

    if (mode == 0) {
        const int which = n0 >> 10;          // 0=Q 1=K 2=V (CTA-uniform)
        const int bI    = m0 >> 11;
        const int tokb  = m0 & 2047;
#pragma unroll
        for (int i = 0; i < 4; ++i) {
#pragma unroll
            for (int j = 0; j < 4; ++j) {
                const int n_g = n0 + nloc0 + 8 * j;
                const int tok = tokb + mloc0 + 16 * i;
                const int h = (n_g & 1023) >> 6;
                const int d = n_g & 63;
                const int bh = bI * NHEAD + h;
                float v0 = acc[i][j][0] + bias[n_g];
                float v1 = acc[i][j][1] + bias[n_g + 1];
                float v2 = acc[i][j][2] + bias[n_g];
                float v3 = acc[i][j][3] + bias[n_g + 1];
                if (which == 0) {
                    v0 *= QSCALE; v1 *= QSCALE; v2 *= QSCALE; v3 *= QSCALE;
                    const size_t a0 = ((size_t)bh * SEQ + tok) * HDIM + d;
                    *(uint32_t*)(g_q + a0)            = pack_h2(v0, v1);
                    *(uint32_t*)(g_q + a0 + 8 * HDIM) = pack_h2(v2, v3);
                } else if (which == 1) {
                    const size_t a0 = ((size_t)bh * SEQ + tok) * HDIM + d;
                    *(uint32_t*)(g_k + a0)            = pack_h2(v0, v1);
                    *(uint32_t*)(g_k + a0 + 8 * HDIM) = pack_h2(v2, v3);
                } else {
                    // V d-major: [bh][d][tok]
                    const size_t b0 = ((size_t)bh * HDIM + d) * SEQ + tok;
                    g_v[b0]           = __float2half_rn(v0);
                    g_v[b0 + SEQ]     = __float2half_rn(v1);
                    g_v[b0 + 8]       = __float2half_rn(v2);
                    g_v[b0 + SEQ + 8] = __float2half_rn(v3);
                }
            }
        }
    } else {
#pragma unroll
        for (int i = 0; i < 4; ++i) {
#pragma unroll
            for (int j = 0; j < 4; ++j) {
                const int n_g = n0 + nloc0 + 8 * j;
                const int m_g = m0 + mloc0 + 16 * i;
                const float bv0 = bias[n_g], bv1 = bias[n_g + 1];
                float* r0 = outp + (size_t)m_g * DIM + n_g;
                *(float2*)r0 =
                    make_float2(acc[i][j][0] + bv0, acc[i][j][1] + bv1);
                *(float2*)(r0 + 8 * DIM) =
                    make_float2(acc[i][j][2] + bv0, acc[i][j][3] + bv1);
            }
        }
    }
}

// ---------------------------------------------------------------------------
// Flash attention, pure fp16 mma.sync (1 MMA per product).
// CTA: 128 q-rows x one bh; 8 warps. S = Q*K, O += P*V.
// ---------------------------------------------------------------------------
#define AT_SROW 144                       // 64 fp16 + 16B pad
#define AT_QT_B (128 * AT_SROW)           // 18432
#define AT_KT_B (64 * AT_SROW)            // 9216
#define AT_ST_B (2 * AT_KT_B)             // 18432: K, V
#define AT_SMEM (AT_QT_B + 2 * AT_ST_B)   // 55296

__device__ __forceinline__ void load_kv_tile(uint32_t st, int bh, int kt, int tid)
{
    const __half* kh = g_k + ((size_t)bh * SEQ + kt * 64) * HDIM;
    const __half* vh = g_v + (size_t)bh * HDIM * SEQ + kt * 64;
#pragma unroll
    for (int i = 0; i < 2; i++) {
        const int idx = tid + i * 256;    // 0..511
        const int row = idx >> 3, ch = idx & 7;
        const uint32_t so = (uint32_t)(row * AT_SROW + ch * 16);
        CP_ASYNC16(st + so,           kh + (size_t)row * HDIM + ch * 8);
        CP_ASYNC16(st + AT_KT_B + so, vh + (size_t)row * SEQ + ch * 8);
    }
}

__global__ __launch_bounds__(256, 2) void attn_mma_kernel()
{
    extern __shared__ __align__(128) char sm[];
    const uint32_t smb = smem_u32(sm);
    const uint32_t q_s = smb;
    const uint32_t st0 = smb + AT_QT_B;

    const int tid = threadIdx.x;
    const int wid = tid >> 5, lane = tid & 31;
    const int qt = blockIdx.x, bh = blockIdx.y;

    // Load Q tile, 128 rows x 64 fp16
    {
        const __half* qh = g_q + ((size_t)bh * SEQ + qt * 128) * HDIM;
#pragma unroll
        for (int i = 0; i < 4; i++) {
            const int idx = tid + i * 256;     // 0..1023
            const int row = idx >> 3, ch = idx & 7;
            CP_ASYNC16(q_s + (uint32_t)(row * AT_SROW + ch * 16),
                       qh + (size_t)row * HDIM + ch * 8);
        }
        CP_COMMIT();
    }
    load_kv_tile(st0, bh, 0, tid);
    CP_COMMIT();
    CP_WAIT(1);                // Q complete (KV tile 0 may be pending)
    __syncthreads();

    // Q A-fragments, register-resident: 4 ksteps
    uint32_t qf[4][4];
    {
        const uint32_t qa =
            (uint32_t)((wid * 16 + (lane & 15)) * AT_SROW + (lane >> 4) * 16);
#pragma unroll
        for (int t = 0; t < 4; t++) LDSM4(qf[t], q_s + qa + t * 32);
    }

    float m2[2] = {-1e30f, -1e30f}, l[2] = {0.f, 0.f};
    float po[8][4];
#pragma unroll
    for (int j = 0; j < 8; j++)
#pragma unroll
        for (int e = 0; e < 4; e++) po[j][e] = 0.f;

    const uint32_t brow =
        (uint32_t)((lane & 7) * AT_SROW + ((lane >> 3) & 1) * 16);

    for (int kt = 0; kt < SEQ / 64; kt++) {
        if (kt + 1 < SEQ / 64) {
            load_kv_tile(st0 + ((kt + 1) & 1) * AT_ST_B, bh, kt + 1, tid);
            CP_COMMIT();
            CP_WAIT(1);
        } else {
            CP_WAIT(0);
        }
        __syncthreads();

        const uint32_t sk = st0 + (kt & 1) * AT_ST_B;
        const uint32_t sv = sk + AT_KT_B;

        // S = Q K^T, kstep-outer, quad-striped accumulators
        float s[8][4];
#pragma unroll
        for (int j = 0; j < 8; j++)
#pragma unroll
            for (int e = 0; e < 4; e++) s[j][e] = 0.f;

#pragma unroll
        for (int t = 0; t < 4; t++) {
#pragma unroll
            for (int jq = 0; jq < 2; jq++) {
                uint32_t kbh[4][2];
#pragma unroll
                for (int jj = 0; jj < 4; jj++) {
                    const int j = jq * 4 + jj;
                    LDSM2(kbh[jj],
                          sk + (uint32_t)(j * 8 * AT_SROW) + brow + t * 32);
                }
#pragma unroll
                for (int jj = 0; jj < 4; jj++)
                    MMA_F16(s[jq * 4 + jj], qf[t], kbh[jj]);
            }
        }

        // Online softmax (rows r=lane>>2 and r+8; quad holds a row)
        float rmx0 = s[0][0], rmx1 = s[0][2];
#pragma unroll
        for (int j = 0; j < 8; j++) {
            rmx0 = fmaxf(rmx0, fmaxf(s[j][0], s[j][1]));
            rmx1 = fmaxf(rmx1, fmaxf(s[j][2], s[j][3]));
        }
        rmx0 = fmaxf(rmx0, __shfl_xor_sync(0xffffffffu, rmx0, 1));
        rmx0 = fmaxf(rmx0, __shfl_xor_sync(0xffffffffu, rmx0, 2));
        rmx1 = fmaxf(rmx1, __shfl_xor_sync(0xffffffffu, rmx1, 1));
        rmx1 = fmaxf(rmx1, __shfl_xor_sync(0xffffffffu, rmx1, 2));

        const float mn0 = fmaxf(m2[0], rmx0);
        const float mn1 = fmaxf(m2[1], rmx1);
        const float c0 = fast_ex2(m2[0] - mn0);
        const float c1 = fast_ex2(m2[1] - mn1);
        m2[0] = mn0; m2[1] = mn1;

        float rs0 = 0.f, rs1 = 0.f;
#pragma unroll
        for (int j = 0; j < 8; j++) {
            s[j][0] = fast_ex2(s[j][0] - mn0);
            s[j][1] = fast_ex2(s[j][1] - mn0);
            s[j][2] = fast_ex2(s[j][2] - mn1);
            s[j][3] = fast_ex2(s[j][3] - mn1);
            rs0 += s[j][0] + s[j][1];
            rs1 += s[j][2] + s[j][3];
        }
        rs0 += __shfl_xor_sync(0xffffffffu, rs0, 1);
        rs0 += __shfl_xor_sync(0xffffffffu, rs0, 2);
        rs1 += __shfl_xor_sync(0xffffffffu, rs1, 1);
        rs1 += __shfl_xor_sync(0xffffffffu, rs1, 2);
        l[0] = l[0] * c0 + rs0;
        l[1] = l[1] * c1 + rs1;
#pragma unroll
        for (int j = 0; j < 8; j++) {
            po[j][0] *= c0; po[j][1] *= c0;
            po[j][2] *= c1; po[j][3] *= c1;
        }

        // O += P V : P fp16 (accumulator frag == A frag)
#pragma unroll
        for (int t = 0; t < 4; t++) {
            uint32_t ph[4];
            ph[0] = pack_h2(s[2 * t][0],     s[2 * t][1]);
            ph[1] = pack_h2(s[2 * t][2],     s[2 * t][3]);
            ph[2] = pack_h2(s[2 * t + 1][0], s[2 * t + 1][1]);
            ph[3] = pack_h2(s[2 * t + 1][2], s[2 * t + 1][3]);
#pragma unroll
            for (int jq = 0; jq < 2; jq++) {
                uint32_t vbh[4][2];
#pragma unroll
                for (int jj = 0; jj < 4; jj++) {
                    const int j = jq * 4 + jj;
                    LDSM2(vbh[jj],
                          sv + (uint32_t)(j * 8 * AT_SROW) + brow + t * 32);
                }
#pragma unroll
                for (int jj = 0; jj < 4; jj++)
                    MMA_F16(po[jq * 4 + jj], ph, vbh[jj]);
            }
        }
        __syncthreads();
    }

    // Epilogue: O/l -> fp16 hi/lo [tok][h*64+d]
    const int h = bh & 15, bb = bh >> 4;
    const int tok0 = qt * 128 + wid * 16 + (lane >> 2);
    const float inv0 = 1.f / l[0], inv1 = 1.f / l[1];
#pragma unroll
    for (int j = 0; j < 8; j++) {
        const int d = h * HDIM + j * 8 + (lane & 3) * 2;
        const size_t a0 = ((size_t)(bb * SEQ + tok0)) * DIM + d;
        const size_t a1 = a0 + (size_t)8 * DIM;
        const float v0 = po[j][0] * inv0, v1 = po[j][1] * inv0;
        const float v2 = po[j][2] * inv1, v3 = po[j][3] * inv1;
        uint32_t h2 = pack_h2(v0, v1);
        *(uint32_t*)(g_ohi + a0) = h2;
        *(uint32_t*)(g_olo + a0) = pack_l2(v0, v1, h2);
        h2 = pack_h2(v2, v3);
        *(uint32_t*)(g_ohi + a1) = h2;
        *(uint32_t*)(g_olo + a1) = pack_l2(v2, v3, h2);
    }
}

// ---------------------------------------------------------------------------

extern "C" void kernel_launch(void* const* d_in, const int* in_sizes, int n_in,
                              void* d_out, int out_size)
{
    const float* x      = (const float*)d_in[0];
    const float* w_qkv  = (const float*)d_in[1];
    const float* b_qkv  = (const float*)d_in[2];
    const float* w_proj = (const float*)d_in[3];
    const float* b_proj = (const float*)d_in[4];
    float* out = (float*)d_out;

    __half *h_xh, *h_wqh, *h_wph, *h_ohi, *h_olo;
    cudaGetSymbolAddress((void**)&h_xh,  g_xh);
    cudaGetSymbolAddress((void**)&h_wqh, g_wqh);
    cudaGetSymbolAddress((void**)&h_wph, g_wph);
    cudaGetSymbolAddress((void**)&h_ohi, g_ohi);
    cudaGetSymbolAddress((void**)&h_olo, g_olo);

    cudaFuncSetAttribute(gemm_fp16_kernel<0>,
                         cudaFuncAttributeMaxDynamicSharedMemorySize,
                         2 * 2 * TILE_B);
    cudaFuncSetAttribute(gemm_fp16_kernel<1>,
                         cudaFuncAttributeMaxDynamicSharedMemorySize,
                         2 * 3 * TILE_B);
    cudaFuncSetAttribute(attn_mma_kernel,
                         cudaFuncAttributeMaxDynamicSharedMemorySize,
                         AT_SMEM);

    // 1. Convert inputs/weights to fp16
    cvt_h_kernel<<<(M_TOK * DIM / 4 + 255) / 256, 256>>>(
        x, h_xh, M_TOK * DIM / 4);
    cvt_h_kernel<<<(3 * DIM * DIM / 4 + 255) / 256, 256>>>(
        w_qkv, h_wqh, 3 * DIM * DIM / 4);
    cvt_h_kernel<<<(DIM * DIM / 4 + 255) / 256, 256>>>(
        w_proj, h_wph, DIM * DIM / 4);

    // 2. QKV GEMM (1 MMA/product) -> fp16 Q / K / V in attention layouts
    dim3 gq(3 * DIM / 128, M_TOK / 128);
    gemm_fp16_kernel<0><<<gq, 256, 2 * 2 * TILE_B>>>(
        h_xh, nullptr, h_wqh, b_qkv, nullptr, 0);

    // 3. Tensor-core flash attention -> g_ohi/g_olo
    dim3 ga(SEQ / 128, NBH);
    attn_mma_kernel<<<ga, 256, AT_SMEM>>>();

    // 4. Projection GEMM (2 MMA/product, A split): M=4096, N=1024
    dim3 gp(DIM / 128, M_TOK / 128);
    gemm_fp16_kernel<1><<<gp, 256, 2 * 3 * TILE_B>>>(
        h_ohi, h_olo, h_wph, b_proj, out, 1);
}

// round 14
// speedup vs baseline: 11.7074x; 1.1503x over previous
#include <cuda_runtime.h>
#include <cuda_fp16.h>
#include <cstdint>

// Problem constants
#define BATCH 2
#define SEQ   2048
#define DIM   1024
#define NHEAD 16
#define HDIM  64
// SCALE * log2(e): fold into Q so QK^T scores are already in base-2 domain
#define QSCALE (0.125f * 1.4426950408889634f)

#define M_TOK (BATCH * SEQ)          // 4096 rows of tokens
#define NBH   (BATCH * NHEAD)        // 32

// ---------------------------------------------------------------------------
// Scratch (device globals: allocation-free rule)   — fp16 everywhere
// ---------------------------------------------------------------------------
__device__ __half g_q[NBH * SEQ * HDIM];     // [bh][tok][64], QSCALE folded
__device__ __half g_k[NBH * SEQ * HDIM];     // [bh][tok][64]
__device__ __half g_v[NBH * HDIM * SEQ];     // [bh][d][tok] d-major
__device__ __half g_ohi[M_TOK * DIM];        // attn out hi/lo [b*n][h*64+d]
__device__ __half g_olo[M_TOK * DIM];
__device__ __half g_xh[M_TOK * DIM];
__device__ __half g_wqh[3 * DIM * DIM];
__device__ __half g_wph[DIM * DIM];

// ---------------------------------------------------------------------------
// PTX helpers
// ---------------------------------------------------------------------------
__device__ __forceinline__ uint32_t smem_u32(const void* p) {
    uint32_t a;
    asm("{ .reg .u64 t; cvta.to.shared.u64 t, %1; cvt.u32.u64 %0, t; }"
        : "=r"(a) : "l"(p));
    return a;
}

#define CP_ASYNC16(dst, src) \
    asm volatile("cp.async.cg.shared.global [%0], [%1], 16;" \
        :: "r"(dst), "l"(src))
#define CP_COMMIT() asm volatile("cp.async.commit_group;" ::: "memory")
#define CP_WAIT(n)  asm volatile("cp.async.wait_group %0;" :: "n"(n) : "memory")

#define LDSM4(r, addr) \
    asm volatile("ldmatrix.sync.aligned.m8n8.x4.shared.b16 {%0,%1,%2,%3}, [%4];" \
        : "=r"((r)[0]), "=r"((r)[1]), "=r"((r)[2]), "=r"((r)[3]) : "r"(addr))

#define MMA_F16(d, a, b) \
    asm volatile("mma.sync.aligned.m16n8k16.row.col.f32.f16.f16.f32 " \
        "{%0,%1,%2,%3}, {%4,%5,%6,%7}, {%8,%9}, {%0,%1,%2,%3};" \
        : "+f"((d)[0]), "+f"((d)[1]), "+f"((d)[2]), "+f"((d)[3]) \
        : "r"((a)[0]), "r"((a)[1]), "r"((a)[2]), "r"((a)[3]), \
          "r"((b)[0]), "r"((b)[1]))

// fast 2^y for y <= 0 (FMA/ALU pipes, no MUFU)
__device__ __forceinline__ float fast_ex2(float y) {
    y = fmaxf(y, -120.f);
    const float z = y + 12582912.f;              // 1.5 * 2^23
    const float r = y - (z - 12582912.f);
    const uint32_t fb = (__float_as_uint(z) + 0xB4C0007Fu) << 23;  // 2^n
    float p = 0.0013333558f;
    p = fmaf(p, r, 0.0096181291f);
    p = fmaf(p, r, 0.0555041087f);
    p = fmaf(p, r, 0.2402265069f);
    p = fmaf(p, r, 0.6931471806f);
    p = fmaf(p, r, 1.0f);
    return __uint_as_float(fb) * p;
}

__device__ __forceinline__ uint32_t pack_h2(float x, float y) {
    __half2 h = __floats2half2_rn(x, y);
    return *(uint32_t*)&h;
}
__device__ __forceinline__ uint32_t pack_l2(float x, float y, uint32_t h2) {
    __half2 h = *(__half2*)&h2;
    __half2 l = __floats2half2_rn(x - __half2float(h.x),
                                  y - __half2float(h.y));
    return *(uint32_t*)&l;
}

// ---------------------------------------------------------------------------
// Single merged fp32->fp16 converter for x, w_qkv, w_proj (one launch)
// ---------------------------------------------------------------------------
#define NX4 (M_TOK * DIM / 4)            // 1048576
#define WQ4 (3 * DIM * DIM / 4)          // 786432
#define WP4 (DIM * DIM / 4)              // 262144

__global__ __launch_bounds__(256) void cvt_all_kernel(
    const float* __restrict__ x, const float* __restrict__ wq,
    const float* __restrict__ wp)
{
    const int i = blockIdx.x * blockDim.x + threadIdx.x;
    const float* src;
    __half* dst;
    int off;
    if (i < NX4)            { src = x;  dst = g_xh;  off = i; }
    else if (i < NX4 + WQ4) { src = wq; dst = g_wqh; off = i - NX4; }
    else                    { src = wp; dst = g_wph; off = i - NX4 - WQ4; }
    const float4 v = ((const float4*)src)[off];
    ((uint32_t*)dst)[2 * off]     = pack_h2(v.x, v.y);
    ((uint32_t*)dst)[2 * off + 1] = pack_h2(v.z, v.w);
}

// ---------------------------------------------------------------------------
// mma.sync fp16 GEMM: D[m,n] = sum_k A[m,k]*B[n,k] + bias[n]
// SPLIT=1: A = Ah + Al (2 MMAs); SPLIT=0: A = Ah (1 MMA).
// CTA 128x128, BK=64 (one syncthreads per 64 k), 8 warps, cp.async 2-stage.
// B fragments loaded as LDSM4 pairs.
// ---------------------------------------------------------------------------
#define BK 64
#define SROW 144                    // 64 fp16 + 16B pad
#define TILE_B (128 * SROW)         // 18432
#define NCHUNK (DIM / BK)           // 16

template <int SPLIT>
__device__ __forceinline__ void stage_load(
    char* stage,
    const __half* __restrict__ Ah, const __half* __restrict__ Al,
    const __half* __restrict__ Bh, int k0, int tid)
{
    constexpr uint32_t BOFF = (SPLIT ? 2u : 1u) * TILE_B;
    const uint32_t d0 = smem_u32(stage);
#pragma unroll
    for (int i = 0; i < 4; ++i) {
        const int idx = tid + i * 256;          // 0..1023
        const int row = idx >> 3, ch = idx & 7;
        const uint32_t doff = (uint32_t)(row * SROW + ch * 16);
        const size_t goff = (size_t)row * DIM + k0 + ch * 8;
        CP_ASYNC16(d0 + doff,        Ah + goff);
        if (SPLIT) CP_ASYNC16(d0 + TILE_B + doff, Al + goff);
        CP_ASYNC16(d0 + BOFF + doff, Bh + goff);
    }
}

template <int SPLIT>
__global__ __launch_bounds__(256, 2) void gemm_fp16_kernel(
    const __half* __restrict__ Ahi, const __half* __restrict__ Alo,
    const __half* __restrict__ Bhs,
    const float* __restrict__ bias, float* __restrict__ outp, int mode)
{
    constexpr uint32_t STAGE_B = (SPLIT ? 3u : 2u) * TILE_B;
    constexpr uint32_t BOFF    = (SPLIT ? 2u : 1u) * TILE_B;

    extern __shared__ __align__(128) char smd[];
    const uint32_t smb = smem_u32(smd);

    const int tid  = threadIdx.x;
    const int wid  = tid >> 5;
    const int lane = tid & 31;
    const int m0 = blockIdx.y * 128;
    const int n0 = blockIdx.x * 128;

    const int wm = (wid >> 2) * 64;
    const int wn = (wid & 3) * 32;

    const __half* Ah = Ahi + (size_t)m0 * DIM;
    const __half* Al = SPLIT ? (Alo + (size_t)m0 * DIM) : Ahi;
    const __half* Bh = Bhs + (size_t)n0 * DIM;

    float acc[4][4][4];
#pragma unroll
    for (int i = 0; i < 4; i++)
#pragma unroll
        for (int j = 0; j < 4; j++)
#pragma unroll
            for (int e = 0; e < 4; e++) acc[i][j][e] = 0.f;

    // A LDSM4 address components
    const uint32_t a_row  = (uint32_t)(wm + (lane & 15));
    const uint32_t a_coff = (uint32_t)((lane >> 4) * 16);
    // B LDSM4-pair address components: lanes 0-15 -> rows +0..7 (klo/khi),
    // lanes 16-31 -> rows +8..15
    const uint32_t b4_row  = (uint32_t)(wn + ((lane >> 4) << 3) + (lane & 7));
    const uint32_t b4_coff = (uint32_t)(((lane >> 3) & 1) * 16);

    stage_load<SPLIT>(smd, Ah, Al, Bh, 0, tid);
    CP_COMMIT();

    for (int c = 0; c < NCHUNK; ++c) {
        if (c + 1 < NCHUNK) {
            stage_load<SPLIT>(smd + ((c + 1) & 1) * STAGE_B, Ah, Al, Bh,
                              (c + 1) * BK, tid);
            CP_COMMIT();
            CP_WAIT(1);
        } else {
            CP_WAIT(0);
        }
        __syncthreads();

        const uint32_t sb = smb + (c & 1) * STAGE_B;
#pragma unroll
        for (int ks = 0; ks < 4; ++ks) {
            // B: 2x LDSM4 -> 4 n8k16 fragments (bf[2j], bf[2j+1])
            uint32_t bf[8];
#pragma unroll
            for (int p = 0; p < 2; ++p) {
                LDSM4(bf + 4 * p,
                      sb + BOFF + (b4_row + 16 * p) * SROW + ks * 32 + b4_coff);
            }
#pragma unroll
            for (int i = 0; i < 4; ++i) {
                uint32_t ahf[4];
                const uint32_t aa =
                    sb + (a_row + 16 * i) * SROW + ks * 32 + a_coff;
                LDSM4(ahf, aa);
#pragma unroll
                for (int j = 0; j < 4; ++j)
                    MMA_F16(acc[i][j], ahf, &bf[2 * j]);
                if (SPLIT) {
                    uint32_t alf[4];
                    LDSM4(alf, aa + TILE_B);
#pragma unroll
                    for (int j = 0; j < 4; ++j)
                        MMA_F16(acc[i][j], alf, &bf[2 * j]);
                }
            }
        }
        __syncthreads();
    }

    // Epilogue. acc map: c0:(m,n) c1:(m,n+1) c2:(m+8,n) c3:(m+8,n+1)
    const int mloc0 = wm + (lane >> 2);
    const int nloc0 = wn + (lane & 3) * 2;

    if (mode == 0) {
        const int which = n0 >> 10;          // 0=Q 1=K 2=V (CTA-uniform)
        const int bI    = m0 >> 11;
        const int tokb  = m0 & 2047;
#pragma unroll
        for (int i = 0; i < 4; ++i) {
#pragma unroll
            for (int j = 0; j < 4; ++j) {
                const int n_g = n0 + nloc0 + 8 * j;
                const int tok = tokb + mloc0 + 16 * i;
                const int h = (n_g & 1023) >> 6;
                const int d = n_g & 63;
                const int bh = bI * NHEAD + h;
                float v0 = acc[i][j][0] + bias[n_g];
                float v1 = acc[i][j][1] + bias[n_g + 1];
                float v2 = acc[i][j][2] + bias[n_g];
                float v3 = acc[i][j][3] + bias[n_g + 1];
                if (which == 0) {
                    v0 *= QSCALE; v1 *= QSCALE; v2 *= QSCALE; v3 *= QSCALE;
                    const size_t a0 = ((size_t)bh * SEQ + tok) * HDIM + d;
                    *(uint32_t*)(g_q + a0)            = pack_h2(v0, v1);
                    *(uint32_t*)(g_q + a0 + 8 * HDIM) = pack_h2(v2, v3);
                } else if (which == 1) {
                    const size_t a0 = ((size_t)bh * SEQ + tok) * HDIM + d;
                    *(uint32_t*)(g_k + a0)            = pack_h2(v0, v1);
                    *(uint32_t*)(g_k + a0 + 8 * HDIM) = pack_h2(v2, v3);
                } else {
                    // V d-major: [bh][d][tok]
                    const size_t b0 = ((size_t)bh * HDIM + d) * SEQ + tok;
                    g_v[b0]           = __float2half_rn(v0);
                    g_v[b0 + SEQ]     = __float2half_rn(v1);
                    g_v[b0 + 8]       = __float2half_rn(v2);
                    g_v[b0 + SEQ + 8] = __float2half_rn(v3);
                }
            }
        }
    } else {
#pragma unroll
        for (int i = 0; i < 4; ++i) {
#pragma unroll
            for (int j = 0; j < 4; ++j) {
                const int n_g = n0 + nloc0 + 8 * j;
                const int m_g = m0 + mloc0 + 16 * i;
                const float bv0 = bias[n_g], bv1 = bias[n_g + 1];
                float* r0 = outp + (size_t)m_g * DIM + n_g;
                *(float2*)r0 =
                    make_float2(acc[i][j][0] + bv0, acc[i][j][1] + bv1);
                *(float2*)(r0 + 8 * DIM) =
                    make_float2(acc[i][j][2] + bv0, acc[i][j][3] + bv1);
            }
        }
    }
}

// ---------------------------------------------------------------------------
// Flash attention, pure fp16 mma.sync. B fragments via LDSM4 pairs.
// CTA: 128 q-rows x one bh; 8 warps. S = Q*K, O += P*V.
// ---------------------------------------------------------------------------
#define AT_SROW 144                       // 64 fp16 + 16B pad
#define AT_QT_B (128 * AT_SROW)           // 18432
#define AT_KT_B (64 * AT_SROW)            // 9216
#define AT_ST_B (2 * AT_KT_B)             // 18432: K, V
#define AT_SMEM (AT_QT_B + 2 * AT_ST_B)   // 55296

__device__ __forceinline__ void load_kv_tile(uint32_t st, int bh, int kt, int tid)
{
    const __half* kh = g_k + ((size_t)bh * SEQ + kt * 64) * HDIM;
    const __half* vh = g_v + (size_t)bh * HDIM * SEQ + kt * 64;
#pragma unroll
    for (int i = 0; i < 2; i++) {
        const int idx = tid + i * 256;    // 0..511
        const int row = idx >> 3, ch = idx & 7;
        const uint32_t so = (uint32_t)(row * AT_SROW + ch * 16);
        CP_ASYNC16(st + so,           kh + (size_t)row * HDIM + ch * 8);
        CP_ASYNC16(st + AT_KT_B + so, vh + (size_t)row * SEQ + ch * 8);
    }
}

__global__ __launch_bounds__(256, 2) void attn_mma_kernel()
{
    extern __shared__ __align__(128) char sm[];
    const uint32_t smb = smem_u32(sm);
    const uint32_t q_s = smb;
    const uint32_t st0 = smb + AT_QT_B;

    const int tid = threadIdx.x;
    const int wid = tid >> 5, lane = tid & 31;
    const int qt = blockIdx.x, bh = blockIdx.y;

    // Load Q tile, 128 rows x 64 fp16
    {
        const __half* qh = g_q + ((size_t)bh * SEQ + qt * 128) * HDIM;
#pragma unroll
        for (int i = 0; i < 4; i++) {
            const int idx = tid + i * 256;     // 0..1023
            const int row = idx >> 3, ch = idx & 7;
            CP_ASYNC16(q_s + (uint32_t)(row * AT_SROW + ch * 16),
                       qh + (size_t)row * HDIM + ch * 8);
        }
        CP_COMMIT();
    }
    load_kv_tile(st0, bh, 0, tid);
    CP_COMMIT();
    CP_WAIT(1);                // Q complete (KV tile 0 may be pending)
    __syncthreads();

    // Q A-fragments, register-resident: 4 ksteps
    uint32_t qf[4][4];
    {
        const uint32_t qa =
            (uint32_t)((wid * 16 + (lane & 15)) * AT_SROW + (lane >> 4) * 16);
#pragma unroll
        for (int t = 0; t < 4; t++) LDSM4(qf[t], q_s + qa + t * 32);
    }

    float m2[2] = {-1e30f, -1e30f}, l[2] = {0.f, 0.f};
    float po[8][4];
#pragma unroll
    for (int j = 0; j < 8; j++)
#pragma unroll
        for (int e = 0; e < 4; e++) po[j][e] = 0.f;

    // LDSM4-pair address components for K/V B-fragments
    const uint32_t b4_row  = (uint32_t)(((lane >> 4) << 3) + (lane & 7));
    const uint32_t b4_coff = (uint32_t)(((lane >> 3) & 1) * 16);

    for (int kt = 0; kt < SEQ / 64; kt++) {
        if (kt + 1 < SEQ / 64) {
            load_kv_tile(st0 + ((kt + 1) & 1) * AT_ST_B, bh, kt + 1, tid);
            CP_COMMIT();
            CP_WAIT(1);
        } else {
            CP_WAIT(0);
        }
        __syncthreads();

        const uint32_t sk = st0 + (kt & 1) * AT_ST_B;
        const uint32_t sv = sk + AT_KT_B;

        // S = Q K^T, kstep-outer, quad-striped accumulators
        float s[8][4];
#pragma unroll
        for (int j = 0; j < 8; j++)
#pragma unroll
            for (int e = 0; e < 4; e++) s[j][e] = 0.f;

#pragma unroll
        for (int t = 0; t < 4; t++) {
#pragma unroll
            for (int jq = 0; jq < 2; jq++) {
                uint32_t kf[8];
#pragma unroll
                for (int p = 0; p < 2; ++p) {
                    LDSM4(kf + 4 * p,
                          sk + (uint32_t)((jq * 32 + p * 16 + b4_row) * AT_SROW)
                             + b4_coff + t * 32);
                }
#pragma unroll
                for (int jj = 0; jj < 4; jj++)
                    MMA_F16(s[jq * 4 + jj], qf[t], &kf[2 * jj]);
            }
        }

        // Online softmax (rows r=lane>>2 and r+8; quad holds a row)
        float rmx0 = s[0][0], rmx1 = s[0][2];
#pragma unroll
        for (int j = 0; j < 8; j++) {
            rmx0 = fmaxf(rmx0, fmaxf(s[j][0], s[j][1]));
            rmx1 = fmaxf(rmx1, fmaxf(s[j][2], s[j][3]));
        }
        rmx0 = fmaxf(rmx0, __shfl_xor_sync(0xffffffffu, rmx0, 1));
        rmx0 = fmaxf(rmx0, __shfl_xor_sync(0xffffffffu, rmx0, 2));
        rmx1 = fmaxf(rmx1, __shfl_xor_sync(0xffffffffu, rmx1, 1));
        rmx1 = fmaxf(rmx1, __shfl_xor_sync(0xffffffffu, rmx1, 2));

        const float mn0 = fmaxf(m2[0], rmx0);
        const float mn1 = fmaxf(m2[1], rmx1);
        const float c0 = fast_ex2(m2[0] - mn0);
        const float c1 = fast_ex2(m2[1] - mn1);
        m2[0] = mn0; m2[1] = mn1;

        float rs0 = 0.f, rs1 = 0.f;
#pragma unroll
        for (int j = 0; j < 8; j++) {
            s[j][0] = fast_ex2(s[j][0] - mn0);
            s[j][1] = fast_ex2(s[j][1] - mn0);
            s[j][2] = fast_ex2(s[j][2] - mn1);
            s[j][3] = fast_ex2(s[j][3] - mn1);
            rs0 += s[j][0] + s[j][1];
            rs1 += s[j][2] + s[j][3];
        }
        rs0 += __shfl_xor_sync(0xffffffffu, rs0, 1);
        rs0 += __shfl_xor_sync(0xffffffffu, rs0, 2);
        rs1 += __shfl_xor_sync(0xffffffffu, rs1, 1);
        rs1 += __shfl_xor_sync(0xffffffffu, rs1, 2);
        l[0] = l[0] * c0 + rs0;
        l[1] = l[1] * c1 + rs1;
#pragma unroll
        for (int j = 0; j < 8; j++) {
            po[j][0] *= c0; po[j][1] *= c0;
            po[j][2] *= c1; po[j][3] *= c1;
        }

        // O += P V : P fp16 (accumulator frag == A frag)
#pragma unroll
        for (int t = 0; t < 4; t++) {
            uint32_t ph[4];
            ph[0] = pack_h2(s[2 * t][0],     s[2 * t][1]);
            ph[1] = pack_h2(s[2 * t][2],     s[2 * t][3]);
            ph[2] = pack_h2(s[2 * t + 1][0], s[2 * t + 1][1]);
            ph[3] = pack_h2(s[2 * t + 1][2], s[2 * t + 1][3]);
#pragma unroll
            for (int jq = 0; jq < 2; jq++) {
                uint32_t vf[8];
#pragma unroll
                for (int p = 0; p < 2; ++p) {
                    LDSM4(vf + 4 * p,
                          sv + (uint32_t)((jq * 32 + p * 16 + b4_row) * AT_SROW)
                             + b4_coff + t * 32);
                }
#pragma unroll
                for (int jj = 0; jj < 4; jj++)
                    MMA_F16(po[jq * 4 + jj], ph, &vf[2 * jj]);
            }
        }
        __syncthreads();
    }

    // Epilogue: O/l -> fp16 hi/lo [tok][h*64+d]
    const int h = bh & 15, bb = bh >> 4;
    const int tok0 = qt * 128 + wid * 16 + (lane >> 2);
    const float inv0 = 1.f / l[0], inv1 = 1.f / l[1];
#pragma unroll
    for (int j = 0; j < 8; j++) {
        const int d = h * HDIM + j * 8 + (lane & 3) * 2;
        const size_t a0 = ((size_t)(bb * SEQ + tok0)) * DIM + d;
        const size_t a1 = a0 + (size_t)8 * DIM;
        const float v0 = po[j][0] * inv0, v1 = po[j][1] * inv0;
        const float v2 = po[j][2] * inv1, v3 = po[j][3] * inv1;
        uint32_t h2 = pack_h2(v0, v1);
        *(uint32_t*)(g_ohi + a0) = h2;
        *(uint32_t*)(g_olo + a0) = pack_l2(v0, v1, h2);
        h2 = pack_h2(v2, v3);
        *(uint32_t*)(g_ohi + a1) = h2;
        *(uint32_t*)(g_olo + a1) = pack_l2(v2, v3, h2);
    }
}

// ---------------------------------------------------------------------------

extern "C" void kernel_launch(void* const* d_in, const int* in_sizes, int n_in,
                              void* d_out, int out_size)
{
    const float* x      = (const float*)d_in[0];
    const float* w_qkv  = (const float*)d_in[1];
    const float* b_qkv  = (const float*)d_in[2];
    const float* w_proj = (const float*)d_in[3];
    const float* b_proj = (const float*)d_in[4];
    float* out = (float*)d_out;

    __half *h_xh, *h_wqh, *h_wph, *h_ohi, *h_olo;
    cudaGetSymbolAddress((void**)&h_xh,  g_xh);
    cudaGetSymbolAddress((void**)&h_wqh, g_wqh);
    cudaGetSymbolAddress((void**)&h_wph, g_wph);
    cudaGetSymbolAddress((void**)&h_ohi, g_ohi);
    cudaGetSymbolAddress((void**)&h_olo, g_olo);

    cudaFuncSetAttribute(gemm_fp16_kernel<0>,
                         cudaFuncAttributeMaxDynamicSharedMemorySize,
                         2 * 2 * TILE_B);
    cudaFuncSetAttribute(gemm_fp16_kernel<1>,
                         cudaFuncAttributeMaxDynamicSharedMemorySize,
                         2 * 3 * TILE_B);
    cudaFuncSetAttribute(attn_mma_kernel,
                         cudaFuncAttributeMaxDynamicSharedMemorySize,
                         AT_SMEM);

    // 1. Convert x + weights to fp16 (single launch)
    cvt_all_kernel<<<(NX4 + WQ4 + WP4 + 255) / 256, 256>>>(x, w_qkv, w_proj);

    // 2. QKV GEMM (1 MMA/product) -> fp16 Q / K / V in attention layouts
    dim3 gq(3 * DIM / 128, M_TOK / 128);
    gemm_fp16_kernel<0><<<gq, 256, 2 * 2 * TILE_B>>>(
        h_xh, nullptr, h_wqh, b_qkv, nullptr, 0);

    // 3. Tensor-core flash attention -> g_ohi/g_olo
    dim3 ga(SEQ / 128, NBH);
    attn_mma_kernel<<<ga, 256, AT_SMEM>>>();

    // 4. Projection GEMM (2 MMA/product, A split): M=4096, N=1024
    dim3 gp(DIM / 128, M_TOK / 128);
    gemm_fp16_kernel<1><<<gp, 256, 2 * 3 * TILE_B>>>(
        h_ohi, h_olo, h_wph, b_proj, out, 1);
}

// round 15
// speedup vs baseline: 11.7120x; 1.0004x over previous
#include <cuda_runtime.h>
#include <cuda_fp16.h>
#include <cstdint>

// Problem constants
#define BATCH 2
#define SEQ   2048
#define DIM   1024
#define NHEAD 16
#define HDIM  64
// SCALE * log2(e): fold into Q so QK^T scores are already in base-2 domain
#define QSCALE (0.125f * 1.4426950408889634f)

#define M_TOK (BATCH * SEQ)          // 4096 rows of tokens
#define NBH   (BATCH * NHEAD)        // 32

// ---------------------------------------------------------------------------
// Scratch (device globals: allocation-free rule)   — fp16 everywhere
// ---------------------------------------------------------------------------
__device__ __half g_q[NBH * SEQ * HDIM];     // [bh][tok][64], QSCALE folded
__device__ __half g_k[NBH * SEQ * HDIM];     // [bh][tok][64]
__device__ __half g_v[NBH * HDIM * SEQ];     // [bh][d][tok] d-major
__device__ __half g_ohi[M_TOK * DIM];        // attn out hi/lo [b*n][h*64+d]
__device__ __half g_olo[M_TOK * DIM];
__device__ __half g_xh[M_TOK * DIM];
__device__ __half g_wqh[3 * DIM * DIM];
__device__ __half g_wph[DIM * DIM];

// ---------------------------------------------------------------------------
// PTX helpers
// ---------------------------------------------------------------------------
__device__ __forceinline__ uint32_t smem_u32(const void* p) {
    uint32_t a;
    asm("{ .reg .u64 t; cvta.to.shared.u64 t, %1; cvt.u32.u64 %0, t; }"
        : "=r"(a) : "l"(p));
    return a;
}

#define CP_ASYNC16(dst, src) \
    asm volatile("cp.async.cg.shared.global [%0], [%1], 16;" \
        :: "r"(dst), "l"(src))
#define CP_COMMIT() asm volatile("cp.async.commit_group;" ::: "memory")
#define CP_WAIT(n)  asm volatile("cp.async.wait_group %0;" :: "n"(n) : "memory")

#define LDSM4(r, addr) \
    asm volatile("ldmatrix.sync.aligned.m8n8.x4.shared.b16 {%0,%1,%2,%3}, [%4];" \
        : "=r"((r)[0]), "=r"((r)[1]), "=r"((r)[2]), "=r"((r)[3]) : "r"(addr))

#define MMA_F16(d, a, b) \
    asm volatile("mma.sync.aligned.m16n8k16.row.col.f32.f16.f16.f32 " \
        "{%0,%1,%2,%3}, {%4,%5,%6,%7}, {%8,%9}, {%0,%1,%2,%3};" \
        : "+f"((d)[0]), "+f"((d)[1]), "+f"((d)[2]), "+f"((d)[3]) \
        : "r"((a)[0]), "r"((a)[1]), "r"((a)[2]), "r"((a)[3]), \
          "r"((b)[0]), "r"((b)[1]))

// fast 2^y for y <= 0 (FMA/ALU pipes, no MUFU)
__device__ __forceinline__ float fast_ex2(float y) {
    y = fmaxf(y, -120.f);
    const float z = y + 12582912.f;              // 1.5 * 2^23
    const float r = y - (z - 12582912.f);
    const uint32_t fb = (__float_as_uint(z) + 0xB4C0007Fu) << 23;  // 2^n
    float p = 0.0013333558f;
    p = fmaf(p, r, 0.0096181291f);
    p = fmaf(p, r, 0.0555041087f);
    p = fmaf(p, r, 0.2402265069f);
    p = fmaf(p, r, 0.6931471806f);
    p = fmaf(p, r, 1.0f);
    return __uint_as_float(fb) * p;
}

__device__ __forceinline__ uint32_t pack_h2(float x, float y) {
    __half2 h = __floats2half2_rn(x, y);
    return *(uint32_t*)&h;
}
__device__ __forceinline__ uint32_t pack_l2(float x, float y, uint32_t h2) {
    __half2 h = *(__half2*)&h2;
    __half2 l = __floats2half2_rn(x - __half2float(h.x),
                                  y - __half2float(h.y));
    return *(uint32_t*)&l;
}

// ---------------------------------------------------------------------------
// Single merged fp32->fp16 converter for x, w_qkv, w_proj (one launch)
// ---------------------------------------------------------------------------
#define NX4 (M_TOK * DIM / 4)            // 1048576
#define WQ4 (3 * DIM * DIM / 4)          // 786432
#define WP4 (DIM * DIM / 4)              // 262144

__global__ __launch_bounds__(256) void cvt_all_kernel(
    const float* __restrict__ x, const float* __restrict__ wq,
    const float* __restrict__ wp)
{
    const int i = blockIdx.x * blockDim.x + threadIdx.x;
    const float* src;
    __half* dst;
    int off;
    if (i < NX4)            { src = x;  dst = g_xh;  off = i; }
    else if (i < NX4 + WQ4) { src = wq; dst = g_wqh; off = i - NX4; }
    else                    { src = wp; dst = g_wph; off = i - NX4 - WQ4; }
    const float4 v = ((const float4*)src)[off];
    ((uint32_t*)dst)[2 * off]     = pack_h2(v.x, v.y);
    ((uint32_t*)dst)[2 * off + 1] = pack_h2(v.z, v.w);
}

// ---------------------------------------------------------------------------
// mma.sync fp16 GEMM: D[m,n] = sum_k A[m,k]*B[n,k] + bias[n]
// SPLIT=1: A = Ah + Al (2 MMAs); SPLIT=0: A = Ah (1 MMA).
// CTA 128x128, BK=64 (one syncthreads per 64 k), 8 warps, cp.async 2-stage.
// B fragments loaded as LDSM4 pairs.
// ---------------------------------------------------------------------------
#define BK 64
#define SROW 144                    // 64 fp16 + 16B pad
#define TILE_B (128 * SROW)         // 18432
#define NCHUNK (DIM / BK)           // 16

template <int SPLIT>
__device__ __forceinline__ void stage_load(
    char* stage,
    const __half* __restrict__ Ah, const __half* __restrict__ Al,
    const __half* __restrict__ Bh, int k0, int tid)
{
    constexpr uint32_t BOFF = (SPLIT ? 2u : 1u) * TILE_B;
    const uint32_t d0 = smem_u32(stage);
#pragma unroll
    for (int i = 0; i < 4; ++i) {
        const int idx = tid + i * 256;          // 0..1023
        const int row = idx >> 3, ch = idx & 7;
        const uint32_t doff = (uint32_t)(row * SROW + ch * 16);
        const size_t goff = (size_t)row * DIM + k0 + ch * 8;
        CP_ASYNC16(d0 + doff,        Ah + goff);
        if (SPLIT) CP_ASYNC16(d0 + TILE_B + doff, Al + goff);
        CP_ASYNC16(d0 + BOFF + doff, Bh + goff);
    }
}

template <int SPLIT>
__global__ __launch_bounds__(256, 2) void gemm_fp16_kernel(
    const __half* __restrict__ Ahi, const __half* __restrict__ Alo,
    const __half* __restrict__ Bhs,
    const float* __restrict__ bias, float* __restrict__ outp, int mode)
{
    constexpr uint32_t STAGE_B = (SPLIT ? 3u : 2u) * TILE_B;
    constexpr uint32_t BOFF    = (SPLIT ? 2u : 1u) * TILE_B;

    extern __shared__ __align__(128) char smd[];
    const uint32_t smb = smem_u32(smd);

    const int tid  = threadIdx.x;
    const int wid  = tid >> 5;
    const int lane = tid & 31;
    const int m0 = blockIdx.y * 128;
    const int n0 = blockIdx.x * 128;

    const int wm = (wid >> 2) * 64;
    const int wn = (wid & 3) * 32;

    const __half* Ah = Ahi + (size_t)m0 * DIM;
    const __half* Al = SPLIT ? (Alo + (size_t)m0 * DIM) : Ahi;
    const __half* Bh = Bhs + (size_t)n0 * DIM;

    float acc[4][4][4];
#pragma unroll
    for (int i = 0; i < 4; i++)
#pragma unroll
        for (int j = 0; j < 4; j++)
#pragma unroll
            for (int e = 0; e < 4; e++) acc[i][j][e] = 0.f;

    // A LDSM4 address components
    const uint32_t a_row  = (uint32_t)(wm + (lane & 15));
    const uint32_t a_coff = (uint32_t)((lane >> 4) * 16);
    // B LDSM4-pair address components: lanes 0-15 -> rows +0..7 (klo/khi),
    // lanes 16-31 -> rows +8..15
    const uint32_t b4_row  = (uint32_t)(wn + ((lane >> 4) << 3) + (lane & 7));
    const uint32_t b4_coff = (uint32_t)(((lane >> 3) & 1) * 16);

    stage_load<SPLIT>(smd, Ah, Al, Bh, 0, tid);
    CP_COMMIT();

    for (int c = 0; c < NCHUNK; ++c) {
        if (c + 1 < NCHUNK) {
            stage_load<SPLIT>(smd + ((c + 1) & 1) * STAGE_B, Ah, Al, Bh,
                              (c + 1) * BK, tid);
            CP_COMMIT();
            CP_WAIT(1);
        } else {
            CP_WAIT(0);
        }
        __syncthreads();

        const uint32_t sb = smb + (c & 1) * STAGE_B;
#pragma unroll
        for (int ks = 0; ks < 4; ++ks) {
            // B: 2x LDSM4 -> 4 n8k16 fragments (bf[2j], bf[2j+1])
            uint32_t bf[8];
#pragma unroll
            for (int p = 0; p < 2; ++p) {
                LDSM4(bf + 4 * p,
                      sb + BOFF + (b4_row + 16 * p) * SROW + ks * 32 + b4_coff);
            }
#pragma unroll
            for (int i = 0; i < 4; ++i) {
                uint32_t ahf[4];
                const uint32_t aa =
                    sb + (a_row + 16 * i) * SROW + ks * 32 + a_coff;
                LDSM4(ahf, aa);
#pragma unroll
                for (int j = 0; j < 4; ++j)
                    MMA_F16(acc[i][j], ahf, &bf[2 * j]);
                if (SPLIT) {
                    uint32_t alf[4];
                    LDSM4(alf, aa + TILE_B);
#pragma unroll
                    for (int j = 0; j < 4; ++j)
                        MMA_F16(acc[i][j], alf, &bf[2 * j]);
                }
            }
        }
        __syncthreads();
    }

    // Epilogue. acc map: c0:(m,n) c1:(m,n+1) c2:(m+8,n) c3:(m+8,n+1)
    const int mloc0 = wm + (lane >> 2);
    const int nloc0 = wn + (lane & 3) * 2;

    if (mode == 0) {
        const int which = n0 >> 10;          // 0=Q 1=K 2=V (CTA-uniform)
        const int bI    = m0 >> 11;
        const int tokb  = m0 & 2047;
#pragma unroll
        for (int i = 0; i < 4; ++i) {
#pragma unroll
            for (int j = 0; j < 4; ++j) {
                const int n_g = n0 + nloc0 + 8 * j;
                const int tok = tokb + mloc0 + 16 * i;
                const int h = (n_g & 1023) >> 6;
                const int d = n_g & 63;
                const int bh = bI * NHEAD + h;
                float v0 = acc[i][j][0] + bias[n_g];
                float v1 = acc[i][j][1] + bias[n_g + 1];
                float v2 = acc[i][j][2] + bias[n_g];
                float v3 = acc[i][j][3] + bias[n_g + 1];
                if (which == 0) {
                    v0 *= QSCALE; v1 *= QSCALE; v2 *= QSCALE; v3 *= QSCALE;
                    const size_t a0 = ((size_t)bh * SEQ + tok) * HDIM + d;
                    *(uint32_t*)(g_q + a0)            = pack_h2(v0, v1);
                    *(uint32_t*)(g_q + a0 + 8 * HDIM) = pack_h2(v2, v3);
                } else if (which == 1) {
                    const size_t a0 = ((size_t)bh * SEQ + tok) * HDIM + d;
                    *(uint32_t*)(g_k + a0)            = pack_h2(v0, v1);
                    *(uint32_t*)(g_k + a0 + 8 * HDIM) = pack_h2(v2, v3);
                } else {
                    // V d-major: [bh][d][tok]
                    const size_t b0 = ((size_t)bh * HDIM + d) * SEQ + tok;
                    g_v[b0]           = __float2half_rn(v0);
                    g_v[b0 + SEQ]     = __float2half_rn(v1);
                    g_v[b0 + 8]       = __float2half_rn(v2);
                    g_v[b0 + SEQ + 8] = __float2half_rn(v3);
                }
            }
        }
    } else {
#pragma unroll
        for (int i = 0; i < 4; ++i) {
#pragma unroll
            for (int j = 0; j < 4; ++j) {
                const int n_g = n0 + nloc0 + 8 * j;
                const int m_g = m0 + mloc0 + 16 * i;
                const float bv0 = bias[n_g], bv1 = bias[n_g + 1];
                float* r0 = outp + (size_t)m_g * DIM + n_g;
                *(float2*)r0 =
                    make_float2(acc[i][j][0] + bv0, acc[i][j][1] + bv1);
                *(float2*)(r0 + 8 * DIM) =
                    make_float2(acc[i][j][2] + bv0, acc[i][j][3] + bv1);
            }
        }
    }
}

// ---------------------------------------------------------------------------
// Flash attention, pure fp16 mma.sync. B fragments via LDSM4 pairs.
// CTA: 128 q-rows x one bh; 8 warps. S = Q*K, O += P*V.
// ---------------------------------------------------------------------------
#define AT_SROW 144                       // 64 fp16 + 16B pad
#define AT_QT_B (128 * AT_SROW)           // 18432
#define AT_KT_B (64 * AT_SROW)            // 9216
#define AT_ST_B (2 * AT_KT_B)             // 18432: K, V
#define AT_SMEM (AT_QT_B + 2 * AT_ST_B)   // 55296

__device__ __forceinline__ void load_kv_tile(uint32_t st, int bh, int kt, int tid)
{
    const __half* kh = g_k + ((size_t)bh * SEQ + kt * 64) * HDIM;
    const __half* vh = g_v + (size_t)bh * HDIM * SEQ + kt * 64;
#pragma unroll
    for (int i = 0; i < 2; i++) {
        const int idx = tid + i * 256;    // 0..511
        const int row = idx >> 3, ch = idx & 7;
        const uint32_t so = (uint32_t)(row * AT_SROW + ch * 16);
        CP_ASYNC16(st + so,           kh + (size_t)row * HDIM + ch * 8);
        CP_ASYNC16(st + AT_KT_B + so, vh + (size_t)row * SEQ + ch * 8);
    }
}

__global__ __launch_bounds__(256, 2) void attn_mma_kernel()
{
    extern __shared__ __align__(128) char sm[];
    const uint32_t smb = smem_u32(sm);
    const uint32_t q_s = smb;
    const uint32_t st0 = smb + AT_QT_B;

    const int tid = threadIdx.x;
    const int wid = tid >> 5, lane = tid & 31;
    const int qt = blockIdx.x, bh = blockIdx.y;

    // Load Q tile, 128 rows x 64 fp16
    {
        const __half* qh = g_q + ((size_t)bh * SEQ + qt * 128) * HDIM;
#pragma unroll
        for (int i = 0; i < 4; i++) {
            const int idx = tid + i * 256;     // 0..1023
            const int row = idx >> 3, ch = idx & 7;
            CP_ASYNC16(q_s + (uint32_t)(row * AT_SROW + ch * 16),
                       qh + (size_t)row * HDIM + ch * 8);
        }
        CP_COMMIT();
    }
    load_kv_tile(st0, bh, 0, tid);
    CP_COMMIT();
    CP_WAIT(1);                // Q complete (KV tile 0 may be pending)
    __syncthreads();

    // Q A-fragments, register-resident: 4 ksteps
    uint32_t qf[4][4];
    {
        const uint32_t qa =
            (uint32_t)((wid * 16 + (lane & 15)) * AT_SROW + (lane >> 4) * 16);
#pragma unroll
        for (int t = 0; t < 4; t++) LDSM4(qf[t], q_s + qa + t * 32);
    }

    float m2[2] = {-1e30f, -1e30f}, l[2] = {0.f, 0.f};
    float po[8][4];
#pragma unroll
    for (int j = 0; j < 8; j++)
#pragma unroll
        for (int e = 0; e < 4; e++) po[j][e] = 0.f;

    // LDSM4-pair address components for K/V B-fragments
    const uint32_t b4_row  = (uint32_t)(((lane >> 4) << 3) + (lane & 7));
    const uint32_t b4_coff = (uint32_t)(((lane >> 3) & 1) * 16);

    for (int kt = 0; kt < SEQ / 64; kt++) {
        if (kt + 1 < SEQ / 64) {
            load_kv_tile(st0 + ((kt + 1) & 1) * AT_ST_B, bh, kt + 1, tid);
            CP_COMMIT();
            CP_WAIT(1);
        } else {
            CP_WAIT(0);
        }
        __syncthreads();

        const uint32_t sk = st0 + (kt & 1) * AT_ST_B;
        const uint32_t sv = sk + AT_KT_B;

        // S = Q K^T, kstep-outer, quad-striped accumulators
        float s[8][4];
#pragma unroll
        for (int j = 0; j < 8; j++)
#pragma unroll
            for (int e = 0; e < 4; e++) s[j][e] = 0.f;

#pragma unroll
        for (int t = 0; t < 4; t++) {
#pragma unroll
            for (int jq = 0; jq < 2; jq++) {
                uint32_t kf[8];
#pragma unroll
                for (int p = 0; p < 2; ++p) {
                    LDSM4(kf + 4 * p,
                          sk + (uint32_t)((jq * 32 + p * 16 + b4_row) * AT_SROW)
                             + b4_coff + t * 32);
                }
#pragma unroll
                for (int jj = 0; jj < 4; jj++)
                    MMA_F16(s[jq * 4 + jj], qf[t], &kf[2 * jj]);
            }
        }

        // Online softmax (rows r=lane>>2 and r+8; quad holds a row)
        float rmx0 = s[0][0], rmx1 = s[0][2];
#pragma unroll
        for (int j = 0; j < 8; j++) {
            rmx0 = fmaxf(rmx0, fmaxf(s[j][0], s[j][1]));
            rmx1 = fmaxf(rmx1, fmaxf(s[j][2], s[j][3]));
        }
        rmx0 = fmaxf(rmx0, __shfl_xor_sync(0xffffffffu, rmx0, 1));
        rmx0 = fmaxf(rmx0, __shfl_xor_sync(0xffffffffu, rmx0, 2));
        rmx1 = fmaxf(rmx1, __shfl_xor_sync(0xffffffffu, rmx1, 1));
        rmx1 = fmaxf(rmx1, __shfl_xor_sync(0xffffffffu, rmx1, 2));

        const float mn0 = fmaxf(m2[0], rmx0);
        const float mn1 = fmaxf(m2[1], rmx1);
        const float c0 = fast_ex2(m2[0] - mn0);
        const float c1 = fast_ex2(m2[1] - mn1);
        m2[0] = mn0; m2[1] = mn1;

        float rs0 = 0.f, rs1 = 0.f;
#pragma unroll
        for (int j = 0; j < 8; j++) {
            s[j][0] = fast_ex2(s[j][0] - mn0);
            s[j][1] = fast_ex2(s[j][1] - mn0);
            s[j][2] = fast_ex2(s[j][2] - mn1);
            s[j][3] = fast_ex2(s[j][3] - mn1);
            rs0 += s[j][0] + s[j][1];
            rs1 += s[j][2] + s[j][3];
        }
        rs0 += __shfl_xor_sync(0xffffffffu, rs0, 1);
        rs0 += __shfl_xor_sync(0xffffffffu, rs0, 2);
        rs1 += __shfl_xor_sync(0xffffffffu, rs1, 1);
        rs1 += __shfl_xor_sync(0xffffffffu, rs1, 2);
        l[0] = l[0] * c0 + rs0;
        l[1] = l[1] * c1 + rs1;
#pragma unroll
        for (int j = 0; j < 8; j++) {
            po[j][0] *= c0; po[j][1] *= c0;
            po[j][2] *= c1; po[j][3] *= c1;
        }

        // O += P V : P fp16 (accumulator frag == A frag)
#pragma unroll
        for (int t = 0; t < 4; t++) {
            uint32_t ph[4];
            ph[0] = pack_h2(s[2 * t][0],     s[2 * t][1]);
            ph[1] = pack_h2(s[2 * t][2],     s[2 * t][3]);
            ph[2] = pack_h2(s[2 * t + 1][0], s[2 * t + 1][1]);
            ph[3] = pack_h2(s[2 * t + 1][2], s[2 * t + 1][3]);
#pragma unroll
            for (int jq = 0; jq < 2; jq++) {
                uint32_t vf[8];
#pragma unroll
                for (int p = 0; p < 2; ++p) {
                    LDSM4(vf + 4 * p,
                          sv + (uint32_t)((jq * 32 + p * 16 + b4_row) * AT_SROW)
                             + b4_coff + t * 32);
                }
#pragma unroll
                for (int jj = 0; jj < 4; jj++)
                    MMA_F16(po[jq * 4 + jj], ph, &vf[2 * jj]);
            }
        }
        __syncthreads();
    }

    // Epilogue: O/l -> fp16 hi/lo [tok][h*64+d]
    const int h = bh & 15, bb = bh >> 4;
    const int tok0 = qt * 128 + wid * 16 + (lane >> 2);
    const float inv0 = 1.f / l[0], inv1 = 1.f / l[1];
#pragma unroll
    for (int j = 0; j < 8; j++) {
        const int d = h * HDIM + j * 8 + (lane & 3) * 2;
        const size_t a0 = ((size_t)(bb * SEQ + tok0)) * DIM + d;
        const size_t a1 = a0 + (size_t)8 * DIM;
        const float v0 = po[j][0] * inv0, v1 = po[j][1] * inv0;
        const float v2 = po[j][2] * inv1, v3 = po[j][3] * inv1;
        uint32_t h2 = pack_h2(v0, v1);
        *(uint32_t*)(g_ohi + a0) = h2;
        *(uint32_t*)(g_olo + a0) = pack_l2(v0, v1, h2);
        h2 = pack_h2(v2, v3);
        *(uint32_t*)(g_ohi + a1) = h2;
        *(uint32_t*)(g_olo + a1) = pack_l2(v2, v3, h2);
    }
}

// ---------------------------------------------------------------------------

extern "C" void kernel_launch(void* const* d_in, const int* in_sizes, int n_in,
                              void* d_out, int out_size)
{
    const float* x      = (const float*)d_in[0];
    const float* w_qkv  = (const float*)d_in[1];
    const float* b_qkv  = (const float*)d_in[2];
    const float* w_proj = (const float*)d_in[3];
    const float* b_proj = (const float*)d_in[4];
    float* out = (float*)d_out;

    __half *h_xh, *h_wqh, *h_wph, *h_ohi, *h_olo;
    cudaGetSymbolAddress((void**)&h_xh,  g_xh);
    cudaGetSymbolAddress((void**)&h_wqh, g_wqh);
    cudaGetSymbolAddress((void**)&h_wph, g_wph);
    cudaGetSymbolAddress((void**)&h_ohi, g_ohi);
    cudaGetSymbolAddress((void**)&h_olo, g_olo);

    cudaFuncSetAttribute(gemm_fp16_kernel<0>,
                         cudaFuncAttributeMaxDynamicSharedMemorySize,
                         2 * 2 * TILE_B);
    cudaFuncSetAttribute(gemm_fp16_kernel<1>,
                         cudaFuncAttributeMaxDynamicSharedMemorySize,
                         2 * 3 * TILE_B);
    cudaFuncSetAttribute(attn_mma_kernel,
                         cudaFuncAttributeMaxDynamicSharedMemorySize,
                         AT_SMEM);

    // 1. Convert x + weights to fp16 (single launch)
    cvt_all_kernel<<<(NX4 + WQ4 + WP4 + 255) / 256, 256>>>(x, w_qkv, w_proj);

    // 2. QKV GEMM (1 MMA/product) -> fp16 Q / K / V in attention layouts
    dim3 gq(3 * DIM / 128, M_TOK / 128);
    gemm_fp16_kernel<0><<<gq, 256, 2 * 2 * TILE_B>>>(
        h_xh, nullptr, h_wqh, b_qkv, nullptr, 0);

    // 3. Tensor-core flash attention -> g_ohi/g_olo
    dim3 ga(SEQ / 128, NBH);
    attn_mma_kernel<<<ga, 256, AT_SMEM>>>();

    // 4. Projection GEMM (2 MMA/product, A split): M=4096, N=1024
    dim3 gp(DIM / 128, M_TOK / 128);
    gemm_fp16_kernel<1><<<gp, 256, 2 * 3 * TILE_B>>>(
        h_ohi, h_olo, h_wph, b_proj, out, 1);
}